// round 1
// baseline (speedup 1.0000x reference)
#include <cuda_runtime.h>
#include <math.h>

// Problem dims (fixed)
#define Bq 2
#define Tt 2048
#define Mm 1024
#define Hh 8
#define Dd 128
#define BT (Bq*Tt)      // 4096
#define HD (Hh*Dd)      // 1024

// Scratch (no cudaMalloc allowed) — [B,T,H,D] layouts, i.e. [BT, HD] row-major
__device__ float g_q[BT*HD];
__device__ float g_k[BT*HD];
__device__ float g_v[BT*HD];
__device__ float g_o[BT*HD];

// ---------------------------------------------------------------------------
// SGEMM: C[M,N] = A[M,K] * B[K,N], all row-major fp32.
// 128x128 tile, BK=8, 8x8 per thread, 256 threads. M,N,K multiples of tile.
// ---------------------------------------------------------------------------
__global__ __launch_bounds__(256) void sgemm(const float* __restrict__ A,
                                             const float* __restrict__ B,
                                             float* __restrict__ C,
                                             int M, int N, int K) {
    const int BM = 128, BN = 128, BK = 8;
    __shared__ float As[BK][BM];        // transposed A tile
    __shared__ float Bs[BK][BN + 4];    // padded

    int tid  = threadIdx.x;
    int trow = tid >> 4;   // 0..15
    int tcol = tid & 15;   // 0..15
    int rowBase = blockIdx.y * BM;
    int colBase = blockIdx.x * BN;

    float acc[8][8];
#pragma unroll
    for (int i = 0; i < 8; i++)
#pragma unroll
        for (int j = 0; j < 8; j++) acc[i][j] = 0.f;

    // A: each thread loads one float4 (row = tid>>1, seg = tid&1)
    const float* Aptr = A + (size_t)(rowBase + (tid >> 1)) * K + ((tid & 1) << 2);
    // B: each thread loads one float4 (row = tid>>5, col4 = tid&31)
    const float* Bptr = B + (size_t)(tid >> 5) * N + colBase + ((tid & 31) << 2);

    for (int k0 = 0; k0 < K; k0 += BK) {
        float4 av = *(const float4*)(Aptr + k0);
        int ar = tid >> 1, ak = (tid & 1) << 2;
        As[ak + 0][ar] = av.x;
        As[ak + 1][ar] = av.y;
        As[ak + 2][ar] = av.z;
        As[ak + 3][ar] = av.w;

        float4 bv = *(const float4*)(Bptr + (size_t)k0 * N);
        *(float4*)&Bs[tid >> 5][(tid & 31) << 2] = bv;
        __syncthreads();

#pragma unroll
        for (int kk = 0; kk < BK; kk++) {
            float a[8], b[8];
#pragma unroll
            for (int i = 0; i < 8; i++) a[i] = As[kk][trow * 8 + i];
            float4 b0 = *(float4*)&Bs[kk][tcol * 8];
            float4 b1 = *(float4*)&Bs[kk][tcol * 8 + 4];
            b[0] = b0.x; b[1] = b0.y; b[2] = b0.z; b[3] = b0.w;
            b[4] = b1.x; b[5] = b1.y; b[6] = b1.z; b[7] = b1.w;
#pragma unroll
            for (int i = 0; i < 8; i++)
#pragma unroll
                for (int j = 0; j < 8; j++) acc[i][j] = fmaf(a[i], b[j], acc[i][j]);
        }
        __syncthreads();
    }

#pragma unroll
    for (int i = 0; i < 8; i++) {
        int r = rowBase + trow * 8 + i;
        float* cp = C + (size_t)r * N + colBase + tcol * 8;
        float4 c0 = make_float4(acc[i][0], acc[i][1], acc[i][2], acc[i][3]);
        float4 c1 = make_float4(acc[i][4], acc[i][5], acc[i][6], acc[i][7]);
        *(float4*)cp = c0;
        *(float4*)(cp + 4) = c1;
    }
}

// ---------------------------------------------------------------------------
// RMSNorm (no gains) + RoPE + fold mult = sqrt(1/128) into q and k.
// One warp per (b,t,h) row of D=128. First nrows warps -> q, next -> k.
// ---------------------------------------------------------------------------
__global__ __launch_bounds__(256) void normrope(float* __restrict__ q,
                                                float* __restrict__ k) {
    int gwarp = (blockIdx.x * blockDim.x + threadIdx.x) >> 5;
    int lane  = threadIdx.x & 31;
    const int nrows = BT * Hh;     // 32768 per tensor
    float* base = (gwarp < nrows) ? q : k;
    int row = (gwarp < nrows) ? gwarp : gwarp - nrows;
    int t = (row / Hh) % Tt;       // row = (b*T + t)*H + h

    float* p = base + (size_t)row * Dd;
    float e0 = p[lane], e1 = p[lane + 32];
    float o0 = p[lane + 64], o1 = p[lane + 96];

    float ss = e0 * e0 + e1 * e1 + o0 * o0 + o1 * o1;
#pragma unroll
    for (int off = 16; off; off >>= 1) ss += __shfl_xor_sync(0xffffffffu, ss, off);

    // x / sqrt(mean(x^2) + eps), then * sqrt(QK_SCALE)
    float scale = rsqrtf(ss * (1.0f / 128.0f) + 1e-6f) * 0.08838834764831845f;
    e0 *= scale; e1 *= scale; o0 *= scale; o1 *= scale;

    float f0 = powf(10000.0f, -((float)lane) * (1.0f / 64.0f));
    float f1 = powf(10000.0f, -((float)(lane + 32)) * (1.0f / 64.0f));
    float r0 = (float)t * f0, r1 = (float)t * f1;
    float s0, c0, s1, c1;
    sincosf(r0, &s0, &c0);
    sincosf(r1, &s1, &c1);

    p[lane]      = e0 * c0 - o0 * s0;
    p[lane + 32] = e1 * c1 - o1 * s1;
    p[lane + 64] = e0 * s0 + o0 * c0;
    p[lane + 96] = e1 * s1 + o1 * c1;
}

// ---------------------------------------------------------------------------
// Flash-style causal attention, all fp32.
// Grid: (T/64, H, B). CTA: 256 threads. BR=BC=64, D=128.
// smem: Qs[64][132], Kt[128][68], Vs[64][132], Ss[64][68], m/l/c[64]
// ---------------------------------------------------------------------------
#define BR 64
#define BC 64
#define QS(r,c)  smQ[(r)*132 + (c)]
#define KT(d,r)  smK[(d)*68  + (r)]
#define VS(r,c)  smV[(r)*132 + (c)]
#define SS(r,c)  smS[(r)*68  + (c)]

__global__ __launch_bounds__(256) void attn(const float* __restrict__ q,
                                            const float* __restrict__ k,
                                            const float* __restrict__ v,
                                            float* __restrict__ o) {
    extern __shared__ float sm[];
    float* smQ  = sm;                       // 64*132 = 8448
    float* smK  = smQ + 64 * 132;           // 128*68 = 8704
    float* smV  = smK + 128 * 68;           // 8448
    float* smS  = smV + 64 * 132;           // 64*68 = 4352
    float* mrow = smS + 64 * 68;            // 64
    float* lrow = mrow + 64;                // 64
    float* crow = lrow + 64;                // 64

    int tid = threadIdx.x;
    int ty = tid >> 4, tx = tid & 15;
    int qb = blockIdx.x;
    int h  = blockIdx.y;
    int b  = blockIdx.z;
    int t0 = qb * BR;

    const size_t headOff = ((size_t)b * Tt * Hh + h) * Dd;
    const float* qbase = q + headOff;
    const float* kbase = k + headOff;
    const float* vbase = v + headOff;

    // Load Q tile (rows t0..t0+63, 128 each)
    for (int s = tid; s < BR * 32; s += 256) {
        int r = s >> 5, c4 = (s & 31) << 2;
        float4 qv = *(const float4*)(qbase + (size_t)(t0 + r) * HD + c4);
        *(float4*)&QS(r, c4) = qv;
    }
    if (tid < BR) { mrow[tid] = -1e30f; lrow[tid] = 0.f; }

    float acc[4][8];
#pragma unroll
    for (int i = 0; i < 4; i++)
#pragma unroll
        for (int j = 0; j < 8; j++) acc[i][j] = 0.f;
    __syncthreads();

    for (int kb = 0; kb <= qb; kb++) {
        int tk0 = kb * BC;
        // Load K (transposed into smem) and V
        for (int s = tid; s < BC * 32; s += 256) {
            int r = s >> 5, c4 = (s & 31) << 2;
            float4 kv = *(const float4*)(kbase + (size_t)(tk0 + r) * HD + c4);
            KT(c4 + 0, r) = kv.x;
            KT(c4 + 1, r) = kv.y;
            KT(c4 + 2, r) = kv.z;
            KT(c4 + 3, r) = kv.w;
            float4 vv = *(const float4*)(vbase + (size_t)(tk0 + r) * HD + c4);
            *(float4*)&VS(r, c4) = vv;
        }
        __syncthreads();

        // S = Q K^T (each thread: 4 rows x 4 cols)
        float sacc[4][4];
#pragma unroll
        for (int i = 0; i < 4; i++)
#pragma unroll
            for (int j = 0; j < 4; j++) sacc[i][j] = 0.f;

#pragma unroll 4
        for (int kk = 0; kk < Dd; kk++) {
            float a0 = QS(ty * 4 + 0, kk);
            float a1 = QS(ty * 4 + 1, kk);
            float a2 = QS(ty * 4 + 2, kk);
            float a3 = QS(ty * 4 + 3, kk);
            float4 bq = *(float4*)&KT(kk, tx * 4);
            sacc[0][0] = fmaf(a0, bq.x, sacc[0][0]); sacc[0][1] = fmaf(a0, bq.y, sacc[0][1]);
            sacc[0][2] = fmaf(a0, bq.z, sacc[0][2]); sacc[0][3] = fmaf(a0, bq.w, sacc[0][3]);
            sacc[1][0] = fmaf(a1, bq.x, sacc[1][0]); sacc[1][1] = fmaf(a1, bq.y, sacc[1][1]);
            sacc[1][2] = fmaf(a1, bq.z, sacc[1][2]); sacc[1][3] = fmaf(a1, bq.w, sacc[1][3]);
            sacc[2][0] = fmaf(a2, bq.x, sacc[2][0]); sacc[2][1] = fmaf(a2, bq.y, sacc[2][1]);
            sacc[2][2] = fmaf(a2, bq.z, sacc[2][2]); sacc[2][3] = fmaf(a2, bq.w, sacc[2][3]);
            sacc[3][0] = fmaf(a3, bq.x, sacc[3][0]); sacc[3][1] = fmaf(a3, bq.y, sacc[3][1]);
            sacc[3][2] = fmaf(a3, bq.z, sacc[3][2]); sacc[3][3] = fmaf(a3, bq.w, sacc[3][3]);
        }

        // Causal mask on the diagonal block (local: row < col => masked)
        if (kb == qb) {
#pragma unroll
            for (int i = 0; i < 4; i++)
#pragma unroll
                for (int j = 0; j < 4; j++)
                    if (ty * 4 + i < tx * 4 + j) sacc[i][j] = -1e30f;
        }
#pragma unroll
        for (int i = 0; i < 4; i++) {
            float4 sv = make_float4(sacc[i][0], sacc[i][1], sacc[i][2], sacc[i][3]);
            *(float4*)&SS(ty * 4 + i, tx * 4) = sv;
        }
        __syncthreads();

        // Online softmax per row: 4 threads per row (16 cols each)
        {
            int r = tid >> 2;
            int part = tid & 3;
            int j0 = part * 16;
            float mx = -1e30f;
#pragma unroll
            for (int j = 0; j < 16; j++) mx = fmaxf(mx, SS(r, j0 + j));
            mx = fmaxf(mx, __shfl_xor_sync(0xffffffffu, mx, 1));
            mx = fmaxf(mx, __shfl_xor_sync(0xffffffffu, mx, 2));
            float mo = mrow[r];
            float newm = fmaxf(mo, mx);
            float sum = 0.f;
#pragma unroll
            for (int j = 0; j < 16; j++) {
                float e = expf(SS(r, j0 + j) - newm);
                SS(r, j0 + j) = e;
                sum += e;
            }
            sum += __shfl_xor_sync(0xffffffffu, sum, 1);
            sum += __shfl_xor_sync(0xffffffffu, sum, 2);
            if (part == 0) {
                float c = expf(mo - newm);
                lrow[r] = lrow[r] * c + sum;
                mrow[r] = newm;
                crow[r] = c;
            }
        }
        __syncthreads();

        // Rescale accumulators, then O += P @ V (each thread: 4 rows x 8 cols)
        float cf[4];
#pragma unroll
        for (int i = 0; i < 4; i++) cf[i] = crow[ty * 4 + i];
#pragma unroll
        for (int i = 0; i < 4; i++)
#pragma unroll
            for (int j = 0; j < 8; j++) acc[i][j] *= cf[i];

#pragma unroll 4
        for (int jj = 0; jj < BC; jj++) {
            float p0 = SS(ty * 4 + 0, jj);
            float p1 = SS(ty * 4 + 1, jj);
            float p2 = SS(ty * 4 + 2, jj);
            float p3 = SS(ty * 4 + 3, jj);
            float4 v0 = *(float4*)&VS(jj, tx * 8);
            float4 v1 = *(float4*)&VS(jj, tx * 8 + 4);
            float vv[8] = {v0.x, v0.y, v0.z, v0.w, v1.x, v1.y, v1.z, v1.w};
#pragma unroll
            for (int j = 0; j < 8; j++) {
                acc[0][j] = fmaf(p0, vv[j], acc[0][j]);
                acc[1][j] = fmaf(p1, vv[j], acc[1][j]);
                acc[2][j] = fmaf(p2, vv[j], acc[2][j]);
                acc[3][j] = fmaf(p3, vv[j], acc[3][j]);
            }
        }
        __syncthreads();   // protect smem before next tile load
    }

    // Epilogue: O / l, write to o buffer [B,T,H,D]
    float* obase = o + headOff;
#pragma unroll
    for (int i = 0; i < 4; i++) {
        int r = ty * 4 + i;
        float inv = 1.0f / lrow[r];
        float4 c0 = make_float4(acc[i][0] * inv, acc[i][1] * inv,
                                acc[i][2] * inv, acc[i][3] * inv);
        float4 c1 = make_float4(acc[i][4] * inv, acc[i][5] * inv,
                                acc[i][6] * inv, acc[i][7] * inv);
        float* op = obase + (size_t)(t0 + r) * HD + tx * 8;
        *(float4*)op = c0;
        *(float4*)(op + 4) = c1;
    }
}

// ---------------------------------------------------------------------------
extern "C" void kernel_launch(void* const* d_in, const int* in_sizes, int n_in,
                              void* d_out, int out_size) {
    const float* x  = (const float*)d_in[0];
    const float* wq = (const float*)d_in[1];
    const float* wk = (const float*)d_in[2];
    const float* wv = (const float*)d_in[3];
    const float* wo = (const float*)d_in[4];
    float* out = (float*)d_out;

    float *qp, *kp, *vp, *op;
    cudaGetSymbolAddress((void**)&qp, g_q);
    cudaGetSymbolAddress((void**)&kp, g_k);
    cudaGetSymbolAddress((void**)&vp, g_v);
    cudaGetSymbolAddress((void**)&op, g_o);

    // QKV projections: [BT, M] x [M, HD] -> [BT, HD]
    dim3 gp(HD / 128, BT / 128);
    sgemm<<<gp, 256>>>(x, wq, qp, BT, HD, Mm);
    sgemm<<<gp, 256>>>(x, wk, kp, BT, HD, Mm);
    sgemm<<<gp, 256>>>(x, wv, vp, BT, HD, Mm);

    // RMSNorm + RoPE + mult fold (q and k)
    int totalWarps = 2 * BT * Hh;   // 65536
    normrope<<<totalWarps / 8, 256>>>(qp, kp);

    // Causal attention
    size_t smem = (size_t)(64 * 132 + 128 * 68 + 64 * 132 + 64 * 68 + 3 * 64) * sizeof(float);
    cudaFuncSetAttribute(attn, cudaFuncAttributeMaxDynamicSharedMemorySize, (int)smem);
    dim3 ga(Tt / BR, Hh, Bq);
    attn<<<ga, 256, smem>>>(qp, kp, vp, op);

    // Output projection: [BT, HD] x [HD, M] -> [BT, M]
    dim3 go(Mm / 128, BT / 128);
    sgemm<<<go, 256>>>(op, wo, out, BT, Mm, HD);
}

// round 2
// speedup vs baseline: 2.2638x; 2.2638x over previous
#include <cuda_runtime.h>
#include <math.h>
#include <stdint.h>

// Problem dims (fixed)
#define Bq 2
#define Tt 2048
#define Mm 1024
#define Hh 8
#define Dd 128
#define BT (Bq*Tt)      // 4096
#define HD (Hh*Dd)      // 1024

// Scratch (no cudaMalloc allowed) — [B,T,H,D] layouts, i.e. [BT, HD] row-major
__device__ float g_q[BT*HD];
__device__ float g_k[BT*HD];
__device__ float g_v[BT*HD];
__device__ float g_o[BT*HD];

// ---------------------------------------------------------------------------
// TF32 tensor-core GEMM: C[M,N] = A[M,K] * B[K,N], row-major fp32 in/out.
// CTA tile 128x128, BK=8. 4 warps (128 thr), warp tile 64x64.
// mma.sync.aligned.m16n8k8.row.col.f32.tf32.tf32.f32
// SMEM layouts (stride 12 words) chosen for conflict-free fragment loads:
//   As[m][k]  : addr = m*12 + k   (m in 0..127, k in 0..7)
//   Bs[n][k]  : addr = n*12 + k   (n in 0..127, k in 0..7)
// ---------------------------------------------------------------------------
__device__ __forceinline__ uint32_t f2tf32(float f) {
    uint32_t u;
    asm("cvt.rna.tf32.f32 %0, %1;" : "=r"(u) : "f"(f));
    return u;
}

__device__ __forceinline__ void mma_tf32(float c[4], uint32_t a0, uint32_t a1,
                                         uint32_t a2, uint32_t a3,
                                         uint32_t b0, uint32_t b1) {
    asm volatile(
        "mma.sync.aligned.m16n8k8.row.col.f32.tf32.tf32.f32 "
        "{%0,%1,%2,%3}, {%4,%5,%6,%7}, {%8,%9}, {%0,%1,%2,%3};\n"
        : "+f"(c[0]), "+f"(c[1]), "+f"(c[2]), "+f"(c[3])
        : "r"(a0), "r"(a1), "r"(a2), "r"(a3), "r"(b0), "r"(b1));
}

__global__ __launch_bounds__(128) void gemm_tf32(const float* __restrict__ A,
                                                 const float* __restrict__ Bm,
                                                 float* __restrict__ C,
                                                 int M, int N, int K) {
    __shared__ uint32_t As[2][128 * 12];
    __shared__ uint32_t Bs[2][128 * 12];

    const int tid  = threadIdx.x;
    const int lane = tid & 31;
    const int warp = tid >> 5;
    const int gid  = lane >> 2;   // 0..7
    const int tig  = lane & 3;    // 0..3
    const int wm   = (warp >> 1) * 64;
    const int wn   = (warp & 1) * 64;
    const int rowBase = blockIdx.y * 128;
    const int colBase = blockIdx.x * 128;

    const float* Ag = A + (size_t)rowBase * K;
    const float* Bg = Bm + colBase;

    float acc[4][8][4];
#pragma unroll
    for (int mt = 0; mt < 4; mt++)
#pragma unroll
        for (int nt = 0; nt < 8; nt++)
#pragma unroll
            for (int i = 0; i < 4; i++) acc[mt][nt][i] = 0.f;

    // Global-load staging registers
    float4 abuf0, abuf1;
    float  bbuf[8];

    const int am0 = tid >> 1;            // A row (0..63), +64 for second
    const int ak4 = (tid & 1) * 4;       // A k-offset (0 or 4)

    // ---- prologue: tile 0 ----
    {
        abuf0 = *(const float4*)(Ag + (size_t)am0 * K + ak4);
        abuf1 = *(const float4*)(Ag + (size_t)(am0 + 64) * K + ak4);
#pragma unroll
        for (int kk = 0; kk < 8; kk++)
            bbuf[kk] = Bg[(size_t)kk * N + tid];

        uint32_t* ap = &As[0][am0 * 12 + ak4];
        ap[0] = f2tf32(abuf0.x); ap[1] = f2tf32(abuf0.y);
        ap[2] = f2tf32(abuf0.z); ap[3] = f2tf32(abuf0.w);
        uint32_t* ap2 = &As[0][(am0 + 64) * 12 + ak4];
        ap2[0] = f2tf32(abuf1.x); ap2[1] = f2tf32(abuf1.y);
        ap2[2] = f2tf32(abuf1.z); ap2[3] = f2tf32(abuf1.w);
        uint32_t* bp = &Bs[0][tid * 12];
#pragma unroll
        for (int kk = 0; kk < 8; kk++) bp[kk] = f2tf32(bbuf[kk]);
    }
    __syncthreads();

    const int niter = K >> 3;   // K/8
    for (int it = 0; it < niter; it++) {
        const int cur = it & 1;

        // Issue global loads for next tile (latency overlapped with MMAs)
        if (it + 1 < niter) {
            const int k0 = (it + 1) << 3;
            abuf0 = *(const float4*)(Ag + (size_t)am0 * K + k0 + ak4);
            abuf1 = *(const float4*)(Ag + (size_t)(am0 + 64) * K + k0 + ak4);
#pragma unroll
            for (int kk = 0; kk < 8; kk++)
                bbuf[kk] = Bg[(size_t)(k0 + kk) * N + tid];
        }

        // Load A fragments (4 m-tiles), reuse across 8 n-tiles
        uint32_t af[4][4];
#pragma unroll
        for (int mt = 0; mt < 4; mt++) {
            const int r = wm + mt * 16 + gid;
            const uint32_t* p  = &As[cur][r * 12 + tig];
            const uint32_t* p8 = &As[cur][(r + 8) * 12 + tig];
            af[mt][0] = p[0];  af[mt][2] = p[4];
            af[mt][1] = p8[0]; af[mt][3] = p8[4];
        }
#pragma unroll
        for (int nt = 0; nt < 8; nt++) {
            const int n = wn + nt * 8 + gid;
            const uint32_t* bp = &Bs[cur][n * 12 + tig];
            const uint32_t b0 = bp[0], b1 = bp[4];
#pragma unroll
            for (int mt = 0; mt < 4; mt++)
                mma_tf32(acc[mt][nt], af[mt][0], af[mt][1], af[mt][2], af[mt][3], b0, b1);
        }

        if (it + 1 < niter) {
            const int nxt = cur ^ 1;
            uint32_t* ap = &As[nxt][am0 * 12 + ak4];
            ap[0] = f2tf32(abuf0.x); ap[1] = f2tf32(abuf0.y);
            ap[2] = f2tf32(abuf0.z); ap[3] = f2tf32(abuf0.w);
            uint32_t* ap2 = &As[nxt][(am0 + 64) * 12 + ak4];
            ap2[0] = f2tf32(abuf1.x); ap2[1] = f2tf32(abuf1.y);
            ap2[2] = f2tf32(abuf1.z); ap2[3] = f2tf32(abuf1.w);
            uint32_t* bp = &Bs[nxt][tid * 12];
#pragma unroll
            for (int kk = 0; kk < 8; kk++) bp[kk] = f2tf32(bbuf[kk]);
            __syncthreads();
        }
    }

    // Epilogue: write C (float2 per half-tile row)
#pragma unroll
    for (int mt = 0; mt < 4; mt++) {
#pragma unroll
        for (int nt = 0; nt < 8; nt++) {
            const int r0 = rowBase + wm + mt * 16 + gid;
            const int c0 = colBase + wn + nt * 8 + 2 * tig;
            float2 v0 = make_float2(acc[mt][nt][0], acc[mt][nt][1]);
            float2 v1 = make_float2(acc[mt][nt][2], acc[mt][nt][3]);
            *(float2*)(C + (size_t)r0 * N + c0)        = v0;
            *(float2*)(C + (size_t)(r0 + 8) * N + c0)  = v1;
        }
    }
}

// ---------------------------------------------------------------------------
// RMSNorm (no gains) + RoPE + fold mult = sqrt(1/128) into q and k.
// One warp per (b,t,h) row of D=128.
// ---------------------------------------------------------------------------
__global__ __launch_bounds__(256) void normrope(float* __restrict__ q,
                                                float* __restrict__ k) {
    int gwarp = (blockIdx.x * blockDim.x + threadIdx.x) >> 5;
    int lane  = threadIdx.x & 31;
    const int nrows = BT * Hh;
    float* base = (gwarp < nrows) ? q : k;
    int row = (gwarp < nrows) ? gwarp : gwarp - nrows;
    int t = (row / Hh) % Tt;

    float* p = base + (size_t)row * Dd;
    float e0 = p[lane], e1 = p[lane + 32];
    float o0 = p[lane + 64], o1 = p[lane + 96];

    float ss = e0 * e0 + e1 * e1 + o0 * o0 + o1 * o1;
#pragma unroll
    for (int off = 16; off; off >>= 1) ss += __shfl_xor_sync(0xffffffffu, ss, off);

    float scale = rsqrtf(ss * (1.0f / 128.0f) + 1e-6f) * 0.08838834764831845f;
    e0 *= scale; e1 *= scale; o0 *= scale; o1 *= scale;

    float f0 = powf(10000.0f, -((float)lane) * (1.0f / 64.0f));
    float f1 = powf(10000.0f, -((float)(lane + 32)) * (1.0f / 64.0f));
    float r0 = (float)t * f0, r1 = (float)t * f1;
    float s0, c0, s1, c1;
    sincosf(r0, &s0, &c0);
    sincosf(r1, &s1, &c1);

    p[lane]      = e0 * c0 - o0 * s0;
    p[lane + 32] = e1 * c1 - o1 * s1;
    p[lane + 64] = e0 * s0 + o0 * c0;
    p[lane + 96] = e1 * s1 + o1 * c1;
}

// ---------------------------------------------------------------------------
// Flash-style causal attention, fp32 (unchanged from round 1).
// ---------------------------------------------------------------------------
#define BR 64
#define BC 64
#define QS(r,c)  smQ[(r)*132 + (c)]
#define KT(d,r)  smK[(d)*68  + (r)]
#define VS(r,c)  smV[(r)*132 + (c)]
#define SS(r,c)  smS[(r)*68  + (c)]

__global__ __launch_bounds__(256) void attn(const float* __restrict__ q,
                                            const float* __restrict__ k,
                                            const float* __restrict__ v,
                                            float* __restrict__ o) {
    extern __shared__ float sm[];
    float* smQ  = sm;
    float* smK  = smQ + 64 * 132;
    float* smV  = smK + 128 * 68;
    float* smS  = smV + 64 * 132;
    float* mrow = smS + 64 * 68;
    float* lrow = mrow + 64;
    float* crow = lrow + 64;

    int tid = threadIdx.x;
    int ty = tid >> 4, tx = tid & 15;
    int qb = blockIdx.x;
    int h  = blockIdx.y;
    int b  = blockIdx.z;
    int t0 = qb * BR;

    const size_t headOff = ((size_t)b * Tt * Hh + h) * Dd;
    const float* qbase = q + headOff;
    const float* kbase = k + headOff;
    const float* vbase = v + headOff;

    for (int s = tid; s < BR * 32; s += 256) {
        int r = s >> 5, c4 = (s & 31) << 2;
        float4 qv = *(const float4*)(qbase + (size_t)(t0 + r) * HD + c4);
        *(float4*)&QS(r, c4) = qv;
    }
    if (tid < BR) { mrow[tid] = -1e30f; lrow[tid] = 0.f; }

    float acc[4][8];
#pragma unroll
    for (int i = 0; i < 4; i++)
#pragma unroll
        for (int j = 0; j < 8; j++) acc[i][j] = 0.f;
    __syncthreads();

    for (int kb = 0; kb <= qb; kb++) {
        int tk0 = kb * BC;
        for (int s = tid; s < BC * 32; s += 256) {
            int r = s >> 5, c4 = (s & 31) << 2;
            float4 kv = *(const float4*)(kbase + (size_t)(tk0 + r) * HD + c4);
            KT(c4 + 0, r) = kv.x;
            KT(c4 + 1, r) = kv.y;
            KT(c4 + 2, r) = kv.z;
            KT(c4 + 3, r) = kv.w;
            float4 vv = *(const float4*)(vbase + (size_t)(tk0 + r) * HD + c4);
            *(float4*)&VS(r, c4) = vv;
        }
        __syncthreads();

        float sacc[4][4];
#pragma unroll
        for (int i = 0; i < 4; i++)
#pragma unroll
            for (int j = 0; j < 4; j++) sacc[i][j] = 0.f;

#pragma unroll 4
        for (int kk = 0; kk < Dd; kk++) {
            float a0 = QS(ty * 4 + 0, kk);
            float a1 = QS(ty * 4 + 1, kk);
            float a2 = QS(ty * 4 + 2, kk);
            float a3 = QS(ty * 4 + 3, kk);
            float4 bqv = *(float4*)&KT(kk, tx * 4);
            sacc[0][0] = fmaf(a0, bqv.x, sacc[0][0]); sacc[0][1] = fmaf(a0, bqv.y, sacc[0][1]);
            sacc[0][2] = fmaf(a0, bqv.z, sacc[0][2]); sacc[0][3] = fmaf(a0, bqv.w, sacc[0][3]);
            sacc[1][0] = fmaf(a1, bqv.x, sacc[1][0]); sacc[1][1] = fmaf(a1, bqv.y, sacc[1][1]);
            sacc[1][2] = fmaf(a1, bqv.z, sacc[1][2]); sacc[1][3] = fmaf(a1, bqv.w, sacc[1][3]);
            sacc[2][0] = fmaf(a2, bqv.x, sacc[2][0]); sacc[2][1] = fmaf(a2, bqv.y, sacc[2][1]);
            sacc[2][2] = fmaf(a2, bqv.z, sacc[2][2]); sacc[2][3] = fmaf(a2, bqv.w, sacc[2][3]);
            sacc[3][0] = fmaf(a3, bqv.x, sacc[3][0]); sacc[3][1] = fmaf(a3, bqv.y, sacc[3][1]);
            sacc[3][2] = fmaf(a3, bqv.z, sacc[3][2]); sacc[3][3] = fmaf(a3, bqv.w, sacc[3][3]);
        }

        if (kb == qb) {
#pragma unroll
            for (int i = 0; i < 4; i++)
#pragma unroll
                for (int j = 0; j < 4; j++)
                    if (ty * 4 + i < tx * 4 + j) sacc[i][j] = -1e30f;
        }
#pragma unroll
        for (int i = 0; i < 4; i++) {
            float4 sv = make_float4(sacc[i][0], sacc[i][1], sacc[i][2], sacc[i][3]);
            *(float4*)&SS(ty * 4 + i, tx * 4) = sv;
        }
        __syncthreads();

        {
            int r = tid >> 2;
            int part = tid & 3;
            int j0 = part * 16;
            float mx = -1e30f;
#pragma unroll
            for (int j = 0; j < 16; j++) mx = fmaxf(mx, SS(r, j0 + j));
            mx = fmaxf(mx, __shfl_xor_sync(0xffffffffu, mx, 1));
            mx = fmaxf(mx, __shfl_xor_sync(0xffffffffu, mx, 2));
            float mo = mrow[r];
            float newm = fmaxf(mo, mx);
            float sum = 0.f;
#pragma unroll
            for (int j = 0; j < 16; j++) {
                float e = expf(SS(r, j0 + j) - newm);
                SS(r, j0 + j) = e;
                sum += e;
            }
            sum += __shfl_xor_sync(0xffffffffu, sum, 1);
            sum += __shfl_xor_sync(0xffffffffu, sum, 2);
            if (part == 0) {
                float c = expf(mo - newm);
                lrow[r] = lrow[r] * c + sum;
                mrow[r] = newm;
                crow[r] = c;
            }
        }
        __syncthreads();

        float cf[4];
#pragma unroll
        for (int i = 0; i < 4; i++) cf[i] = crow[ty * 4 + i];
#pragma unroll
        for (int i = 0; i < 4; i++)
#pragma unroll
            for (int j = 0; j < 8; j++) acc[i][j] *= cf[i];

#pragma unroll 4
        for (int jj = 0; jj < BC; jj++) {
            float p0 = SS(ty * 4 + 0, jj);
            float p1 = SS(ty * 4 + 1, jj);
            float p2 = SS(ty * 4 + 2, jj);
            float p3 = SS(ty * 4 + 3, jj);
            float4 v0 = *(float4*)&VS(jj, tx * 8);
            float4 v1 = *(float4*)&VS(jj, tx * 8 + 4);
            float vv[8] = {v0.x, v0.y, v0.z, v0.w, v1.x, v1.y, v1.z, v1.w};
#pragma unroll
            for (int j = 0; j < 8; j++) {
                acc[0][j] = fmaf(p0, vv[j], acc[0][j]);
                acc[1][j] = fmaf(p1, vv[j], acc[1][j]);
                acc[2][j] = fmaf(p2, vv[j], acc[2][j]);
                acc[3][j] = fmaf(p3, vv[j], acc[3][j]);
            }
        }
        __syncthreads();
    }

    float* obase = o + headOff;
#pragma unroll
    for (int i = 0; i < 4; i++) {
        int r = ty * 4 + i;
        float inv = 1.0f / lrow[r];
        float4 c0 = make_float4(acc[i][0] * inv, acc[i][1] * inv,
                                acc[i][2] * inv, acc[i][3] * inv);
        float4 c1 = make_float4(acc[i][4] * inv, acc[i][5] * inv,
                                acc[i][6] * inv, acc[i][7] * inv);
        float* op = obase + (size_t)(t0 + r) * HD + tx * 8;
        *(float4*)op = c0;
        *(float4*)(op + 4) = c1;
    }
}

// ---------------------------------------------------------------------------
extern "C" void kernel_launch(void* const* d_in, const int* in_sizes, int n_in,
                              void* d_out, int out_size) {
    const float* x  = (const float*)d_in[0];
    const float* wq = (const float*)d_in[1];
    const float* wk = (const float*)d_in[2];
    const float* wv = (const float*)d_in[3];
    const float* wo = (const float*)d_in[4];
    float* out = (float*)d_out;

    float *qp, *kp, *vp, *op;
    cudaGetSymbolAddress((void**)&qp, g_q);
    cudaGetSymbolAddress((void**)&kp, g_k);
    cudaGetSymbolAddress((void**)&vp, g_v);
    cudaGetSymbolAddress((void**)&op, g_o);

    // QKV projections: [BT, M] x [M, HD] -> [BT, HD]  (tf32 tensor cores)
    dim3 gp(HD / 128, BT / 128);
    gemm_tf32<<<gp, 128>>>(x, wq, qp, BT, HD, Mm);
    gemm_tf32<<<gp, 128>>>(x, wk, kp, BT, HD, Mm);
    gemm_tf32<<<gp, 128>>>(x, wv, vp, BT, HD, Mm);

    // RMSNorm + RoPE + mult fold (q and k)
    int totalWarps = 2 * BT * Hh;
    normrope<<<totalWarps / 8, 256>>>(qp, kp);

    // Causal attention (fp32)
    size_t smem = (size_t)(64 * 132 + 128 * 68 + 64 * 132 + 64 * 68 + 3 * 64) * sizeof(float);
    cudaFuncSetAttribute(attn, cudaFuncAttributeMaxDynamicSharedMemorySize, (int)smem);
    dim3 ga(Tt / BR, Hh, Bq);
    attn<<<ga, 256, smem>>>(qp, kp, vp, op);

    // Output projection: [BT, HD] x [HD, M] -> [BT, M]  (tf32 tensor cores)
    dim3 go(Mm / 128, BT / 128);
    gemm_tf32<<<go, 128>>>(op, wo, out, BT, Mm, HD);
}

// round 3
// speedup vs baseline: 4.2127x; 1.8609x over previous
#include <cuda_runtime.h>
#include <math.h>
#include <stdint.h>

// Problem dims (fixed)
#define Bq 2
#define Tt 2048
#define Mm 1024
#define Hh 8
#define Dd 128
#define BT (Bq*Tt)      // 4096
#define HD (Hh*Dd)      // 1024

// Scratch — [B,T,H,D] layouts, i.e. [BT, HD] row-major
__device__ float g_q[BT*HD];
__device__ float g_k[BT*HD];
__device__ float g_v[BT*HD];
__device__ float g_o[BT*HD];

__device__ __forceinline__ uint32_t f2tf32(float f) {
    uint32_t u;
    asm("cvt.rna.tf32.f32 %0, %1;" : "=r"(u) : "f"(f));
    return u;
}

__device__ __forceinline__ void mma_tf32(float c[4], uint32_t a0, uint32_t a1,
                                         uint32_t a2, uint32_t a3,
                                         uint32_t b0, uint32_t b1) {
    asm volatile(
        "mma.sync.aligned.m16n8k8.row.col.f32.tf32.tf32.f32 "
        "{%0,%1,%2,%3}, {%4,%5,%6,%7}, {%8,%9}, {%0,%1,%2,%3};\n"
        : "+f"(c[0]), "+f"(c[1]), "+f"(c[2]), "+f"(c[3])
        : "r"(a0), "r"(a1), "r"(a2), "r"(a3), "r"(b0), "r"(b1));
}

// ---------------------------------------------------------------------------
// TF32 tensor-core GEMM: C[M,N] = A[M,K]*B[K,N], 128x128 tile, BK=8, 4 warps.
// Batched over blockIdx.z via pointer arrays (for fused QKV).
// ---------------------------------------------------------------------------
__global__ __launch_bounds__(128) void gemm_tf32(const float* __restrict__ A,
                                                 const float* __restrict__ B0,
                                                 const float* __restrict__ B1,
                                                 const float* __restrict__ B2,
                                                 float* __restrict__ C0,
                                                 float* __restrict__ C1,
                                                 float* __restrict__ C2,
                                                 int M, int N, int K) {
    const float* Bm = (blockIdx.z == 0) ? B0 : (blockIdx.z == 1) ? B1 : B2;
    float* C = (blockIdx.z == 0) ? C0 : (blockIdx.z == 1) ? C1 : C2;

    __shared__ uint32_t As[2][128 * 12];
    __shared__ uint32_t Bs[2][128 * 12];

    const int tid  = threadIdx.x;
    const int lane = tid & 31;
    const int warp = tid >> 5;
    const int gid  = lane >> 2;
    const int tig  = lane & 3;
    const int wm   = (warp >> 1) * 64;
    const int wn   = (warp & 1) * 64;
    const int rowBase = blockIdx.y * 128;
    const int colBase = blockIdx.x * 128;

    const float* Ag = A + (size_t)rowBase * K;
    const float* Bg = Bm + colBase;

    float acc[4][8][4];
#pragma unroll
    for (int mt = 0; mt < 4; mt++)
#pragma unroll
        for (int nt = 0; nt < 8; nt++)
#pragma unroll
            for (int i = 0; i < 4; i++) acc[mt][nt][i] = 0.f;

    float4 abuf0, abuf1;
    float  bbuf[8];
    const int am0 = tid >> 1;
    const int ak4 = (tid & 1) * 4;

    {
        abuf0 = *(const float4*)(Ag + (size_t)am0 * K + ak4);
        abuf1 = *(const float4*)(Ag + (size_t)(am0 + 64) * K + ak4);
#pragma unroll
        for (int kk = 0; kk < 8; kk++) bbuf[kk] = Bg[(size_t)kk * N + tid];

        uint32_t* ap = &As[0][am0 * 12 + ak4];
        ap[0] = f2tf32(abuf0.x); ap[1] = f2tf32(abuf0.y);
        ap[2] = f2tf32(abuf0.z); ap[3] = f2tf32(abuf0.w);
        uint32_t* ap2 = &As[0][(am0 + 64) * 12 + ak4];
        ap2[0] = f2tf32(abuf1.x); ap2[1] = f2tf32(abuf1.y);
        ap2[2] = f2tf32(abuf1.z); ap2[3] = f2tf32(abuf1.w);
        uint32_t* bp = &Bs[0][tid * 12];
#pragma unroll
        for (int kk = 0; kk < 8; kk++) bp[kk] = f2tf32(bbuf[kk]);
    }
    __syncthreads();

    const int niter = K >> 3;
    for (int it = 0; it < niter; it++) {
        const int cur = it & 1;
        if (it + 1 < niter) {
            const int k0 = (it + 1) << 3;
            abuf0 = *(const float4*)(Ag + (size_t)am0 * K + k0 + ak4);
            abuf1 = *(const float4*)(Ag + (size_t)(am0 + 64) * K + k0 + ak4);
#pragma unroll
            for (int kk = 0; kk < 8; kk++) bbuf[kk] = Bg[(size_t)(k0 + kk) * N + tid];
        }

        uint32_t af[4][4];
#pragma unroll
        for (int mt = 0; mt < 4; mt++) {
            const int r = wm + mt * 16 + gid;
            const uint32_t* p  = &As[cur][r * 12 + tig];
            const uint32_t* p8 = &As[cur][(r + 8) * 12 + tig];
            af[mt][0] = p[0];  af[mt][2] = p[4];
            af[mt][1] = p8[0]; af[mt][3] = p8[4];
        }
#pragma unroll
        for (int nt = 0; nt < 8; nt++) {
            const int n = wn + nt * 8 + gid;
            const uint32_t* bp = &Bs[cur][n * 12 + tig];
            const uint32_t b0 = bp[0], b1 = bp[4];
#pragma unroll
            for (int mt = 0; mt < 4; mt++)
                mma_tf32(acc[mt][nt], af[mt][0], af[mt][1], af[mt][2], af[mt][3], b0, b1);
        }

        if (it + 1 < niter) {
            const int nxt = cur ^ 1;
            uint32_t* ap = &As[nxt][am0 * 12 + ak4];
            ap[0] = f2tf32(abuf0.x); ap[1] = f2tf32(abuf0.y);
            ap[2] = f2tf32(abuf0.z); ap[3] = f2tf32(abuf0.w);
            uint32_t* ap2 = &As[nxt][(am0 + 64) * 12 + ak4];
            ap2[0] = f2tf32(abuf1.x); ap2[1] = f2tf32(abuf1.y);
            ap2[2] = f2tf32(abuf1.z); ap2[3] = f2tf32(abuf1.w);
            uint32_t* bp = &Bs[nxt][tid * 12];
#pragma unroll
            for (int kk = 0; kk < 8; kk++) bp[kk] = f2tf32(bbuf[kk]);
            __syncthreads();
        }
    }

#pragma unroll
    for (int mt = 0; mt < 4; mt++) {
#pragma unroll
        for (int nt = 0; nt < 8; nt++) {
            const int r0 = rowBase + wm + mt * 16 + gid;
            const int c0 = colBase + wn + nt * 8 + 2 * tig;
            *(float2*)(C + (size_t)r0 * N + c0)       = make_float2(acc[mt][nt][0], acc[mt][nt][1]);
            *(float2*)(C + (size_t)(r0 + 8) * N + c0) = make_float2(acc[mt][nt][2], acc[mt][nt][3]);
        }
    }
}

// ---------------------------------------------------------------------------
// RMSNorm + RoPE + fold sqrt(1/128); one warp per (b,t,h) row of 128.
// ---------------------------------------------------------------------------
__global__ __launch_bounds__(256) void normrope(float* __restrict__ q,
                                                float* __restrict__ k) {
    int gwarp = (blockIdx.x * blockDim.x + threadIdx.x) >> 5;
    int lane  = threadIdx.x & 31;
    const int nrows = BT * Hh;
    float* base = (gwarp < nrows) ? q : k;
    int row = (gwarp < nrows) ? gwarp : gwarp - nrows;
    int t = (row / Hh) % Tt;

    float* p = base + (size_t)row * Dd;
    float e0 = p[lane], e1 = p[lane + 32];
    float o0 = p[lane + 64], o1 = p[lane + 96];

    float ss = e0 * e0 + e1 * e1 + o0 * o0 + o1 * o1;
#pragma unroll
    for (int off = 16; off; off >>= 1) ss += __shfl_xor_sync(0xffffffffu, ss, off);

    float scale = rsqrtf(ss * (1.0f / 128.0f) + 1e-6f) * 0.08838834764831845f;
    e0 *= scale; e1 *= scale; o0 *= scale; o1 *= scale;

    float f0 = powf(10000.0f, -((float)lane) * (1.0f / 64.0f));
    float f1 = powf(10000.0f, -((float)(lane + 32)) * (1.0f / 64.0f));
    float r0 = (float)t * f0, r1 = (float)t * f1;
    float s0, c0, s1, c1;
    sincosf(r0, &s0, &c0);
    sincosf(r1, &s1, &c1);

    p[lane]      = e0 * c0 - o0 * s0;
    p[lane + 32] = e1 * c1 - o1 * s1;
    p[lane + 64] = e0 * s0 + o0 * c0;
    p[lane + 96] = e1 * s1 + o1 * c1;
}

// ---------------------------------------------------------------------------
// TF32 tensor-core flash attention (causal).
// Grid (T/128, H, B), 256 threads = 8 warps; warp w owns q-rows [16w,16w+16).
// BR=128, BC=64, D=128. All smem operands pre-rounded tf32.
// Fragment LDS patterns are bank-conflict-free: bank = (4*gid+tig)%32 unique.
// ---------------------------------------------------------------------------
#define BRt 128
#define BCt 64

__global__ __launch_bounds__(256) void attn_tc(const float* __restrict__ q,
                                               const float* __restrict__ k,
                                               const float* __restrict__ v,
                                               float* __restrict__ o) {
    extern __shared__ uint32_t smu[];
    uint32_t* Qs = smu;                 // [128][132]
    uint32_t* Ks = Qs + 128 * 132;      // [64][132]  row=key, col=d
    uint32_t* Vs = Ks + 64 * 132;       // [64][132]  row=key, col=d
    uint32_t* Ps = Vs + 64 * 132;       // [128][68]  row=q, col=key

    const int tid  = threadIdx.x;
    const int lane = tid & 31;
    const int warp = tid >> 5;
    const int gid  = lane >> 2;
    const int tig  = lane & 3;
    const int qb = blockIdx.x, h = blockIdx.y, b = blockIdx.z;
    const int t0 = qb * BRt;
    const int wrow = warp * 16;

    const size_t headOff = ((size_t)b * Tt * Hh + h) * Dd;
    const float* qbase = q + headOff;
    const float* kbase = k + headOff;
    const float* vbase = v + headOff;

    // Load + round Q tile
    for (int s = tid; s < BRt * 32; s += 256) {
        int r = s >> 5, c4 = (s & 31) << 2;
        float4 qv = *(const float4*)(qbase + (size_t)(t0 + r) * HD + c4);
        uint32_t* p = &Qs[r * 132 + c4];
        p[0] = f2tf32(qv.x); p[1] = f2tf32(qv.y);
        p[2] = f2tf32(qv.z); p[3] = f2tf32(qv.w);
    }

    float m0 = -1e30f, m1 = -1e30f, l0 = 0.f, l1 = 0.f;
    float oacc[16][4];
#pragma unroll
    for (int nt = 0; nt < 16; nt++)
#pragma unroll
        for (int i = 0; i < 4; i++) oacc[nt][i] = 0.f;
    __syncthreads();

    const int kbmax = 2 * qb + 1;
    for (int kb = 0; kb <= kbmax; kb++) {
        const int tk0 = kb * BCt;
        for (int s = tid; s < BCt * 32; s += 256) {
            int r = s >> 5, c4 = (s & 31) << 2;
            float4 kv = *(const float4*)(kbase + (size_t)(tk0 + r) * HD + c4);
            uint32_t* pk = &Ks[r * 132 + c4];
            pk[0] = f2tf32(kv.x); pk[1] = f2tf32(kv.y);
            pk[2] = f2tf32(kv.z); pk[3] = f2tf32(kv.w);
            float4 vv = *(const float4*)(vbase + (size_t)(tk0 + r) * HD + c4);
            uint32_t* pv = &Vs[r * 132 + c4];
            pv[0] = f2tf32(vv.x); pv[1] = f2tf32(vv.y);
            pv[2] = f2tf32(vv.z); pv[3] = f2tf32(vv.w);
        }
        __syncthreads();

        // S = Q K^T : warp tile 16x64
        float sacc[8][4];
#pragma unroll
        for (int nt = 0; nt < 8; nt++)
#pragma unroll
            for (int i = 0; i < 4; i++) sacc[nt][i] = 0.f;

#pragma unroll
        for (int ks = 0; ks < 16; ks++) {
            const int k0 = ks * 8;
            const uint32_t a0 = Qs[(wrow + gid) * 132 + k0 + tig];
            const uint32_t a1 = Qs[(wrow + gid + 8) * 132 + k0 + tig];
            const uint32_t a2 = Qs[(wrow + gid) * 132 + k0 + tig + 4];
            const uint32_t a3 = Qs[(wrow + gid + 8) * 132 + k0 + tig + 4];
#pragma unroll
            for (int nt = 0; nt < 8; nt++) {
                const uint32_t b0 = Ks[(nt * 8 + gid) * 132 + k0 + tig];
                const uint32_t b1 = Ks[(nt * 8 + gid) * 132 + k0 + tig + 4];
                mma_tf32(sacc[nt], a0, a1, a2, a3, b0, b1);
            }
        }

        // Causal mask (only possible on the two diagonal-overlap key blocks)
        if (kb >= 2 * qb) {
            const int rg0 = t0 + wrow + gid;
            const int rg1 = rg0 + 8;
#pragma unroll
            for (int nt = 0; nt < 8; nt++) {
                const int cg = tk0 + nt * 8 + 2 * tig;
                if (rg0 < cg)     sacc[nt][0] = -1e30f;
                if (rg0 < cg + 1) sacc[nt][1] = -1e30f;
                if (rg1 < cg)     sacc[nt][2] = -1e30f;
                if (rg1 < cg + 1) sacc[nt][3] = -1e30f;
            }
        }

        // Online softmax, in registers (rows live in quads)
        float rm0 = -1e30f, rm1 = -1e30f;
#pragma unroll
        for (int nt = 0; nt < 8; nt++) {
            rm0 = fmaxf(rm0, fmaxf(sacc[nt][0], sacc[nt][1]));
            rm1 = fmaxf(rm1, fmaxf(sacc[nt][2], sacc[nt][3]));
        }
        rm0 = fmaxf(rm0, __shfl_xor_sync(0xffffffffu, rm0, 1));
        rm0 = fmaxf(rm0, __shfl_xor_sync(0xffffffffu, rm0, 2));
        rm1 = fmaxf(rm1, __shfl_xor_sync(0xffffffffu, rm1, 1));
        rm1 = fmaxf(rm1, __shfl_xor_sync(0xffffffffu, rm1, 2));

        const float nm0 = fmaxf(m0, rm0);
        const float nm1 = fmaxf(m1, rm1);
        float sum0 = 0.f, sum1 = 0.f;
#pragma unroll
        for (int nt = 0; nt < 8; nt++) {
            float e00 = __expf(sacc[nt][0] - nm0);
            float e01 = __expf(sacc[nt][1] - nm0);
            float e10 = __expf(sacc[nt][2] - nm1);
            float e11 = __expf(sacc[nt][3] - nm1);
            sum0 += e00 + e01;
            sum1 += e10 + e11;
            uint2 p0 = make_uint2(f2tf32(e00), f2tf32(e01));
            uint2 p1 = make_uint2(f2tf32(e10), f2tf32(e11));
            *(uint2*)&Ps[(wrow + gid) * 68 + nt * 8 + 2 * tig]     = p0;
            *(uint2*)&Ps[(wrow + gid + 8) * 68 + nt * 8 + 2 * tig] = p1;
        }
        sum0 += __shfl_xor_sync(0xffffffffu, sum0, 1);
        sum0 += __shfl_xor_sync(0xffffffffu, sum0, 2);
        sum1 += __shfl_xor_sync(0xffffffffu, sum1, 1);
        sum1 += __shfl_xor_sync(0xffffffffu, sum1, 2);

        const float c0 = __expf(m0 - nm0);
        const float c1 = __expf(m1 - nm1);
        l0 = l0 * c0 + sum0; m0 = nm0;
        l1 = l1 * c1 + sum1; m1 = nm1;
#pragma unroll
        for (int nt = 0; nt < 16; nt++) {
            oacc[nt][0] *= c0; oacc[nt][1] *= c0;
            oacc[nt][2] *= c1; oacc[nt][3] *= c1;
        }
        __syncwarp();

        // O += P V : warp tile 16x128
#pragma unroll
        for (int ks = 0; ks < 8; ks++) {
            const int k0 = ks * 8;
            const uint32_t a0 = Ps[(wrow + gid) * 68 + k0 + tig];
            const uint32_t a1 = Ps[(wrow + gid + 8) * 68 + k0 + tig];
            const uint32_t a2 = Ps[(wrow + gid) * 68 + k0 + tig + 4];
            const uint32_t a3 = Ps[(wrow + gid + 8) * 68 + k0 + tig + 4];
#pragma unroll
            for (int nt = 0; nt < 16; nt++) {
                const uint32_t b0 = Vs[(k0 + tig) * 132 + nt * 8 + gid];
                const uint32_t b1 = Vs[(k0 + tig + 4) * 132 + nt * 8 + gid];
                mma_tf32(oacc[nt], a0, a1, a2, a3, b0, b1);
            }
        }
        __syncthreads();
    }

    // Epilogue
    const float i0 = 1.0f / l0;
    const float i1 = 1.0f / l1;
    float* obase = o + headOff;
    const int rg0 = t0 + wrow + gid;
#pragma unroll
    for (int nt = 0; nt < 16; nt++) {
        const int col = nt * 8 + 2 * tig;
        *(float2*)(obase + (size_t)rg0 * HD + col) =
            make_float2(oacc[nt][0] * i0, oacc[nt][1] * i0);
        *(float2*)(obase + (size_t)(rg0 + 8) * HD + col) =
            make_float2(oacc[nt][2] * i1, oacc[nt][3] * i1);
    }
}

// ---------------------------------------------------------------------------
extern "C" void kernel_launch(void* const* d_in, const int* in_sizes, int n_in,
                              void* d_out, int out_size) {
    const float* x  = (const float*)d_in[0];
    const float* wq = (const float*)d_in[1];
    const float* wk = (const float*)d_in[2];
    const float* wv = (const float*)d_in[3];
    const float* wo = (const float*)d_in[4];
    float* out = (float*)d_out;

    float *qp, *kp, *vp, *op;
    cudaGetSymbolAddress((void**)&qp, g_q);
    cudaGetSymbolAddress((void**)&kp, g_k);
    cudaGetSymbolAddress((void**)&vp, g_v);
    cudaGetSymbolAddress((void**)&op, g_o);

    // Fused QKV projections: one launch, z selects weight/output
    dim3 gp(HD / 128, BT / 128, 3);
    gemm_tf32<<<gp, 128>>>(x, wq, wk, wv, qp, kp, vp, BT, HD, Mm);

    // RMSNorm + RoPE + mult fold
    int totalWarps = 2 * BT * Hh;
    normrope<<<totalWarps / 8, 256>>>(qp, kp);

    // TF32 tensor-core causal attention
    size_t smem = (size_t)(128 * 132 + 64 * 132 + 64 * 132 + 128 * 68) * 4;
    cudaFuncSetAttribute(attn_tc, cudaFuncAttributeMaxDynamicSharedMemorySize, (int)smem);
    dim3 ga(Tt / BRt, Hh, Bq);
    attn_tc<<<ga, 256, smem>>>(qp, kp, vp, op);

    // Output projection
    dim3 go(Mm / 128, BT / 128, 1);
    gemm_tf32<<<go, 128>>>(op, wo, wo, wo, out, out, out, BT, Mm, HD);
}

// round 4
// speedup vs baseline: 4.7692x; 1.1321x over previous
#include <cuda_runtime.h>
#include <math.h>
#include <stdint.h>

// Problem dims (fixed)
#define Bq 2
#define Tt 2048
#define Mm 1024
#define Hh 8
#define Dd 128
#define BT (Bq*Tt)      // 4096
#define HD (Hh*Dd)      // 1024

// Scratch — [B,T,H,D] layouts, i.e. [BT, HD] row-major
__device__ float g_q[BT*HD];
__device__ float g_k[BT*HD];
__device__ float g_v[BT*HD];
__device__ float g_o[BT*HD];

__device__ __forceinline__ uint32_t f2tf32(float f) {
    uint32_t u;
    asm("cvt.rna.tf32.f32 %0, %1;" : "=r"(u) : "f"(f));
    return u;
}

__device__ __forceinline__ void mma_tf32(float c[4], uint32_t a0, uint32_t a1,
                                         uint32_t a2, uint32_t a3,
                                         uint32_t b0, uint32_t b1) {
    asm volatile(
        "mma.sync.aligned.m16n8k8.row.col.f32.tf32.tf32.f32 "
        "{%0,%1,%2,%3}, {%4,%5,%6,%7}, {%8,%9}, {%0,%1,%2,%3};\n"
        : "+f"(c[0]), "+f"(c[1]), "+f"(c[2]), "+f"(c[3])
        : "r"(a0), "r"(a1), "r"(a2), "r"(a3), "r"(b0), "r"(b1));
}

// ---------------------------------------------------------------------------
// TF32 tensor-core GEMM (unchanged from round 3): 128x128 tile, BK=8, 4 warps.
// Batched over blockIdx.z for fused QKV.
// ---------------------------------------------------------------------------
__global__ __launch_bounds__(128) void gemm_tf32(const float* __restrict__ A,
                                                 const float* __restrict__ B0,
                                                 const float* __restrict__ B1,
                                                 const float* __restrict__ B2,
                                                 float* __restrict__ C0,
                                                 float* __restrict__ C1,
                                                 float* __restrict__ C2,
                                                 int M, int N, int K) {
    const float* Bm = (blockIdx.z == 0) ? B0 : (blockIdx.z == 1) ? B1 : B2;
    float* C = (blockIdx.z == 0) ? C0 : (blockIdx.z == 1) ? C1 : C2;

    __shared__ uint32_t As[2][128 * 12];
    __shared__ uint32_t Bs[2][128 * 12];

    const int tid  = threadIdx.x;
    const int lane = tid & 31;
    const int warp = tid >> 5;
    const int gid  = lane >> 2;
    const int tig  = lane & 3;
    const int wm   = (warp >> 1) * 64;
    const int wn   = (warp & 1) * 64;
    const int rowBase = blockIdx.y * 128;
    const int colBase = blockIdx.x * 128;

    const float* Ag = A + (size_t)rowBase * K;
    const float* Bg = Bm + colBase;

    float acc[4][8][4];
#pragma unroll
    for (int mt = 0; mt < 4; mt++)
#pragma unroll
        for (int nt = 0; nt < 8; nt++)
#pragma unroll
            for (int i = 0; i < 4; i++) acc[mt][nt][i] = 0.f;

    float4 abuf0, abuf1;
    float  bbuf[8];
    const int am0 = tid >> 1;
    const int ak4 = (tid & 1) * 4;

    {
        abuf0 = *(const float4*)(Ag + (size_t)am0 * K + ak4);
        abuf1 = *(const float4*)(Ag + (size_t)(am0 + 64) * K + ak4);
#pragma unroll
        for (int kk = 0; kk < 8; kk++) bbuf[kk] = Bg[(size_t)kk * N + tid];

        uint32_t* ap = &As[0][am0 * 12 + ak4];
        ap[0] = f2tf32(abuf0.x); ap[1] = f2tf32(abuf0.y);
        ap[2] = f2tf32(abuf0.z); ap[3] = f2tf32(abuf0.w);
        uint32_t* ap2 = &As[0][(am0 + 64) * 12 + ak4];
        ap2[0] = f2tf32(abuf1.x); ap2[1] = f2tf32(abuf1.y);
        ap2[2] = f2tf32(abuf1.z); ap2[3] = f2tf32(abuf1.w);
        uint32_t* bp = &Bs[0][tid * 12];
#pragma unroll
        for (int kk = 0; kk < 8; kk++) bp[kk] = f2tf32(bbuf[kk]);
    }
    __syncthreads();

    const int niter = K >> 3;
    for (int it = 0; it < niter; it++) {
        const int cur = it & 1;
        if (it + 1 < niter) {
            const int k0 = (it + 1) << 3;
            abuf0 = *(const float4*)(Ag + (size_t)am0 * K + k0 + ak4);
            abuf1 = *(const float4*)(Ag + (size_t)(am0 + 64) * K + k0 + ak4);
#pragma unroll
            for (int kk = 0; kk < 8; kk++) bbuf[kk] = Bg[(size_t)(k0 + kk) * N + tid];
        }

        uint32_t af[4][4];
#pragma unroll
        for (int mt = 0; mt < 4; mt++) {
            const int r = wm + mt * 16 + gid;
            const uint32_t* p  = &As[cur][r * 12 + tig];
            const uint32_t* p8 = &As[cur][(r + 8) * 12 + tig];
            af[mt][0] = p[0];  af[mt][2] = p[4];
            af[mt][1] = p8[0]; af[mt][3] = p8[4];
        }
#pragma unroll
        for (int nt = 0; nt < 8; nt++) {
            const int n = wn + nt * 8 + gid;
            const uint32_t* bp = &Bs[cur][n * 12 + tig];
            const uint32_t b0 = bp[0], b1 = bp[4];
#pragma unroll
            for (int mt = 0; mt < 4; mt++)
                mma_tf32(acc[mt][nt], af[mt][0], af[mt][1], af[mt][2], af[mt][3], b0, b1);
        }

        if (it + 1 < niter) {
            const int nxt = cur ^ 1;
            uint32_t* ap = &As[nxt][am0 * 12 + ak4];
            ap[0] = f2tf32(abuf0.x); ap[1] = f2tf32(abuf0.y);
            ap[2] = f2tf32(abuf0.z); ap[3] = f2tf32(abuf0.w);
            uint32_t* ap2 = &As[nxt][(am0 + 64) * 12 + ak4];
            ap2[0] = f2tf32(abuf1.x); ap2[1] = f2tf32(abuf1.y);
            ap2[2] = f2tf32(abuf1.z); ap2[3] = f2tf32(abuf1.w);
            uint32_t* bp = &Bs[nxt][tid * 12];
#pragma unroll
            for (int kk = 0; kk < 8; kk++) bp[kk] = f2tf32(bbuf[kk]);
            __syncthreads();
        }
    }

#pragma unroll
    for (int mt = 0; mt < 4; mt++) {
#pragma unroll
        for (int nt = 0; nt < 8; nt++) {
            const int r0 = rowBase + wm + mt * 16 + gid;
            const int c0 = colBase + wn + nt * 8 + 2 * tig;
            *(float2*)(C + (size_t)r0 * N + c0)       = make_float2(acc[mt][nt][0], acc[mt][nt][1]);
            *(float2*)(C + (size_t)(r0 + 8) * N + c0) = make_float2(acc[mt][nt][2], acc[mt][nt][3]);
        }
    }
}

// ---------------------------------------------------------------------------
// RMSNorm + RoPE + fold sqrt(1/128); one warp per (b,t,h) row of 128.
// ---------------------------------------------------------------------------
__global__ __launch_bounds__(256) void normrope(float* __restrict__ q,
                                                float* __restrict__ k) {
    int gwarp = (blockIdx.x * blockDim.x + threadIdx.x) >> 5;
    int lane  = threadIdx.x & 31;
    const int nrows = BT * Hh;
    float* base = (gwarp < nrows) ? q : k;
    int row = (gwarp < nrows) ? gwarp : gwarp - nrows;
    int t = (row / Hh) % Tt;

    float* p = base + (size_t)row * Dd;
    float e0 = p[lane], e1 = p[lane + 32];
    float o0 = p[lane + 64], o1 = p[lane + 96];

    float ss = e0 * e0 + e1 * e1 + o0 * o0 + o1 * o1;
#pragma unroll
    for (int off = 16; off; off >>= 1) ss += __shfl_xor_sync(0xffffffffu, ss, off);

    float scale = rsqrtf(ss * (1.0f / 128.0f) + 1e-6f) * 0.08838834764831845f;
    e0 *= scale; e1 *= scale; o0 *= scale; o1 *= scale;

    float f0 = powf(10000.0f, -((float)lane) * (1.0f / 64.0f));
    float f1 = powf(10000.0f, -((float)(lane + 32)) * (1.0f / 64.0f));
    float r0 = (float)t * f0, r1 = (float)t * f1;
    float s0, c0, s1, c1;
    sincosf(r0, &s0, &c0);
    sincosf(r1, &s1, &c1);

    p[lane]      = e0 * c0 - o0 * s0;
    p[lane + 32] = e1 * c1 - o1 * s1;
    p[lane + 64] = e0 * s0 + o0 * c0;
    p[lane + 96] = e1 * s1 + o1 * c1;
}

// ---------------------------------------------------------------------------
// TF32 flash attention v2 (causal).
// BR=64, BC=64, 4 warps (warp w owns q-rows [16w,16w+16)).
// Q fragments cached in registers; P pane aliases the dead Q pane.
// smem = 3 * 64*132 words = 99 KB  -> 2 CTAs/SM.
// Heavy q-blocks launch first: qb = 31 - blockIdx.x.
// ---------------------------------------------------------------------------
#define BRt 64
#define BCt 64

__global__ __launch_bounds__(128) void attn_tc(const float* __restrict__ q,
                                               const float* __restrict__ k,
                                               const float* __restrict__ v,
                                               float* __restrict__ o) {
    extern __shared__ uint32_t smu[];
    uint32_t* Qs = smu;                 // [64][132]; becomes Ps [64][68] after prologue
    uint32_t* Ks = Qs + 64 * 132;       // [64][132]  row=key, col=d
    uint32_t* Vs = Ks + 64 * 132;       // [64][132]  row=key, col=d
    uint32_t* Ps = Qs;                  // alias (Q fragments live in registers)

    const int tid  = threadIdx.x;
    const int lane = tid & 31;
    const int warp = tid >> 5;
    const int gid  = lane >> 2;
    const int tig  = lane & 3;
    const int qb = (gridDim.x - 1) - blockIdx.x;   // heavy blocks first
    const int h = blockIdx.y, b = blockIdx.z;
    const int t0 = qb * BRt;
    const int wrow = warp * 16;

    const size_t headOff = ((size_t)b * Tt * Hh + h) * Dd;
    const float* qbase = q + headOff;
    const float* kbase = k + headOff;
    const float* vbase = v + headOff;

    // Prologue: stage Q tile in smem (coalesced), then lift fragments to regs.
    for (int s = tid; s < BRt * 32; s += 128) {
        int r = s >> 5, c4 = (s & 31) << 2;
        float4 qv = *(const float4*)(qbase + (size_t)(t0 + r) * HD + c4);
        uint32_t* p = &Qs[r * 132 + c4];
        p[0] = f2tf32(qv.x); p[1] = f2tf32(qv.y);
        p[2] = f2tf32(qv.z); p[3] = f2tf32(qv.w);
    }
    __syncthreads();

    uint32_t qf[16][4];
#pragma unroll
    for (int ks = 0; ks < 16; ks++) {
        const int k0 = ks * 8;
        qf[ks][0] = Qs[(wrow + gid) * 132 + k0 + tig];
        qf[ks][1] = Qs[(wrow + gid + 8) * 132 + k0 + tig];
        qf[ks][2] = Qs[(wrow + gid) * 132 + k0 + tig + 4];
        qf[ks][3] = Qs[(wrow + gid + 8) * 132 + k0 + tig + 4];
    }
    __syncthreads();   // Qs now dead; its space is Ps from here on

    float m0 = -1e30f, m1 = -1e30f, l0 = 0.f, l1 = 0.f;
    float oacc[16][4];
#pragma unroll
    for (int nt = 0; nt < 16; nt++)
#pragma unroll
        for (int i = 0; i < 4; i++) oacc[nt][i] = 0.f;

    for (int kb = 0; kb <= qb; kb++) {
        const int tk0 = kb * BCt;
        for (int s = tid; s < BCt * 32; s += 128) {
            int r = s >> 5, c4 = (s & 31) << 2;
            float4 kv = *(const float4*)(kbase + (size_t)(tk0 + r) * HD + c4);
            uint32_t* pk = &Ks[r * 132 + c4];
            pk[0] = f2tf32(kv.x); pk[1] = f2tf32(kv.y);
            pk[2] = f2tf32(kv.z); pk[3] = f2tf32(kv.w);
            float4 vv = *(const float4*)(vbase + (size_t)(tk0 + r) * HD + c4);
            uint32_t* pv = &Vs[r * 132 + c4];
            pv[0] = f2tf32(vv.x); pv[1] = f2tf32(vv.y);
            pv[2] = f2tf32(vv.z); pv[3] = f2tf32(vv.w);
        }
        __syncthreads();

        // S = Q K^T : warp tile 16x64, A from registers
        float sacc[8][4];
#pragma unroll
        for (int nt = 0; nt < 8; nt++)
#pragma unroll
            for (int i = 0; i < 4; i++) sacc[nt][i] = 0.f;

#pragma unroll
        for (int ks = 0; ks < 16; ks++) {
            const int k0 = ks * 8;
#pragma unroll
            for (int nt = 0; nt < 8; nt++) {
                const uint32_t b0 = Ks[(nt * 8 + gid) * 132 + k0 + tig];
                const uint32_t b1 = Ks[(nt * 8 + gid) * 132 + k0 + tig + 4];
                mma_tf32(sacc[nt], qf[ks][0], qf[ks][1], qf[ks][2], qf[ks][3], b0, b1);
            }
        }

        if (kb == qb) {   // diagonal block: causal mask
            const int rg0 = t0 + wrow + gid;
            const int rg1 = rg0 + 8;
#pragma unroll
            for (int nt = 0; nt < 8; nt++) {
                const int cg = tk0 + nt * 8 + 2 * tig;
                if (rg0 < cg)     sacc[nt][0] = -1e30f;
                if (rg0 < cg + 1) sacc[nt][1] = -1e30f;
                if (rg1 < cg)     sacc[nt][2] = -1e30f;
                if (rg1 < cg + 1) sacc[nt][3] = -1e30f;
            }
        }

        // Online softmax in registers (rows live in quads)
        float rm0 = -1e30f, rm1 = -1e30f;
#pragma unroll
        for (int nt = 0; nt < 8; nt++) {
            rm0 = fmaxf(rm0, fmaxf(sacc[nt][0], sacc[nt][1]));
            rm1 = fmaxf(rm1, fmaxf(sacc[nt][2], sacc[nt][3]));
        }
        rm0 = fmaxf(rm0, __shfl_xor_sync(0xffffffffu, rm0, 1));
        rm0 = fmaxf(rm0, __shfl_xor_sync(0xffffffffu, rm0, 2));
        rm1 = fmaxf(rm1, __shfl_xor_sync(0xffffffffu, rm1, 1));
        rm1 = fmaxf(rm1, __shfl_xor_sync(0xffffffffu, rm1, 2));

        const float nm0 = fmaxf(m0, rm0);
        const float nm1 = fmaxf(m1, rm1);
        float sum0 = 0.f, sum1 = 0.f;
#pragma unroll
        for (int nt = 0; nt < 8; nt++) {
            float e00 = __expf(sacc[nt][0] - nm0);
            float e01 = __expf(sacc[nt][1] - nm0);
            float e10 = __expf(sacc[nt][2] - nm1);
            float e11 = __expf(sacc[nt][3] - nm1);
            sum0 += e00 + e01;
            sum1 += e10 + e11;
            *(uint2*)&Ps[(wrow + gid) * 68 + nt * 8 + 2 * tig] =
                make_uint2(f2tf32(e00), f2tf32(e01));
            *(uint2*)&Ps[(wrow + gid + 8) * 68 + nt * 8 + 2 * tig] =
                make_uint2(f2tf32(e10), f2tf32(e11));
        }
        sum0 += __shfl_xor_sync(0xffffffffu, sum0, 1);
        sum0 += __shfl_xor_sync(0xffffffffu, sum0, 2);
        sum1 += __shfl_xor_sync(0xffffffffu, sum1, 1);
        sum1 += __shfl_xor_sync(0xffffffffu, sum1, 2);

        const float c0 = __expf(m0 - nm0);
        const float c1 = __expf(m1 - nm1);
        l0 = l0 * c0 + sum0; m0 = nm0;
        l1 = l1 * c1 + sum1; m1 = nm1;
#pragma unroll
        for (int nt = 0; nt < 16; nt++) {
            oacc[nt][0] *= c0; oacc[nt][1] *= c0;
            oacc[nt][2] *= c1; oacc[nt][3] *= c1;
        }
        __syncwarp();   // P visible across lanes of this warp

        // O += P V : warp tile 16x128 (P pane is per-warp private)
#pragma unroll
        for (int ks = 0; ks < 8; ks++) {
            const int k0 = ks * 8;
            const uint32_t a0 = Ps[(wrow + gid) * 68 + k0 + tig];
            const uint32_t a1 = Ps[(wrow + gid + 8) * 68 + k0 + tig];
            const uint32_t a2 = Ps[(wrow + gid) * 68 + k0 + tig + 4];
            const uint32_t a3 = Ps[(wrow + gid + 8) * 68 + k0 + tig + 4];
#pragma unroll
            for (int nt = 0; nt < 16; nt++) {
                const uint32_t b0 = Vs[(k0 + tig) * 132 + nt * 8 + gid];
                const uint32_t b1 = Vs[(k0 + tig + 4) * 132 + nt * 8 + gid];
                mma_tf32(oacc[nt], a0, a1, a2, a3, b0, b1);
            }
        }
        __syncthreads();   // all warps done with Ks/Vs before next load
    }

    const float i0 = 1.0f / l0;
    const float i1 = 1.0f / l1;
    float* obase = o + headOff;
    const int rg0 = t0 + wrow + gid;
#pragma unroll
    for (int nt = 0; nt < 16; nt++) {
        const int col = nt * 8 + 2 * tig;
        *(float2*)(obase + (size_t)rg0 * HD + col) =
            make_float2(oacc[nt][0] * i0, oacc[nt][1] * i0);
        *(float2*)(obase + (size_t)(rg0 + 8) * HD + col) =
            make_float2(oacc[nt][2] * i1, oacc[nt][3] * i1);
    }
}

// ---------------------------------------------------------------------------
extern "C" void kernel_launch(void* const* d_in, const int* in_sizes, int n_in,
                              void* d_out, int out_size) {
    const float* x  = (const float*)d_in[0];
    const float* wq = (const float*)d_in[1];
    const float* wk = (const float*)d_in[2];
    const float* wv = (const float*)d_in[3];
    const float* wo = (const float*)d_in[4];
    float* out = (float*)d_out;

    float *qp, *kp, *vp, *op;
    cudaGetSymbolAddress((void**)&qp, g_q);
    cudaGetSymbolAddress((void**)&kp, g_k);
    cudaGetSymbolAddress((void**)&vp, g_v);
    cudaGetSymbolAddress((void**)&op, g_o);

    // Fused QKV projections
    dim3 gp(HD / 128, BT / 128, 3);
    gemm_tf32<<<gp, 128>>>(x, wq, wk, wv, qp, kp, vp, BT, HD, Mm);

    // RMSNorm + RoPE + mult fold
    int totalWarps = 2 * BT * Hh;
    normrope<<<totalWarps / 8, 256>>>(qp, kp);

    // TF32 tensor-core causal attention v2
    size_t smem = (size_t)(3 * 64 * 132) * 4;   // 101376 B -> 2 CTAs/SM
    cudaFuncSetAttribute(attn_tc, cudaFuncAttributeMaxDynamicSharedMemorySize, (int)smem);
    dim3 ga(Tt / BRt, Hh, Bq);
    attn_tc<<<ga, 128, smem>>>(qp, kp, vp, op);

    // Output projection
    dim3 go(Mm / 128, BT / 128, 1);
    gemm_tf32<<<go, 128>>>(op, wo, wo, wo, out, out, out, BT, Mm, HD);
}

// round 5
// speedup vs baseline: 5.1759x; 1.0853x over previous
#include <cuda_runtime.h>
#include <math.h>
#include <stdint.h>

// Problem dims (fixed)
#define Bq 2
#define Tt 2048
#define Mm 1024
#define Hh 8
#define Dd 128
#define BT (Bq*Tt)      // 4096
#define HD (Hh*Dd)      // 1024

// Scratch — [B,T,H,D] layouts, i.e. [BT, HD] row-major
__device__ float g_q[BT*HD];
__device__ float g_k[BT*HD];
__device__ float g_v[BT*HD];
__device__ float g_o[BT*HD];

__device__ __forceinline__ uint32_t f2tf32(float f) {
    uint32_t u;
    asm("cvt.rna.tf32.f32 %0, %1;" : "=r"(u) : "f"(f));
    return u;
}

__device__ __forceinline__ void mma_tf32(float c[4], uint32_t a0, uint32_t a1,
                                         uint32_t a2, uint32_t a3,
                                         uint32_t b0, uint32_t b1) {
    asm volatile(
        "mma.sync.aligned.m16n8k8.row.col.f32.tf32.tf32.f32 "
        "{%0,%1,%2,%3}, {%4,%5,%6,%7}, {%8,%9}, {%0,%1,%2,%3};\n"
        : "+f"(c[0]), "+f"(c[1]), "+f"(c[2]), "+f"(c[3])
        : "r"(a0), "r"(a1), "r"(a2), "r"(a3), "r"(b0), "r"(b1));
}

__device__ __forceinline__ void cp16(uint32_t dst, const void* src) {
    asm volatile("cp.async.ca.shared.global [%0], [%1], 16;\n" :: "r"(dst), "l"(src));
}
#define CP_COMMIT() asm volatile("cp.async.commit_group;\n" ::: "memory")
#define CP_WAIT(n)  asm volatile("cp.async.wait_group %0;\n" :: "n"(n) : "memory")

// ---------------------------------------------------------------------------
// TF32 tensor-core GEMM: 128x128 tile, BK=8, 4 warps. Batched over z.
// roundMask bit z => write tf32-rounded output (so attention skips cvt).
// ---------------------------------------------------------------------------
__global__ __launch_bounds__(128) void gemm_tf32(const float* __restrict__ A,
                                                 const float* __restrict__ B0,
                                                 const float* __restrict__ B1,
                                                 const float* __restrict__ B2,
                                                 float* __restrict__ C0,
                                                 float* __restrict__ C1,
                                                 float* __restrict__ C2,
                                                 int M, int N, int K,
                                                 unsigned roundMask) {
    const float* Bm = (blockIdx.z == 0) ? B0 : (blockIdx.z == 1) ? B1 : B2;
    float* C = (blockIdx.z == 0) ? C0 : (blockIdx.z == 1) ? C1 : C2;
    const bool doRound = (roundMask >> blockIdx.z) & 1u;

    __shared__ uint32_t As[2][128 * 12];
    __shared__ uint32_t Bs[2][128 * 12];

    const int tid  = threadIdx.x;
    const int lane = tid & 31;
    const int warp = tid >> 5;
    const int gid  = lane >> 2;
    const int tig  = lane & 3;
    const int wm   = (warp >> 1) * 64;
    const int wn   = (warp & 1) * 64;
    const int rowBase = blockIdx.y * 128;
    const int colBase = blockIdx.x * 128;

    const float* Ag = A + (size_t)rowBase * K;
    const float* Bg = Bm + colBase;

    float acc[4][8][4];
#pragma unroll
    for (int mt = 0; mt < 4; mt++)
#pragma unroll
        for (int nt = 0; nt < 8; nt++)
#pragma unroll
            for (int i = 0; i < 4; i++) acc[mt][nt][i] = 0.f;

    float4 abuf0, abuf1;
    float  bbuf[8];
    const int am0 = tid >> 1;
    const int ak4 = (tid & 1) * 4;

    {
        abuf0 = *(const float4*)(Ag + (size_t)am0 * K + ak4);
        abuf1 = *(const float4*)(Ag + (size_t)(am0 + 64) * K + ak4);
#pragma unroll
        for (int kk = 0; kk < 8; kk++) bbuf[kk] = Bg[(size_t)kk * N + tid];

        uint32_t* ap = &As[0][am0 * 12 + ak4];
        ap[0] = f2tf32(abuf0.x); ap[1] = f2tf32(abuf0.y);
        ap[2] = f2tf32(abuf0.z); ap[3] = f2tf32(abuf0.w);
        uint32_t* ap2 = &As[0][(am0 + 64) * 12 + ak4];
        ap2[0] = f2tf32(abuf1.x); ap2[1] = f2tf32(abuf1.y);
        ap2[2] = f2tf32(abuf1.z); ap2[3] = f2tf32(abuf1.w);
        uint32_t* bp = &Bs[0][tid * 12];
#pragma unroll
        for (int kk = 0; kk < 8; kk++) bp[kk] = f2tf32(bbuf[kk]);
    }
    __syncthreads();

    const int niter = K >> 3;
    for (int it = 0; it < niter; it++) {
        const int cur = it & 1;
        if (it + 1 < niter) {
            const int k0 = (it + 1) << 3;
            abuf0 = *(const float4*)(Ag + (size_t)am0 * K + k0 + ak4);
            abuf1 = *(const float4*)(Ag + (size_t)(am0 + 64) * K + k0 + ak4);
#pragma unroll
            for (int kk = 0; kk < 8; kk++) bbuf[kk] = Bg[(size_t)(k0 + kk) * N + tid];
        }

        uint32_t af[4][4];
#pragma unroll
        for (int mt = 0; mt < 4; mt++) {
            const int r = wm + mt * 16 + gid;
            const uint32_t* p  = &As[cur][r * 12 + tig];
            const uint32_t* p8 = &As[cur][(r + 8) * 12 + tig];
            af[mt][0] = p[0];  af[mt][2] = p[4];
            af[mt][1] = p8[0]; af[mt][3] = p8[4];
        }
#pragma unroll
        for (int nt = 0; nt < 8; nt++) {
            const int n = wn + nt * 8 + gid;
            const uint32_t* bp = &Bs[cur][n * 12 + tig];
            const uint32_t b0 = bp[0], b1 = bp[4];
#pragma unroll
            for (int mt = 0; mt < 4; mt++)
                mma_tf32(acc[mt][nt], af[mt][0], af[mt][1], af[mt][2], af[mt][3], b0, b1);
        }

        if (it + 1 < niter) {
            const int nxt = cur ^ 1;
            uint32_t* ap = &As[nxt][am0 * 12 + ak4];
            ap[0] = f2tf32(abuf0.x); ap[1] = f2tf32(abuf0.y);
            ap[2] = f2tf32(abuf0.z); ap[3] = f2tf32(abuf0.w);
            uint32_t* ap2 = &As[nxt][(am0 + 64) * 12 + ak4];
            ap2[0] = f2tf32(abuf1.x); ap2[1] = f2tf32(abuf1.y);
            ap2[2] = f2tf32(abuf1.z); ap2[3] = f2tf32(abuf1.w);
            uint32_t* bp = &Bs[nxt][tid * 12];
#pragma unroll
            for (int kk = 0; kk < 8; kk++) bp[kk] = f2tf32(bbuf[kk]);
            __syncthreads();
        }
    }

    if (doRound) {
#pragma unroll
        for (int mt = 0; mt < 4; mt++)
#pragma unroll
            for (int nt = 0; nt < 8; nt++)
#pragma unroll
                for (int i = 0; i < 4; i++)
                    acc[mt][nt][i] = __uint_as_float(f2tf32(acc[mt][nt][i]));
    }

#pragma unroll
    for (int mt = 0; mt < 4; mt++) {
#pragma unroll
        for (int nt = 0; nt < 8; nt++) {
            const int r0 = rowBase + wm + mt * 16 + gid;
            const int c0 = colBase + wn + nt * 8 + 2 * tig;
            *(float2*)(C + (size_t)r0 * N + c0)       = make_float2(acc[mt][nt][0], acc[mt][nt][1]);
            *(float2*)(C + (size_t)(r0 + 8) * N + c0) = make_float2(acc[mt][nt][2], acc[mt][nt][3]);
        }
    }
}

// ---------------------------------------------------------------------------
// RMSNorm + RoPE + fold sqrt(1/128); writes tf32-rounded bits.
// ---------------------------------------------------------------------------
__global__ __launch_bounds__(256) void normrope(float* __restrict__ q,
                                                float* __restrict__ k) {
    int gwarp = (blockIdx.x * blockDim.x + threadIdx.x) >> 5;
    int lane  = threadIdx.x & 31;
    const int nrows = BT * Hh;
    float* base = (gwarp < nrows) ? q : k;
    int row = (gwarp < nrows) ? gwarp : gwarp - nrows;
    int t = (row / Hh) % Tt;

    float* p = base + (size_t)row * Dd;
    float e0 = p[lane], e1 = p[lane + 32];
    float o0 = p[lane + 64], o1 = p[lane + 96];

    float ss = e0 * e0 + e1 * e1 + o0 * o0 + o1 * o1;
#pragma unroll
    for (int off = 16; off; off >>= 1) ss += __shfl_xor_sync(0xffffffffu, ss, off);

    float scale = rsqrtf(ss * (1.0f / 128.0f) + 1e-6f) * 0.08838834764831845f;
    e0 *= scale; e1 *= scale; o0 *= scale; o1 *= scale;

    float f0 = powf(10000.0f, -((float)lane) * (1.0f / 64.0f));
    float f1 = powf(10000.0f, -((float)(lane + 32)) * (1.0f / 64.0f));
    float r0 = (float)t * f0, r1 = (float)t * f1;
    float s0, c0, s1, c1;
    sincosf(r0, &s0, &c0);
    sincosf(r1, &s1, &c1);

    p[lane]      = __uint_as_float(f2tf32(e0 * c0 - o0 * s0));
    p[lane + 32] = __uint_as_float(f2tf32(e1 * c1 - o1 * s1));
    p[lane + 64] = __uint_as_float(f2tf32(e0 * s0 + o0 * c0));
    p[lane + 96] = __uint_as_float(f2tf32(e1 * s1 + o1 * c1));
}

// ---------------------------------------------------------------------------
// TF32 flash attention v3 (causal): BR=128 (8 warps), BC=64.
// Inputs pre-rounded tf32 -> K/V loads are raw cp.async 16B, double-buffered.
// Q fragments in registers. Heavy q-blocks first.
// smem words: Ps 128*68 | K0 64*132 | V0 64*136 | K1 64*132 | V1 64*136
// ---------------------------------------------------------------------------
#define BRt 128
#define BCt 64
#define KSTR 132
#define VSTR 136
#define PSTR 68
#define OFF_PS 0
#define OFF_K0 (128*PSTR)                    // 8704
#define OFF_V0 (OFF_K0 + 64*KSTR)            // 17152
#define OFF_K1 (OFF_V0 + 64*VSTR)            // 25856
#define OFF_V1 (OFF_K1 + 64*KSTR)            // 34304
#define SM_WORDS (OFF_V1 + 64*VSTR)          // 43008 -> 172032 B

__global__ __launch_bounds__(256) void attn_tc(const float* __restrict__ q,
                                               const float* __restrict__ k,
                                               const float* __restrict__ v,
                                               float* __restrict__ o) {
    extern __shared__ uint32_t smu[];
    uint32_t* Ps = smu + OFF_PS;

    const int tid  = threadIdx.x;
    const int lane = tid & 31;
    const int warp = tid >> 5;
    const int gid  = lane >> 2;
    const int tig  = lane & 3;
    const int qb = (gridDim.x - 1) - blockIdx.x;   // heavy blocks first
    const int h = blockIdx.y, b = blockIdx.z;
    const int t0 = qb * BRt;
    const int wrow = warp * 16;

    const size_t headOff = ((size_t)b * Tt * Hh + h) * Dd;
    const float* qbase = q + headOff;
    const float* kbase = k + headOff;
    const float* vbase = v + headOff;

    const uint32_t smemBase = (uint32_t)__cvta_generic_to_shared(smu);

    // cp.async chunk mapping: 2048 16B-chunks per 64x128 tile, 8 per thread
    const int crow = tid >> 1;          // not used; mapping below uses s-loop
    (void)crow;

    // ---- issue kb=0 loads into buf0 ----
    {
        const int tk0 = 0;
#pragma unroll
        for (int i = 0; i < 8; i++) {
            const int s = tid + i * 256;          // 0..2047
            const int r = s >> 5, c4 = (s & 31) << 2;
            cp16(smemBase + (OFF_K0 + r * KSTR + c4) * 4,
                 kbase + (size_t)(tk0 + r) * HD + c4);
            cp16(smemBase + (OFF_V0 + r * VSTR + c4) * 4,
                 vbase + (size_t)(tk0 + r) * HD + c4);
        }
        CP_COMMIT();
    }

    // ---- stage Q (pre-rounded tf32 bits) into buf1 region, stride 132 ----
    uint32_t* Qstage = smu + OFF_K1;
    for (int s = tid; s < BRt * 32; s += 256) {
        int r = s >> 5, c4 = (s & 31) << 2;
        float4 qv = *(const float4*)(qbase + (size_t)(t0 + r) * HD + c4);
        uint32_t* p = &Qstage[r * 132 + c4];
        p[0] = __float_as_uint(qv.x); p[1] = __float_as_uint(qv.y);
        p[2] = __float_as_uint(qv.z); p[3] = __float_as_uint(qv.w);
    }
    __syncthreads();

    uint32_t qf[16][4];
#pragma unroll
    for (int ks = 0; ks < 16; ks++) {
        const int k0 = ks * 8;
        qf[ks][0] = Qstage[(wrow + gid) * 132 + k0 + tig];
        qf[ks][1] = Qstage[(wrow + gid + 8) * 132 + k0 + tig];
        qf[ks][2] = Qstage[(wrow + gid) * 132 + k0 + tig + 4];
        qf[ks][3] = Qstage[(wrow + gid + 8) * 132 + k0 + tig + 4];
    }
    __syncthreads();   // buf1 free for cp.async reuse

    float m0 = -1e30f, m1 = -1e30f, l0 = 0.f, l1 = 0.f;
    float oacc[16][4];
#pragma unroll
    for (int nt = 0; nt < 16; nt++)
#pragma unroll
        for (int i = 0; i < 4; i++) oacc[nt][i] = 0.f;

    const int kbmax = 2 * qb + 1;
    for (int kb = 0; kb <= kbmax; kb++) {
        // issue next block's loads into the other buffer
        if (kb + 1 <= kbmax) {
            const int tk0 = (kb + 1) * BCt;
            const int offK = ((kb + 1) & 1) ? OFF_K1 : OFF_K0;
            const int offV = ((kb + 1) & 1) ? OFF_V1 : OFF_V0;
#pragma unroll
            for (int i = 0; i < 8; i++) {
                const int s = tid + i * 256;
                const int r = s >> 5, c4 = (s & 31) << 2;
                cp16(smemBase + (offK + r * KSTR + c4) * 4,
                     kbase + (size_t)(tk0 + r) * HD + c4);
                cp16(smemBase + (offV + r * VSTR + c4) * 4,
                     vbase + (size_t)(tk0 + r) * HD + c4);
            }
            CP_COMMIT();
            CP_WAIT(1);
        } else {
            CP_WAIT(0);
        }
        __syncthreads();

        const uint32_t* Ks = smu + ((kb & 1) ? OFF_K1 : OFF_K0);
        const uint32_t* Vs = smu + ((kb & 1) ? OFF_V1 : OFF_V0);
        const int tk0 = kb * BCt;

        // S = Q K^T : warp tile 16x64, A from registers
        float sacc[8][4];
#pragma unroll
        for (int nt = 0; nt < 8; nt++)
#pragma unroll
            for (int i = 0; i < 4; i++) sacc[nt][i] = 0.f;

#pragma unroll
        for (int ks = 0; ks < 16; ks++) {
            const int k0 = ks * 8;
#pragma unroll
            for (int nt = 0; nt < 8; nt++) {
                const uint32_t b0 = Ks[(nt * 8 + gid) * KSTR + k0 + tig];
                const uint32_t b1 = Ks[(nt * 8 + gid) * KSTR + k0 + tig + 4];
                mma_tf32(sacc[nt], qf[ks][0], qf[ks][1], qf[ks][2], qf[ks][3], b0, b1);
            }
        }

        if (kb >= 2 * qb) {   // diagonal-overlap blocks: causal mask
            const int rg0 = t0 + wrow + gid;
            const int rg1 = rg0 + 8;
#pragma unroll
            for (int nt = 0; nt < 8; nt++) {
                const int cg = tk0 + nt * 8 + 2 * tig;
                if (rg0 < cg)     sacc[nt][0] = -1e30f;
                if (rg0 < cg + 1) sacc[nt][1] = -1e30f;
                if (rg1 < cg)     sacc[nt][2] = -1e30f;
                if (rg1 < cg + 1) sacc[nt][3] = -1e30f;
            }
        }

        // Online softmax in registers (rows live in quads)
        float rm0 = -1e30f, rm1 = -1e30f;
#pragma unroll
        for (int nt = 0; nt < 8; nt++) {
            rm0 = fmaxf(rm0, fmaxf(sacc[nt][0], sacc[nt][1]));
            rm1 = fmaxf(rm1, fmaxf(sacc[nt][2], sacc[nt][3]));
        }
        rm0 = fmaxf(rm0, __shfl_xor_sync(0xffffffffu, rm0, 1));
        rm0 = fmaxf(rm0, __shfl_xor_sync(0xffffffffu, rm0, 2));
        rm1 = fmaxf(rm1, __shfl_xor_sync(0xffffffffu, rm1, 1));
        rm1 = fmaxf(rm1, __shfl_xor_sync(0xffffffffu, rm1, 2));

        const float nm0 = fmaxf(m0, rm0);
        const float nm1 = fmaxf(m1, rm1);
        float sum0 = 0.f, sum1 = 0.f;
#pragma unroll
        for (int nt = 0; nt < 8; nt++) {
            float e00 = __expf(sacc[nt][0] - nm0);
            float e01 = __expf(sacc[nt][1] - nm0);
            float e10 = __expf(sacc[nt][2] - nm1);
            float e11 = __expf(sacc[nt][3] - nm1);
            sum0 += e00 + e01;
            sum1 += e10 + e11;
            *(uint2*)&Ps[(wrow + gid) * PSTR + nt * 8 + 2 * tig] =
                make_uint2(f2tf32(e00), f2tf32(e01));
            *(uint2*)&Ps[(wrow + gid + 8) * PSTR + nt * 8 + 2 * tig] =
                make_uint2(f2tf32(e10), f2tf32(e11));
        }
        sum0 += __shfl_xor_sync(0xffffffffu, sum0, 1);
        sum0 += __shfl_xor_sync(0xffffffffu, sum0, 2);
        sum1 += __shfl_xor_sync(0xffffffffu, sum1, 1);
        sum1 += __shfl_xor_sync(0xffffffffu, sum1, 2);

        const float c0 = __expf(m0 - nm0);
        const float c1 = __expf(m1 - nm1);
        l0 = l0 * c0 + sum0; m0 = nm0;
        l1 = l1 * c1 + sum1; m1 = nm1;
#pragma unroll
        for (int nt = 0; nt < 16; nt++) {
            oacc[nt][0] *= c0; oacc[nt][1] *= c0;
            oacc[nt][2] *= c1; oacc[nt][3] *= c1;
        }
        __syncwarp();

        // O += P V : warp tile 16x128 (P pane per-warp private)
#pragma unroll
        for (int ks = 0; ks < 8; ks++) {
            const int k0 = ks * 8;
            const uint32_t a0 = Ps[(wrow + gid) * PSTR + k0 + tig];
            const uint32_t a1 = Ps[(wrow + gid + 8) * PSTR + k0 + tig];
            const uint32_t a2 = Ps[(wrow + gid) * PSTR + k0 + tig + 4];
            const uint32_t a3 = Ps[(wrow + gid + 8) * PSTR + k0 + tig + 4];
#pragma unroll
            for (int nt = 0; nt < 16; nt++) {
                const uint32_t b0 = Vs[(k0 + tig) * VSTR + nt * 8 + gid];
                const uint32_t b1 = Vs[(k0 + tig + 4) * VSTR + nt * 8 + gid];
                mma_tf32(oacc[nt], a0, a1, a2, a3, b0, b1);
            }
        }
        __syncthreads();   // buffer kb&1 free before it is re-issued
    }

    const float i0 = 1.0f / l0;
    const float i1 = 1.0f / l1;
    float* obase = o + headOff;
    const int rg0 = t0 + wrow + gid;
#pragma unroll
    for (int nt = 0; nt < 16; nt++) {
        const int col = nt * 8 + 2 * tig;
        *(float2*)(obase + (size_t)rg0 * HD + col) =
            make_float2(oacc[nt][0] * i0, oacc[nt][1] * i0);
        *(float2*)(obase + (size_t)(rg0 + 8) * HD + col) =
            make_float2(oacc[nt][2] * i1, oacc[nt][3] * i1);
    }
}

// ---------------------------------------------------------------------------
extern "C" void kernel_launch(void* const* d_in, const int* in_sizes, int n_in,
                              void* d_out, int out_size) {
    const float* x  = (const float*)d_in[0];
    const float* wq = (const float*)d_in[1];
    const float* wk = (const float*)d_in[2];
    const float* wv = (const float*)d_in[3];
    const float* wo = (const float*)d_in[4];
    float* out = (float*)d_out;

    float *qp, *kp, *vp, *op;
    cudaGetSymbolAddress((void**)&qp, g_q);
    cudaGetSymbolAddress((void**)&kp, g_k);
    cudaGetSymbolAddress((void**)&vp, g_v);
    cudaGetSymbolAddress((void**)&op, g_o);

    // Fused QKV projections; round all three outputs to tf32 bits
    dim3 gp(HD / 128, BT / 128, 3);
    gemm_tf32<<<gp, 128>>>(x, wq, wk, wv, qp, kp, vp, BT, HD, Mm, 7u);

    // RMSNorm + RoPE + mult fold (writes tf32-rounded)
    int totalWarps = 2 * BT * Hh;
    normrope<<<totalWarps / 8, 256>>>(qp, kp);

    // TF32 flash attention v3 (cp.async double-buffered)
    size_t smem = (size_t)SM_WORDS * 4;
    cudaFuncSetAttribute(attn_tc, cudaFuncAttributeMaxDynamicSharedMemorySize, (int)smem);
    dim3 ga(Tt / BRt, Hh, Bq);
    attn_tc<<<ga, 256, smem>>>(qp, kp, vp, op);

    // Output projection (no rounding of final output)
    dim3 go(Mm / 128, BT / 128, 1);
    gemm_tf32<<<go, 128>>>(op, wo, wo, wo, out, out, out, BT, Mm, HD, 0u);
}

// round 6
// speedup vs baseline: 6.0742x; 1.1735x over previous
#include <cuda_runtime.h>
#include <math.h>
#include <stdint.h>

// Problem dims (fixed)
#define Bq 2
#define Tt 2048
#define Mm 1024
#define Hh 8
#define Dd 128
#define BT (Bq*Tt)      // 4096
#define HD (Hh*Dd)      // 1024

// Scratch — no cudaMalloc allowed
__device__ float g_q[BT*HD];
__device__ float g_k[BT*HD];
__device__ float g_v[BT*HD];
__device__ float g_o[BT*HD];
__device__ float g_xr[BT*Mm];      // tf32-rounded x
__device__ float g_wqr[Mm*HD];
__device__ float g_wkr[Mm*HD];
__device__ float g_wvr[Mm*HD];
__device__ float g_wor[HD*Mm];

__device__ __forceinline__ uint32_t f2tf32(float f) {
    uint32_t u;
    asm("cvt.rna.tf32.f32 %0, %1;" : "=r"(u) : "f"(f));
    return u;
}

__device__ __forceinline__ void mma_tf32(float c[4], uint32_t a0, uint32_t a1,
                                         uint32_t a2, uint32_t a3,
                                         uint32_t b0, uint32_t b1) {
    asm volatile(
        "mma.sync.aligned.m16n8k8.row.col.f32.tf32.tf32.f32 "
        "{%0,%1,%2,%3}, {%4,%5,%6,%7}, {%8,%9}, {%0,%1,%2,%3};\n"
        : "+f"(c[0]), "+f"(c[1]), "+f"(c[2]), "+f"(c[3])
        : "r"(a0), "r"(a1), "r"(a2), "r"(a3), "r"(b0), "r"(b1));
}

__device__ __forceinline__ void cp16(uint32_t dst, const void* src) {
    asm volatile("cp.async.ca.shared.global [%0], [%1], 16;\n" :: "r"(dst), "l"(src));
}
#define CP_COMMIT() asm volatile("cp.async.commit_group;\n" ::: "memory")
#define CP_WAIT(n)  asm volatile("cp.async.wait_group %0;\n" :: "n"(n) : "memory")

// ---------------------------------------------------------------------------
// Pre-round fp32 array to tf32 bits (grid-stride float4).
// ---------------------------------------------------------------------------
__global__ __launch_bounds__(256) void pre_round(const float* __restrict__ src,
                                                 float* __restrict__ dst, int n4) {
    int i = blockIdx.x * blockDim.x + threadIdx.x;
    if (i < n4) {
        float4 v = ((const float4*)src)[i];
        v.x = __uint_as_float(f2tf32(v.x));
        v.y = __uint_as_float(f2tf32(v.y));
        v.z = __uint_as_float(f2tf32(v.z));
        v.w = __uint_as_float(f2tf32(v.w));
        ((float4*)dst)[i] = v;
    }
}

// ---------------------------------------------------------------------------
// TF32 GEMM v2: C[M,N] = A[M,K]*B[K,N]; inputs pre-rounded tf32 bits.
// 128x128 CTA tile, BK=16, 256 threads (8 warps, 32x64 warp tiles).
// cp.async double-buffered. As[m][k] stride 20; Bs[k][n] stride 136.
// Batched over blockIdx.z; roundMask bit z => round output to tf32.
// ---------------------------------------------------------------------------
#define GASTR 20
#define GBSTR 136

__global__ __launch_bounds__(256) void gemm_tf32(const float* __restrict__ A,
                                                 const float* __restrict__ B0,
                                                 const float* __restrict__ B1,
                                                 const float* __restrict__ B2,
                                                 float* __restrict__ C0,
                                                 float* __restrict__ C1,
                                                 float* __restrict__ C2,
                                                 int M, int N, int K,
                                                 unsigned roundMask) {
    const float* Bm = (blockIdx.z == 0) ? B0 : (blockIdx.z == 1) ? B1 : B2;
    float* C = (blockIdx.z == 0) ? C0 : (blockIdx.z == 1) ? C1 : C2;
    const bool doRound = (roundMask >> blockIdx.z) & 1u;

    __shared__ uint32_t As[2][128 * GASTR];
    __shared__ uint32_t Bs[2][16 * GBSTR];

    const int tid  = threadIdx.x;
    const int lane = tid & 31;
    const int warp = tid >> 5;
    const int gid  = lane >> 2;
    const int tig  = lane & 3;
    const int wm   = (warp >> 1) * 32;
    const int wn   = (warp & 1) * 64;
    const int rowBase = blockIdx.y * 128;
    const int colBase = blockIdx.x * 128;

    const float* Ag = A + (size_t)rowBase * K;
    const float* Bg = Bm + colBase;
    const uint32_t sA = (uint32_t)__cvta_generic_to_shared(&As[0][0]);
    const uint32_t sB = (uint32_t)__cvta_generic_to_shared(&Bs[0][0]);

    float acc[2][8][4];
#pragma unroll
    for (int mt = 0; mt < 2; mt++)
#pragma unroll
        for (int nt = 0; nt < 8; nt++)
#pragma unroll
            for (int i = 0; i < 4; i++) acc[mt][nt][i] = 0.f;

    // ---- issue tile 0 ----
    {
        const int k0 = 0;
#pragma unroll
        for (int i = 0; i < 2; i++) {
            const int s = tid + i * 256;
            const int r = s >> 2, c4 = (s & 3) << 2;
            cp16(sA + (r * GASTR + c4) * 4, Ag + (size_t)r * K + k0 + c4);
        }
#pragma unroll
        for (int i = 0; i < 2; i++) {
            const int s = tid + i * 256;
            const int kk = s >> 5, c4 = (s & 31) << 2;
            cp16(sB + (kk * GBSTR + c4) * 4, Bg + (size_t)(k0 + kk) * N + c4);
        }
        CP_COMMIT();
    }

    const int niter = K >> 4;   // K/16
    for (int it = 0; it < niter; it++) {
        const int cur = it & 1;
        if (it + 1 < niter) {
            const int k0 = (it + 1) << 4;
            const int nxt = (it + 1) & 1;
#pragma unroll
            for (int i = 0; i < 2; i++) {
                const int s = tid + i * 256;
                const int r = s >> 2, c4 = (s & 3) << 2;
                cp16(sA + (nxt * 128 * GASTR + r * GASTR + c4) * 4,
                     Ag + (size_t)r * K + k0 + c4);
            }
#pragma unroll
            for (int i = 0; i < 2; i++) {
                const int s = tid + i * 256;
                const int kk = s >> 5, c4 = (s & 31) << 2;
                cp16(sB + (nxt * 16 * GBSTR + kk * GBSTR + c4) * 4,
                     Bg + (size_t)(k0 + kk) * N + c4);
            }
            CP_COMMIT();
            CP_WAIT(1);
        } else {
            CP_WAIT(0);
        }
        __syncthreads();

        const uint32_t* as = &As[cur][0];
        const uint32_t* bs = &Bs[cur][0];
#pragma unroll
        for (int kh = 0; kh < 2; kh++) {
            const int kk = kh * 8;
            uint32_t af[2][4];
#pragma unroll
            for (int mt = 0; mt < 2; mt++) {
                const int r = wm + mt * 16 + gid;
                af[mt][0] = as[r * GASTR + kk + tig];
                af[mt][1] = as[(r + 8) * GASTR + kk + tig];
                af[mt][2] = as[r * GASTR + kk + tig + 4];
                af[mt][3] = as[(r + 8) * GASTR + kk + tig + 4];
            }
#pragma unroll
            for (int nt = 0; nt < 8; nt++) {
                const int n = wn + nt * 8 + gid;
                const uint32_t b0 = bs[(kk + tig) * GBSTR + n];
                const uint32_t b1 = bs[(kk + tig + 4) * GBSTR + n];
#pragma unroll
                for (int mt = 0; mt < 2; mt++)
                    mma_tf32(acc[mt][nt], af[mt][0], af[mt][1], af[mt][2], af[mt][3], b0, b1);
            }
        }
        __syncthreads();
    }

    if (doRound) {
#pragma unroll
        for (int mt = 0; mt < 2; mt++)
#pragma unroll
            for (int nt = 0; nt < 8; nt++)
#pragma unroll
                for (int i = 0; i < 4; i++)
                    acc[mt][nt][i] = __uint_as_float(f2tf32(acc[mt][nt][i]));
    }

#pragma unroll
    for (int mt = 0; mt < 2; mt++) {
#pragma unroll
        for (int nt = 0; nt < 8; nt++) {
            const int r0 = rowBase + wm + mt * 16 + gid;
            const int c0 = colBase + wn + nt * 8 + 2 * tig;
            *(float2*)(C + (size_t)r0 * N + c0)       = make_float2(acc[mt][nt][0], acc[mt][nt][1]);
            *(float2*)(C + (size_t)(r0 + 8) * N + c0) = make_float2(acc[mt][nt][2], acc[mt][nt][3]);
        }
    }
}

// ---------------------------------------------------------------------------
// RMSNorm + RoPE + fold sqrt(1/128); writes tf32-rounded bits.
// ---------------------------------------------------------------------------
__global__ __launch_bounds__(256) void normrope(float* __restrict__ q,
                                                float* __restrict__ k) {
    int gwarp = (blockIdx.x * blockDim.x + threadIdx.x) >> 5;
    int lane  = threadIdx.x & 31;
    const int nrows = BT * Hh;
    float* base = (gwarp < nrows) ? q : k;
    int row = (gwarp < nrows) ? gwarp : gwarp - nrows;
    int t = (row / Hh) % Tt;

    float* p = base + (size_t)row * Dd;
    float e0 = p[lane], e1 = p[lane + 32];
    float o0 = p[lane + 64], o1 = p[lane + 96];

    float ss = e0 * e0 + e1 * e1 + o0 * o0 + o1 * o1;
#pragma unroll
    for (int off = 16; off; off >>= 1) ss += __shfl_xor_sync(0xffffffffu, ss, off);

    float scale = rsqrtf(ss * (1.0f / 128.0f) + 1e-6f) * 0.08838834764831845f;
    e0 *= scale; e1 *= scale; o0 *= scale; o1 *= scale;

    float f0 = powf(10000.0f, -((float)lane) * (1.0f / 64.0f));
    float f1 = powf(10000.0f, -((float)(lane + 32)) * (1.0f / 64.0f));
    float r0 = (float)t * f0, r1 = (float)t * f1;
    float s0, c0, s1, c1;
    sincosf(r0, &s0, &c0);
    sincosf(r1, &s1, &c1);

    p[lane]      = __uint_as_float(f2tf32(e0 * c0 - o0 * s0));
    p[lane + 32] = __uint_as_float(f2tf32(e1 * c1 - o1 * s1));
    p[lane + 64] = __uint_as_float(f2tf32(e0 * s0 + o0 * c0));
    p[lane + 96] = __uint_as_float(f2tf32(e1 * s1 + o1 * c1));
}

// ---------------------------------------------------------------------------
// TF32 flash attention v4 (causal): BR=64 (4 warps, 128 thr), BC=32.
// cp.async double-buffered K/V; Q fragments in registers; P aliases Q pane.
// smem = 25600 words = 102.4 KB -> 2 CTAs/SM. Heavy q-blocks launch first.
// ---------------------------------------------------------------------------
#define BRt 64
#define BCt 32
#define QSTR 132
#define KSTR 132
#define VSTR 136
#define PSTR 36
#define AOFF_Q  0                      // 64*132 = 8448 (Ps aliases this)
#define AOFF_K0 8448                   // 32*132 = 4224
#define AOFF_K1 (AOFF_K0 + 32*KSTR)
#define AOFF_V0 (AOFF_K1 + 32*KSTR)    // 32*136 = 4352
#define AOFF_V1 (AOFF_V0 + 32*VSTR)
#define ASM_WORDS (AOFF_V1 + 32*VSTR)  // 25600

__global__ __launch_bounds__(128) void attn_tc(const float* __restrict__ q,
                                               const float* __restrict__ k,
                                               const float* __restrict__ v,
                                               float* __restrict__ o) {
    extern __shared__ uint32_t smu[];
    uint32_t* Ps = smu + AOFF_Q;

    const int tid  = threadIdx.x;
    const int lane = tid & 31;
    const int warp = tid >> 5;
    const int gid  = lane >> 2;
    const int tig  = lane & 3;
    const int qb = (gridDim.x - 1) - blockIdx.x;
    const int h = blockIdx.y, b = blockIdx.z;
    const int t0 = qb * BRt;
    const int wrow = warp * 16;

    const size_t headOff = ((size_t)b * Tt * Hh + h) * Dd;
    const float* qbase = q + headOff;
    const float* kbase = k + headOff;
    const float* vbase = v + headOff;
    const uint32_t smemBase = (uint32_t)__cvta_generic_to_shared(smu);

    // ---- issue kb=0 K/V loads (K0/V0 disjoint from Q region) ----
    {
#pragma unroll
        for (int i = 0; i < 8; i++) {
            const int s = tid + i * 128;            // 0..1023
            const int r = s >> 5, c4 = (s & 31) << 2;
            cp16(smemBase + (AOFF_K0 + r * KSTR + c4) * 4, kbase + (size_t)r * HD + c4);
            cp16(smemBase + (AOFF_V0 + r * VSTR + c4) * 4, vbase + (size_t)r * HD + c4);
        }
        CP_COMMIT();
    }

    // ---- stage Q (pre-rounded bits), lift fragments to registers ----
    uint32_t* Qs = smu + AOFF_Q;
    for (int s = tid; s < BRt * 32; s += 128) {
        int r = s >> 5, c4 = (s & 31) << 2;
        float4 qv = *(const float4*)(qbase + (size_t)(t0 + r) * HD + c4);
        uint32_t* p = &Qs[r * QSTR + c4];
        p[0] = __float_as_uint(qv.x); p[1] = __float_as_uint(qv.y);
        p[2] = __float_as_uint(qv.z); p[3] = __float_as_uint(qv.w);
    }
    __syncthreads();

    uint32_t qf[16][4];
#pragma unroll
    for (int ks = 0; ks < 16; ks++) {
        const int k0 = ks * 8;
        qf[ks][0] = Qs[(wrow + gid) * QSTR + k0 + tig];
        qf[ks][1] = Qs[(wrow + gid + 8) * QSTR + k0 + tig];
        qf[ks][2] = Qs[(wrow + gid) * QSTR + k0 + tig + 4];
        qf[ks][3] = Qs[(wrow + gid + 8) * QSTR + k0 + tig + 4];
    }

    float m0 = -1e30f, m1 = -1e30f, l0 = 0.f, l1 = 0.f;
    float oacc[16][4];
#pragma unroll
    for (int nt = 0; nt < 16; nt++)
#pragma unroll
        for (int i = 0; i < 4; i++) oacc[nt][i] = 0.f;

    const int kbmax = 2 * qb + 1;
    for (int kb = 0; kb <= kbmax; kb++) {
        if (kb + 1 <= kbmax) {
            const int tk0 = (kb + 1) * BCt;
            const int offK = ((kb + 1) & 1) ? AOFF_K1 : AOFF_K0;
            const int offV = ((kb + 1) & 1) ? AOFF_V1 : AOFF_V0;
#pragma unroll
            for (int i = 0; i < 8; i++) {
                const int s = tid + i * 128;
                const int r = s >> 5, c4 = (s & 31) << 2;
                cp16(smemBase + (offK + r * KSTR + c4) * 4,
                     kbase + (size_t)(tk0 + r) * HD + c4);
                cp16(smemBase + (offV + r * VSTR + c4) * 4,
                     vbase + (size_t)(tk0 + r) * HD + c4);
            }
            CP_COMMIT();
            CP_WAIT(1);
        } else {
            CP_WAIT(0);
        }
        __syncthreads();

        const uint32_t* Ks = smu + ((kb & 1) ? AOFF_K1 : AOFF_K0);
        const uint32_t* Vs = smu + ((kb & 1) ? AOFF_V1 : AOFF_V0);
        const int tk0 = kb * BCt;

        // S = Q K^T : warp tile 16x32
        float sacc[4][4];
#pragma unroll
        for (int nt = 0; nt < 4; nt++)
#pragma unroll
            for (int i = 0; i < 4; i++) sacc[nt][i] = 0.f;

#pragma unroll
        for (int ks = 0; ks < 16; ks++) {
            const int k0 = ks * 8;
#pragma unroll
            for (int nt = 0; nt < 4; nt++) {
                const uint32_t b0 = Ks[(nt * 8 + gid) * KSTR + k0 + tig];
                const uint32_t b1 = Ks[(nt * 8 + gid) * KSTR + k0 + tig + 4];
                mma_tf32(sacc[nt], qf[ks][0], qf[ks][1], qf[ks][2], qf[ks][3], b0, b1);
            }
        }

        if (kb >= 2 * qb) {   // diagonal-overlap blocks: causal mask
            const int rg0 = t0 + wrow + gid;
            const int rg1 = rg0 + 8;
#pragma unroll
            for (int nt = 0; nt < 4; nt++) {
                const int cg = tk0 + nt * 8 + 2 * tig;
                if (rg0 < cg)     sacc[nt][0] = -1e30f;
                if (rg0 < cg + 1) sacc[nt][1] = -1e30f;
                if (rg1 < cg)     sacc[nt][2] = -1e30f;
                if (rg1 < cg + 1) sacc[nt][3] = -1e30f;
            }
        }

        // Online softmax in registers
        float rm0 = -1e30f, rm1 = -1e30f;
#pragma unroll
        for (int nt = 0; nt < 4; nt++) {
            rm0 = fmaxf(rm0, fmaxf(sacc[nt][0], sacc[nt][1]));
            rm1 = fmaxf(rm1, fmaxf(sacc[nt][2], sacc[nt][3]));
        }
        rm0 = fmaxf(rm0, __shfl_xor_sync(0xffffffffu, rm0, 1));
        rm0 = fmaxf(rm0, __shfl_xor_sync(0xffffffffu, rm0, 2));
        rm1 = fmaxf(rm1, __shfl_xor_sync(0xffffffffu, rm1, 1));
        rm1 = fmaxf(rm1, __shfl_xor_sync(0xffffffffu, rm1, 2));

        const float nm0 = fmaxf(m0, rm0);
        const float nm1 = fmaxf(m1, rm1);
        float sum0 = 0.f, sum1 = 0.f;
#pragma unroll
        for (int nt = 0; nt < 4; nt++) {
            float e00 = __expf(sacc[nt][0] - nm0);
            float e01 = __expf(sacc[nt][1] - nm0);
            float e10 = __expf(sacc[nt][2] - nm1);
            float e11 = __expf(sacc[nt][3] - nm1);
            sum0 += e00 + e01;
            sum1 += e10 + e11;
            *(uint2*)&Ps[(wrow + gid) * PSTR + nt * 8 + 2 * tig] =
                make_uint2(f2tf32(e00), f2tf32(e01));
            *(uint2*)&Ps[(wrow + gid + 8) * PSTR + nt * 8 + 2 * tig] =
                make_uint2(f2tf32(e10), f2tf32(e11));
        }
        sum0 += __shfl_xor_sync(0xffffffffu, sum0, 1);
        sum0 += __shfl_xor_sync(0xffffffffu, sum0, 2);
        sum1 += __shfl_xor_sync(0xffffffffu, sum1, 1);
        sum1 += __shfl_xor_sync(0xffffffffu, sum1, 2);

        const float c0 = __expf(m0 - nm0);
        const float c1 = __expf(m1 - nm1);
        l0 = l0 * c0 + sum0; m0 = nm0;
        l1 = l1 * c1 + sum1; m1 = nm1;
#pragma unroll
        for (int nt = 0; nt < 16; nt++) {
            oacc[nt][0] *= c0; oacc[nt][1] *= c0;
            oacc[nt][2] *= c1; oacc[nt][3] *= c1;
        }
        __syncwarp();

        // O += P V : warp tile 16x128
#pragma unroll
        for (int ks = 0; ks < 4; ks++) {
            const int k0 = ks * 8;
            const uint32_t a0 = Ps[(wrow + gid) * PSTR + k0 + tig];
            const uint32_t a1 = Ps[(wrow + gid + 8) * PSTR + k0 + tig];
            const uint32_t a2 = Ps[(wrow + gid) * PSTR + k0 + tig + 4];
            const uint32_t a3 = Ps[(wrow + gid + 8) * PSTR + k0 + tig + 4];
#pragma unroll
            for (int nt = 0; nt < 16; nt++) {
                const uint32_t b0 = Vs[(k0 + tig) * VSTR + nt * 8 + gid];
                const uint32_t b1 = Vs[(k0 + tig + 4) * VSTR + nt * 8 + gid];
                mma_tf32(oacc[nt], a0, a1, a2, a3, b0, b1);
            }
        }
        __syncthreads();
    }

    // Epilogue: O / l, rounded to tf32 (out-proj loads raw via cp.async)
    const float i0 = 1.0f / l0;
    const float i1 = 1.0f / l1;
    float* obase = o + headOff;
    const int rg0 = t0 + wrow + gid;
#pragma unroll
    for (int nt = 0; nt < 16; nt++) {
        const int col = nt * 8 + 2 * tig;
        *(float2*)(obase + (size_t)rg0 * HD + col) = make_float2(
            __uint_as_float(f2tf32(oacc[nt][0] * i0)),
            __uint_as_float(f2tf32(oacc[nt][1] * i0)));
        *(float2*)(obase + (size_t)(rg0 + 8) * HD + col) = make_float2(
            __uint_as_float(f2tf32(oacc[nt][2] * i1)),
            __uint_as_float(f2tf32(oacc[nt][3] * i1)));
    }
}

// ---------------------------------------------------------------------------
extern "C" void kernel_launch(void* const* d_in, const int* in_sizes, int n_in,
                              void* d_out, int out_size) {
    const float* x  = (const float*)d_in[0];
    const float* wq = (const float*)d_in[1];
    const float* wk = (const float*)d_in[2];
    const float* wv = (const float*)d_in[3];
    const float* wo = (const float*)d_in[4];
    float* out = (float*)d_out;

    float *qp, *kp, *vp, *op, *xr, *wqr, *wkr, *wvr, *wor;
    cudaGetSymbolAddress((void**)&qp, g_q);
    cudaGetSymbolAddress((void**)&kp, g_k);
    cudaGetSymbolAddress((void**)&vp, g_v);
    cudaGetSymbolAddress((void**)&op, g_o);
    cudaGetSymbolAddress((void**)&xr, g_xr);
    cudaGetSymbolAddress((void**)&wqr, g_wqr);
    cudaGetSymbolAddress((void**)&wkr, g_wkr);
    cudaGetSymbolAddress((void**)&wvr, g_wvr);
    cudaGetSymbolAddress((void**)&wor, g_wor);

    // Pre-round inputs to tf32 bits
    pre_round<<<(BT*Mm/4 + 255)/256, 256>>>(x, xr, BT*Mm/4);
    pre_round<<<(Mm*HD/4 + 255)/256, 256>>>(wq, wqr, Mm*HD/4);
    pre_round<<<(Mm*HD/4 + 255)/256, 256>>>(wk, wkr, Mm*HD/4);
    pre_round<<<(Mm*HD/4 + 255)/256, 256>>>(wv, wvr, Mm*HD/4);
    pre_round<<<(HD*Mm/4 + 255)/256, 256>>>(wo, wor, HD*Mm/4);

    // Fused QKV projections (round v only; q,k re-rounded by normrope)
    dim3 gp(HD / 128, BT / 128, 3);
    gemm_tf32<<<gp, 256>>>(xr, wqr, wkr, wvr, qp, kp, vp, BT, HD, Mm, 4u);

    // RMSNorm + RoPE + mult fold (writes tf32-rounded)
    int totalWarps = 2 * BT * Hh;
    normrope<<<totalWarps / 8, 256>>>(qp, kp);

    // TF32 flash attention v4
    size_t smem = (size_t)ASM_WORDS * 4;   // 102400 B -> 2 CTAs/SM
    cudaFuncSetAttribute(attn_tc, cudaFuncAttributeMaxDynamicSharedMemorySize, (int)smem);
    dim3 ga(Tt / BRt, Hh, Bq);
    attn_tc<<<ga, 128, smem>>>(qp, kp, vp, op);

    // Output projection
    dim3 go(Mm / 128, BT / 128, 1);
    gemm_tf32<<<go, 256>>>(op, wor, wor, wor, out, out, out, BT, Mm, HD, 0u);
}

// round 7
// speedup vs baseline: 7.5877x; 1.2492x over previous
#include <cuda_runtime.h>
#include <cuda_fp16.h>
#include <math.h>
#include <stdint.h>

// Problem dims (fixed)
#define Bq 2
#define Tt 2048
#define Mm 1024
#define Hh 8
#define Dd 128
#define BT (Bq*Tt)      // 4096
#define HD (Hh*Dd)      // 1024

// Scratch — no cudaMalloc allowed
__device__ float  g_q[BT*HD];          // fp32 q from gemm [b,t,h,d]
__device__ float  g_k[BT*HD];
__device__ float  g_v[BT*HD];
__device__ float  g_o[BT*HD];          // attention out [b,t,h,d] (tf32-rounded)
__device__ float  g_xr[BT*Mm];         // tf32-rounded x
__device__ float  g_wqr[Mm*HD];
__device__ float  g_wkr[Mm*HD];
__device__ float  g_wvr[Mm*HD];
__device__ float  g_wor[HD*Mm];
__device__ __half g_qh[BT*HD];         // fp16 q [b,h,t,d]
__device__ __half g_kh[BT*HD];         // fp16 k [b,h,t,d]
__device__ __half g_vt[BT*HD];         // fp16 v transposed [b,h,d,t]

__device__ __forceinline__ uint32_t f2tf32(float f) {
    uint32_t u;
    asm("cvt.rna.tf32.f32 %0, %1;" : "=r"(u) : "f"(f));
    return u;
}

__device__ __forceinline__ void mma_tf32(float c[4], uint32_t a0, uint32_t a1,
                                         uint32_t a2, uint32_t a3,
                                         uint32_t b0, uint32_t b1) {
    asm volatile(
        "mma.sync.aligned.m16n8k8.row.col.f32.tf32.tf32.f32 "
        "{%0,%1,%2,%3}, {%4,%5,%6,%7}, {%8,%9}, {%0,%1,%2,%3};\n"
        : "+f"(c[0]), "+f"(c[1]), "+f"(c[2]), "+f"(c[3])
        : "r"(a0), "r"(a1), "r"(a2), "r"(a3), "r"(b0), "r"(b1));
}

__device__ __forceinline__ void mma_f16(float c[4], uint32_t a0, uint32_t a1,
                                        uint32_t a2, uint32_t a3,
                                        uint32_t b0, uint32_t b1) {
    asm volatile(
        "mma.sync.aligned.m16n8k16.row.col.f32.f16.f16.f32 "
        "{%0,%1,%2,%3}, {%4,%5,%6,%7}, {%8,%9}, {%0,%1,%2,%3};\n"
        : "+f"(c[0]), "+f"(c[1]), "+f"(c[2]), "+f"(c[3])
        : "r"(a0), "r"(a1), "r"(a2), "r"(a3), "r"(b0), "r"(b1));
}

__device__ __forceinline__ uint32_t packh2(float lo, float hi) {
    __half2 h = __floats2half2_rn(lo, hi);
    return *(uint32_t*)&h;
}

__device__ __forceinline__ void cp16(uint32_t dst, const void* src) {
    asm volatile("cp.async.ca.shared.global [%0], [%1], 16;\n" :: "r"(dst), "l"(src));
}
#define CP_COMMIT() asm volatile("cp.async.commit_group;\n" ::: "memory")
#define CP_WAIT(n)  asm volatile("cp.async.wait_group %0;\n" :: "n"(n) : "memory")

// ---------------------------------------------------------------------------
__global__ __launch_bounds__(256) void pre_round(const float* __restrict__ src,
                                                 float* __restrict__ dst, int n4) {
    int i = blockIdx.x * blockDim.x + threadIdx.x;
    if (i < n4) {
        float4 v = ((const float4*)src)[i];
        v.x = __uint_as_float(f2tf32(v.x));
        v.y = __uint_as_float(f2tf32(v.y));
        v.z = __uint_as_float(f2tf32(v.z));
        v.w = __uint_as_float(f2tf32(v.w));
        ((float4*)dst)[i] = v;
    }
}

// ---------------------------------------------------------------------------
// TF32 GEMM (unchanged v2): 128x128 CTA tile, BK=16, 256 threads.
// ---------------------------------------------------------------------------
#define GASTR 20
#define GBSTR 136

__global__ __launch_bounds__(256) void gemm_tf32(const float* __restrict__ A,
                                                 const float* __restrict__ B0,
                                                 const float* __restrict__ B1,
                                                 const float* __restrict__ B2,
                                                 float* __restrict__ C0,
                                                 float* __restrict__ C1,
                                                 float* __restrict__ C2,
                                                 int M, int N, int K,
                                                 unsigned roundMask) {
    const float* Bm = (blockIdx.z == 0) ? B0 : (blockIdx.z == 1) ? B1 : B2;
    float* C = (blockIdx.z == 0) ? C0 : (blockIdx.z == 1) ? C1 : C2;
    const bool doRound = (roundMask >> blockIdx.z) & 1u;

    __shared__ uint32_t As[2][128 * GASTR];
    __shared__ uint32_t Bs[2][16 * GBSTR];

    const int tid  = threadIdx.x;
    const int lane = tid & 31;
    const int warp = tid >> 5;
    const int gid  = lane >> 2;
    const int tig  = lane & 3;
    const int wm   = (warp >> 1) * 32;
    const int wn   = (warp & 1) * 64;
    const int rowBase = blockIdx.y * 128;
    const int colBase = blockIdx.x * 128;

    const float* Ag = A + (size_t)rowBase * K;
    const float* Bg = Bm + colBase;
    const uint32_t sA = (uint32_t)__cvta_generic_to_shared(&As[0][0]);
    const uint32_t sB = (uint32_t)__cvta_generic_to_shared(&Bs[0][0]);

    float acc[2][8][4];
#pragma unroll
    for (int mt = 0; mt < 2; mt++)
#pragma unroll
        for (int nt = 0; nt < 8; nt++)
#pragma unroll
            for (int i = 0; i < 4; i++) acc[mt][nt][i] = 0.f;

    {
#pragma unroll
        for (int i = 0; i < 2; i++) {
            const int s = tid + i * 256;
            const int r = s >> 2, c4 = (s & 3) << 2;
            cp16(sA + (r * GASTR + c4) * 4, Ag + (size_t)r * K + c4);
        }
#pragma unroll
        for (int i = 0; i < 2; i++) {
            const int s = tid + i * 256;
            const int kk = s >> 5, c4 = (s & 31) << 2;
            cp16(sB + (kk * GBSTR + c4) * 4, Bg + (size_t)kk * N + c4);
        }
        CP_COMMIT();
    }

    const int niter = K >> 4;
    for (int it = 0; it < niter; it++) {
        const int cur = it & 1;
        if (it + 1 < niter) {
            const int k0 = (it + 1) << 4;
            const int nxt = (it + 1) & 1;
#pragma unroll
            for (int i = 0; i < 2; i++) {
                const int s = tid + i * 256;
                const int r = s >> 2, c4 = (s & 3) << 2;
                cp16(sA + (nxt * 128 * GASTR + r * GASTR + c4) * 4,
                     Ag + (size_t)r * K + k0 + c4);
            }
#pragma unroll
            for (int i = 0; i < 2; i++) {
                const int s = tid + i * 256;
                const int kk = s >> 5, c4 = (s & 31) << 2;
                cp16(sB + (nxt * 16 * GBSTR + kk * GBSTR + c4) * 4,
                     Bg + (size_t)(k0 + kk) * N + c4);
            }
            CP_COMMIT();
            CP_WAIT(1);
        } else {
            CP_WAIT(0);
        }
        __syncthreads();

        const uint32_t* as = &As[cur][0];
        const uint32_t* bs = &Bs[cur][0];
#pragma unroll
        for (int kh = 0; kh < 2; kh++) {
            const int kk = kh * 8;
            uint32_t af[2][4];
#pragma unroll
            for (int mt = 0; mt < 2; mt++) {
                const int r = wm + mt * 16 + gid;
                af[mt][0] = as[r * GASTR + kk + tig];
                af[mt][1] = as[(r + 8) * GASTR + kk + tig];
                af[mt][2] = as[r * GASTR + kk + tig + 4];
                af[mt][3] = as[(r + 8) * GASTR + kk + tig + 4];
            }
#pragma unroll
            for (int nt = 0; nt < 8; nt++) {
                const int n = wn + nt * 8 + gid;
                const uint32_t b0 = bs[(kk + tig) * GBSTR + n];
                const uint32_t b1 = bs[(kk + tig + 4) * GBSTR + n];
#pragma unroll
                for (int mt = 0; mt < 2; mt++)
                    mma_tf32(acc[mt][nt], af[mt][0], af[mt][1], af[mt][2], af[mt][3], b0, b1);
            }
        }
        __syncthreads();
    }

    if (doRound) {
#pragma unroll
        for (int mt = 0; mt < 2; mt++)
#pragma unroll
            for (int nt = 0; nt < 8; nt++)
#pragma unroll
                for (int i = 0; i < 4; i++)
                    acc[mt][nt][i] = __uint_as_float(f2tf32(acc[mt][nt][i]));
    }

#pragma unroll
    for (int mt = 0; mt < 2; mt++) {
#pragma unroll
        for (int nt = 0; nt < 8; nt++) {
            const int r0 = rowBase + wm + mt * 16 + gid;
            const int c0 = colBase + wn + nt * 8 + 2 * tig;
            *(float2*)(C + (size_t)r0 * N + c0)       = make_float2(acc[mt][nt][0], acc[mt][nt][1]);
            *(float2*)(C + (size_t)(r0 + 8) * N + c0) = make_float2(acc[mt][nt][2], acc[mt][nt][3]);
        }
    }
}

// ---------------------------------------------------------------------------
// RMSNorm + RoPE + fold sqrt(1/128); fp32 [b,t,h,d] in -> fp16 [b,h,t,d] out.
// One warp per (b,t,h) row.
// ---------------------------------------------------------------------------
__global__ __launch_bounds__(256) void normrope_h(const float* __restrict__ q,
                                                  const float* __restrict__ k,
                                                  __half* __restrict__ qh,
                                                  __half* __restrict__ kh) {
    int gwarp = (blockIdx.x * blockDim.x + threadIdx.x) >> 5;
    int lane  = threadIdx.x & 31;
    const int nrows = BT * Hh;
    const float* src = (gwarp < nrows) ? q : k;
    __half* dst = (gwarp < nrows) ? qh : kh;
    int row = (gwarp < nrows) ? gwarp : gwarp - nrows;
    int bt = row >> 3;           // row = bt*H + h
    int h  = row & 7;
    int t  = bt & (Tt - 1);
    int b  = bt >> 11;           // bt / T

    const float* p = src + (size_t)bt * HD + h * Dd;
    float e0 = p[lane], e1 = p[lane + 32];
    float o0 = p[lane + 64], o1 = p[lane + 96];

    float ss = e0 * e0 + e1 * e1 + o0 * o0 + o1 * o1;
#pragma unroll
    for (int off = 16; off; off >>= 1) ss += __shfl_xor_sync(0xffffffffu, ss, off);

    float scale = rsqrtf(ss * (1.0f / 128.0f) + 1e-6f) * 0.08838834764831845f;
    e0 *= scale; e1 *= scale; o0 *= scale; o1 *= scale;

    float f0 = powf(10000.0f, -((float)lane) * (1.0f / 64.0f));
    float f1 = powf(10000.0f, -((float)(lane + 32)) * (1.0f / 64.0f));
    float r0 = (float)t * f0, r1 = (float)t * f1;
    float s0, c0, s1, c1;
    sincosf(r0, &s0, &c0);
    sincosf(r1, &s1, &c1);

    __half* op = dst + (((size_t)(b * Hh + h)) * Tt + t) * Dd;
    op[lane]      = __float2half_rn(e0 * c0 - o0 * s0);
    op[lane + 32] = __float2half_rn(e1 * c1 - o1 * s1);
    op[lane + 64] = __float2half_rn(e0 * s0 + o0 * c0);
    op[lane + 96] = __float2half_rn(e1 * s1 + o1 * c1);
}

// ---------------------------------------------------------------------------
// V transpose + fp16: g_v [b,t,h,d] fp32 -> g_vt [b,h,d,t] fp16.
// Grid (T/32, D/32, B*H), block (32, 8). smem tile 32x33 half.
// ---------------------------------------------------------------------------
__global__ __launch_bounds__(256) void vtrans(const float* __restrict__ v,
                                              __half* __restrict__ vt) {
    __shared__ __half tile[32][33];
    const int tx = threadIdx.x, ty = threadIdx.y;
    const int t0 = blockIdx.x * 32;
    const int d0 = blockIdx.y * 32;
    const int bh = blockIdx.z;
    const int b = bh >> 3, h = bh & 7;

    const float* in = v + ((size_t)b * Tt) * HD + h * Dd;
#pragma unroll
    for (int i = 0; i < 4; i++) {
        int t = t0 + ty + i * 8;
        tile[ty + i * 8][tx] = __float2half_rn(in[(size_t)t * HD + d0 + tx]);
    }
    __syncthreads();

    __half* out = vt + ((size_t)bh * Dd) * Tt;
#pragma unroll
    for (int i = 0; i < 4; i++) {
        int d = d0 + ty + i * 8;
        out[(size_t)d * Tt + t0 + tx] = tile[tx][ty + i * 8];
    }
}

// ---------------------------------------------------------------------------
// FP16 flash attention v5 (causal): BR=64 (4 warps), BC=64.
// Q frags + P entirely in registers (P A-frags == S C-frags layout).
// K smem [key][d] fp16 (stride 68 u32); V smem [d][key] fp16 (stride 36 u32).
// Double-buffered cp.async. 71.7 KB smem -> 2 CTAs/SM.
// ---------------------------------------------------------------------------
#define BRt 64
#define BCt 64
#define HKSTR 68
#define HVSTR 36
#define HOFF_K0 0
#define HOFF_V0 (HOFF_K0 + 64*HKSTR)    // 4352
#define HOFF_K1 (HOFF_V0 + 128*HVSTR)   // 8960
#define HOFF_V1 (HOFF_K1 + 64*HKSTR)    // 13312
#define HSM_WORDS (HOFF_V1 + 128*HVSTR) // 17920 words = 71680 B

__global__ __launch_bounds__(128) void attn_h(const __half* __restrict__ qh,
                                              const __half* __restrict__ kh,
                                              const __half* __restrict__ vt,
                                              float* __restrict__ o) {
    extern __shared__ uint32_t smu[];

    const int tid  = threadIdx.x;
    const int lane = tid & 31;
    const int warp = tid >> 5;
    const int gid  = lane >> 2;
    const int tig  = lane & 3;
    const int qb = (gridDim.x - 1) - blockIdx.x;   // heavy blocks first
    const int h = blockIdx.y, b = blockIdx.z;
    const int t0 = qb * BRt;
    const int wrow = warp * 16;

    const size_t bhOff = (size_t)(b * Hh + h) * Tt * Dd;
    const __half* qbase = qh + bhOff + (size_t)t0 * Dd;
    const __half* kbase = kh + bhOff;
    const __half* vbase = vt + bhOff;              // [d][t]
    const uint32_t smemBase = (uint32_t)__cvta_generic_to_shared(smu);

    // ---- issue kb=0 K/V into buf0 ----
    {
#pragma unroll
        for (int i = 0; i < 8; i++) {               // K: 64 rows x 16 chunks
            const int s = tid + i * 128;
            const int r = s >> 4, c = s & 15;
            cp16(smemBase + (HOFF_K0 + r * HKSTR + c * 4) * 4,
                 kbase + (size_t)r * Dd + c * 8);
        }
#pragma unroll
        for (int i = 0; i < 8; i++) {               // V: 128 rows x 8 chunks
            const int s = tid + i * 128;
            const int r = s >> 3, c = s & 7;
            cp16(smemBase + (HOFF_V0 + r * HVSTR + c * 4) * 4,
                 vbase + (size_t)r * Tt + c * 8);
        }
        CP_COMMIT();
    }
    // ---- stage Q into buf1 K-region ----
    {
#pragma unroll
        for (int i = 0; i < 8; i++) {
            const int s = tid + i * 128;
            const int r = s >> 4, c = s & 15;
            cp16(smemBase + (HOFF_K1 + r * HKSTR + c * 4) * 4,
                 qbase + (size_t)r * Dd + c * 8);
        }
        CP_COMMIT();
        CP_WAIT(0);
    }
    __syncthreads();

    // Lift Q fragments (8 k16-steps x 4 regs)
    uint32_t qf[8][4];
    {
        const uint32_t* Qs = smu + HOFF_K1;
#pragma unroll
        for (int ks = 0; ks < 8; ks++) {
            qf[ks][0] = Qs[(wrow + gid) * HKSTR + 8 * ks + tig];
            qf[ks][1] = Qs[(wrow + gid + 8) * HKSTR + 8 * ks + tig];
            qf[ks][2] = Qs[(wrow + gid) * HKSTR + 8 * ks + tig + 4];
            qf[ks][3] = Qs[(wrow + gid + 8) * HKSTR + 8 * ks + tig + 4];
        }
    }
    __syncthreads();   // buf1 free for reuse

    float m0 = -1e30f, m1 = -1e30f, l0 = 0.f, l1 = 0.f;
    float oacc[16][4];
#pragma unroll
    for (int nt = 0; nt < 16; nt++)
#pragma unroll
        for (int i = 0; i < 4; i++) oacc[nt][i] = 0.f;

    for (int kb = 0; kb <= qb; kb++) {
        if (kb + 1 <= qb) {
            const int tk0 = (kb + 1) * BCt;
            const int offK = ((kb + 1) & 1) ? HOFF_K1 : HOFF_K0;
            const int offV = ((kb + 1) & 1) ? HOFF_V1 : HOFF_V0;
#pragma unroll
            for (int i = 0; i < 8; i++) {
                const int s = tid + i * 128;
                const int r = s >> 4, c = s & 15;
                cp16(smemBase + (offK + r * HKSTR + c * 4) * 4,
                     kbase + (size_t)(tk0 + r) * Dd + c * 8);
            }
#pragma unroll
            for (int i = 0; i < 8; i++) {
                const int s = tid + i * 128;
                const int r = s >> 3, c = s & 7;
                cp16(smemBase + (offV + r * HVSTR + c * 4) * 4,
                     vbase + (size_t)r * Tt + tk0 + c * 8);
            }
            CP_COMMIT();
            CP_WAIT(1);
        } else {
            CP_WAIT(0);
        }
        __syncthreads();

        const uint32_t* Ks = smu + ((kb & 1) ? HOFF_K1 : HOFF_K0);
        const uint32_t* Vs = smu + ((kb & 1) ? HOFF_V1 : HOFF_V0);
        const int tk0 = kb * BCt;

        // S = Q K^T : warp tile 16x64, fp16 k16 (8 ks x 8 nt)
        float sacc[8][4];
#pragma unroll
        for (int nt = 0; nt < 8; nt++)
#pragma unroll
            for (int i = 0; i < 4; i++) sacc[nt][i] = 0.f;

#pragma unroll
        for (int ks = 0; ks < 8; ks++) {
#pragma unroll
            for (int nt = 0; nt < 8; nt++) {
                const uint32_t b0 = Ks[(nt * 8 + gid) * HKSTR + 8 * ks + tig];
                const uint32_t b1 = Ks[(nt * 8 + gid) * HKSTR + 8 * ks + tig + 4];
                mma_f16(sacc[nt], qf[ks][0], qf[ks][1], qf[ks][2], qf[ks][3], b0, b1);
            }
        }

        if (kb == qb) {   // diagonal block: causal mask
            const int rg0 = t0 + wrow + gid;
            const int rg1 = rg0 + 8;
#pragma unroll
            for (int nt = 0; nt < 8; nt++) {
                const int cg = tk0 + nt * 8 + 2 * tig;
                if (rg0 < cg)     sacc[nt][0] = -1e30f;
                if (rg0 < cg + 1) sacc[nt][1] = -1e30f;
                if (rg1 < cg)     sacc[nt][2] = -1e30f;
                if (rg1 < cg + 1) sacc[nt][3] = -1e30f;
            }
        }

        // Online softmax in registers; pack P directly into fp16 A-frags
        float rm0 = -1e30f, rm1 = -1e30f;
#pragma unroll
        for (int nt = 0; nt < 8; nt++) {
            rm0 = fmaxf(rm0, fmaxf(sacc[nt][0], sacc[nt][1]));
            rm1 = fmaxf(rm1, fmaxf(sacc[nt][2], sacc[nt][3]));
        }
        rm0 = fmaxf(rm0, __shfl_xor_sync(0xffffffffu, rm0, 1));
        rm0 = fmaxf(rm0, __shfl_xor_sync(0xffffffffu, rm0, 2));
        rm1 = fmaxf(rm1, __shfl_xor_sync(0xffffffffu, rm1, 1));
        rm1 = fmaxf(rm1, __shfl_xor_sync(0xffffffffu, rm1, 2));

        const float nm0 = fmaxf(m0, rm0);
        const float nm1 = fmaxf(m1, rm1);
        float sum0 = 0.f, sum1 = 0.f;
        uint32_t pe[8][2];   // pe[nt][0]=pack(c0,c1) row gid; [1]=pack(c2,c3) row gid+8
#pragma unroll
        for (int nt = 0; nt < 8; nt++) {
            float e00 = __expf(sacc[nt][0] - nm0);
            float e01 = __expf(sacc[nt][1] - nm0);
            float e10 = __expf(sacc[nt][2] - nm1);
            float e11 = __expf(sacc[nt][3] - nm1);
            sum0 += e00 + e01;
            sum1 += e10 + e11;
            pe[nt][0] = packh2(e00, e01);
            pe[nt][1] = packh2(e10, e11);
        }
        sum0 += __shfl_xor_sync(0xffffffffu, sum0, 1);
        sum0 += __shfl_xor_sync(0xffffffffu, sum0, 2);
        sum1 += __shfl_xor_sync(0xffffffffu, sum1, 1);
        sum1 += __shfl_xor_sync(0xffffffffu, sum1, 2);

        const float c0 = __expf(m0 - nm0);
        const float c1 = __expf(m1 - nm1);
        l0 = l0 * c0 + sum0; m0 = nm0;
        l1 = l1 * c1 + sum1; m1 = nm1;
#pragma unroll
        for (int nt = 0; nt < 16; nt++) {
            oacc[nt][0] *= c0; oacc[nt][1] *= c0;
            oacc[nt][2] *= c1; oacc[nt][3] *= c1;
        }

        // O += P V : 4 k16-steps over keys x 16 d-tiles; A = pe (registers)
#pragma unroll
        for (int ks = 0; ks < 4; ks++) {
            const uint32_t a0 = pe[2 * ks][0];
            const uint32_t a1 = pe[2 * ks][1];
            const uint32_t a2 = pe[2 * ks + 1][0];
            const uint32_t a3 = pe[2 * ks + 1][1];
#pragma unroll
            for (int nt = 0; nt < 16; nt++) {
                const uint32_t b0 = Vs[(nt * 8 + gid) * HVSTR + 8 * ks + tig];
                const uint32_t b1 = Vs[(nt * 8 + gid) * HVSTR + 8 * ks + tig + 4];
                mma_f16(oacc[nt], a0, a1, a2, a3, b0, b1);
            }
        }
        __syncthreads();   // buffer kb&1 free before re-issue
    }

    // Epilogue: O / l, tf32-rounded, to g_o [b,t,h,d]
    const float i0 = 1.0f / l0;
    const float i1 = 1.0f / l1;
    float* obase = o + ((size_t)b * Tt * Hh + h) * Dd;
    const int rg0 = t0 + wrow + gid;
#pragma unroll
    for (int nt = 0; nt < 16; nt++) {
        const int col = nt * 8 + 2 * tig;
        *(float2*)(obase + (size_t)rg0 * HD + col) = make_float2(
            __uint_as_float(f2tf32(oacc[nt][0] * i0)),
            __uint_as_float(f2tf32(oacc[nt][1] * i0)));
        *(float2*)(obase + (size_t)(rg0 + 8) * HD + col) = make_float2(
            __uint_as_float(f2tf32(oacc[nt][2] * i1)),
            __uint_as_float(f2tf32(oacc[nt][3] * i1)));
    }
}

// ---------------------------------------------------------------------------
extern "C" void kernel_launch(void* const* d_in, const int* in_sizes, int n_in,
                              void* d_out, int out_size) {
    const float* x  = (const float*)d_in[0];
    const float* wq = (const float*)d_in[1];
    const float* wk = (const float*)d_in[2];
    const float* wv = (const float*)d_in[3];
    const float* wo = (const float*)d_in[4];
    float* out = (float*)d_out;

    float *qp, *kp, *vp, *op, *xr, *wqr, *wkr, *wvr, *wor;
    __half *qhp, *khp, *vtp;
    cudaGetSymbolAddress((void**)&qp, g_q);
    cudaGetSymbolAddress((void**)&kp, g_k);
    cudaGetSymbolAddress((void**)&vp, g_v);
    cudaGetSymbolAddress((void**)&op, g_o);
    cudaGetSymbolAddress((void**)&xr, g_xr);
    cudaGetSymbolAddress((void**)&wqr, g_wqr);
    cudaGetSymbolAddress((void**)&wkr, g_wkr);
    cudaGetSymbolAddress((void**)&wvr, g_wvr);
    cudaGetSymbolAddress((void**)&wor, g_wor);
    cudaGetSymbolAddress((void**)&qhp, g_qh);
    cudaGetSymbolAddress((void**)&khp, g_kh);
    cudaGetSymbolAddress((void**)&vtp, g_vt);

    // Pre-round inputs to tf32 bits (for the tf32 projection GEMMs)
    pre_round<<<(BT*Mm/4 + 255)/256, 256>>>(x, xr, BT*Mm/4);
    pre_round<<<(Mm*HD/4 + 255)/256, 256>>>(wq, wqr, Mm*HD/4);
    pre_round<<<(Mm*HD/4 + 255)/256, 256>>>(wk, wkr, Mm*HD/4);
    pre_round<<<(Mm*HD/4 + 255)/256, 256>>>(wv, wvr, Mm*HD/4);
    pre_round<<<(HD*Mm/4 + 255)/256, 256>>>(wo, wor, HD*Mm/4);

    // Fused QKV projections (fp32 outputs; fp16 conversion happens downstream)
    dim3 gp(HD / 128, BT / 128, 3);
    gemm_tf32<<<gp, 256>>>(xr, wqr, wkr, wvr, qp, kp, vp, BT, HD, Mm, 0u);

    // RMSNorm + RoPE -> fp16 q,k in [b,h,t,d]
    int totalWarps = 2 * BT * Hh;
    normrope_h<<<totalWarps / 8, 256>>>(qp, kp, qhp, khp);

    // V -> fp16 transposed [b,h,d,t]
    dim3 gv(Tt / 32, Dd / 32, Bq * Hh);
    vtrans<<<gv, dim3(32, 8)>>>(vp, vtp);

    // FP16 flash attention
    size_t smem = (size_t)HSM_WORDS * 4;   // 71680 B -> 2 CTAs/SM
    cudaFuncSetAttribute(attn_h, cudaFuncAttributeMaxDynamicSharedMemorySize, (int)smem);
    dim3 ga(Tt / BRt, Hh, Bq);
    attn_h<<<ga, 128, smem>>>(qhp, khp, vtp, op);

    // Output projection
    dim3 go(Mm / 128, BT / 128, 1);
    gemm_tf32<<<go, 256>>>(op, wor, wor, wor, out, out, out, BT, Mm, HD, 0u);
}

// round 8
// speedup vs baseline: 10.3383x; 1.3625x over previous
#include <cuda_runtime.h>
#include <cuda_fp16.h>
#include <math.h>
#include <stdint.h>

// Problem dims (fixed)
#define Bq 2
#define Tt 2048
#define Mm 1024
#define Hh 8
#define Dd 128
#define BT (Bq*Tt)      // 4096
#define HD (Hh*Dd)      // 1024

// Scratch — no cudaMalloc allowed
__device__ float  g_q[BT*HD];          // fp32 q from gemm [b,t,h,d]
__device__ float  g_k[BT*HD];
__device__ float  g_v[BT*HD];
__device__ __half g_xh[BT*Mm];         // fp16 x
__device__ __half g_wqt[Mm*HD];        // fp16 wq^T [N][K]
__device__ __half g_wkt[Mm*HD];
__device__ __half g_wvt[Mm*HD];
__device__ __half g_wot[HD*Mm];        // fp16 wo^T [N=Mm][K=HD]
__device__ __half g_qh[BT*HD];         // fp16 q [b,h,t,d]
__device__ __half g_kh[BT*HD];         // fp16 k [b,h,t,d]
__device__ __half g_vt[BT*HD];         // fp16 v transposed [b,h,d,t]
__device__ __half g_oh[BT*HD];         // fp16 attention out [b,t,h,d]

__device__ __forceinline__ void mma_f16(float c[4], uint32_t a0, uint32_t a1,
                                        uint32_t a2, uint32_t a3,
                                        uint32_t b0, uint32_t b1) {
    asm volatile(
        "mma.sync.aligned.m16n8k16.row.col.f32.f16.f16.f32 "
        "{%0,%1,%2,%3}, {%4,%5,%6,%7}, {%8,%9}, {%0,%1,%2,%3};\n"
        : "+f"(c[0]), "+f"(c[1]), "+f"(c[2]), "+f"(c[3])
        : "r"(a0), "r"(a1), "r"(a2), "r"(a3), "r"(b0), "r"(b1));
}

__device__ __forceinline__ uint32_t packh2(float lo, float hi) {
    __half2 h = __floats2half2_rn(lo, hi);
    return *(uint32_t*)&h;
}

__device__ __forceinline__ void cp16(uint32_t dst, const void* src) {
    asm volatile("cp.async.ca.shared.global [%0], [%1], 16;\n" :: "r"(dst), "l"(src));
}
#define CP_COMMIT() asm volatile("cp.async.commit_group;\n" ::: "memory")
#define CP_WAIT(n)  asm volatile("cp.async.wait_group %0;\n" :: "n"(n) : "memory")

// ---------------------------------------------------------------------------
// fp32 -> fp16 elementwise (float4 granularity)
// ---------------------------------------------------------------------------
__global__ __launch_bounds__(256) void f2h(const float* __restrict__ src,
                                           __half* __restrict__ dst, int n4) {
    int i = blockIdx.x * blockDim.x + threadIdx.x;
    if (i < n4) {
        float4 v = ((const float4*)src)[i];
        ((uint2*)dst)[i] = make_uint2(packh2(v.x, v.y), packh2(v.z, v.w));
    }
}

// ---------------------------------------------------------------------------
// Weight transpose + fp16: w [1024][1024] fp32 -> wt [1024][1024] fp16 (w^T).
// Grid (32, 32, 4); block (32, 8). z selects which weight.
// ---------------------------------------------------------------------------
__global__ __launch_bounds__(256) void wtrans(const float* __restrict__ w0,
                                              const float* __restrict__ w1,
                                              const float* __restrict__ w2,
                                              const float* __restrict__ w3,
                                              __half* __restrict__ o0,
                                              __half* __restrict__ o1,
                                              __half* __restrict__ o2,
                                              __half* __restrict__ o3) {
    const float* w = (blockIdx.z == 0) ? w0 : (blockIdx.z == 1) ? w1
                     : (blockIdx.z == 2) ? w2 : w3;
    __half* o = (blockIdx.z == 0) ? o0 : (blockIdx.z == 1) ? o1
                : (blockIdx.z == 2) ? o2 : o3;
    __shared__ __half tile[32][33];
    const int tx = threadIdx.x, ty = threadIdx.y;
    const int k0 = blockIdx.x * 32, n0 = blockIdx.y * 32;
#pragma unroll
    for (int i = 0; i < 4; i++)
        tile[ty + i * 8][tx] = __float2half_rn(w[(size_t)(k0 + ty + i * 8) * 1024 + n0 + tx]);
    __syncthreads();
#pragma unroll
    for (int i = 0; i < 4; i++)
        o[(size_t)(n0 + ty + i * 8) * 1024 + k0 + tx] = tile[tx][ty + i * 8];
}

// ---------------------------------------------------------------------------
// FP16 GEMM: C[M,N](fp32) = A[M,K](fp16, row-major) * B^T[N,K](fp16).
// 128x128 CTA tile, BK=32, 256 threads (8 warps, 32x64 warp tiles).
// mma.m16n8k16. smem stride 20 u32 (16 data + 4 pad) — bank-conflict-free.
// Batched over blockIdx.z via pointer triples.
// ---------------------------------------------------------------------------
#define HGSTR 20

__global__ __launch_bounds__(256) void gemm_h(const __half* __restrict__ A,
                                              const __half* __restrict__ B0,
                                              const __half* __restrict__ B1,
                                              const __half* __restrict__ B2,
                                              float* __restrict__ C0,
                                              float* __restrict__ C1,
                                              float* __restrict__ C2,
                                              int M, int N, int K) {
    const __half* Bt = (blockIdx.z == 0) ? B0 : (blockIdx.z == 1) ? B1 : B2;
    float* C = (blockIdx.z == 0) ? C0 : (blockIdx.z == 1) ? C1 : C2;

    __shared__ uint32_t As[2][128 * HGSTR];
    __shared__ uint32_t Bs[2][128 * HGSTR];

    const int tid  = threadIdx.x;
    const int lane = tid & 31;
    const int warp = tid >> 5;
    const int gid  = lane >> 2;
    const int tig  = lane & 3;
    const int wm   = (warp >> 1) * 32;
    const int wn   = (warp & 1) * 64;
    const int rowBase = blockIdx.y * 128;
    const int colBase = blockIdx.x * 128;

    const __half* Ag = A + (size_t)rowBase * K;
    const __half* Bg = Bt + (size_t)colBase * K;
    const uint32_t sA = (uint32_t)__cvta_generic_to_shared(&As[0][0]);
    const uint32_t sB = (uint32_t)__cvta_generic_to_shared(&Bs[0][0]);

    float acc[2][8][4];
#pragma unroll
    for (int mt = 0; mt < 2; mt++)
#pragma unroll
        for (int nt = 0; nt < 8; nt++)
#pragma unroll
            for (int i = 0; i < 4; i++) acc[mt][nt][i] = 0.f;

    // ---- issue tile 0: each tile 128 rows x 32 fp16 = 512 chunks of 16B ----
    {
#pragma unroll
        for (int i = 0; i < 2; i++) {
            const int s = tid + i * 256;
            const int r = s >> 2, c = s & 3;          // c: which 8-fp16 chunk
            cp16(sA + (r * HGSTR + c * 4) * 4, Ag + (size_t)r * K + c * 8);
            cp16(sB + (r * HGSTR + c * 4) * 4, Bg + (size_t)r * K + c * 8);
        }
        CP_COMMIT();
    }

    const int niter = K >> 5;   // K/32
    for (int it = 0; it < niter; it++) {
        const int cur = it & 1;
        if (it + 1 < niter) {
            const int k0 = (it + 1) << 5;
            const int nxt = (it + 1) & 1;
#pragma unroll
            for (int i = 0; i < 2; i++) {
                const int s = tid + i * 256;
                const int r = s >> 2, c = s & 3;
                cp16(sA + (nxt * 128 * HGSTR + r * HGSTR + c * 4) * 4,
                     Ag + (size_t)r * K + k0 + c * 8);
                cp16(sB + (nxt * 128 * HGSTR + r * HGSTR + c * 4) * 4,
                     Bg + (size_t)r * K + k0 + c * 8);
            }
            CP_COMMIT();
            CP_WAIT(1);
        } else {
            CP_WAIT(0);
        }
        __syncthreads();

        const uint32_t* as = &As[cur][0];
        const uint32_t* bs = &Bs[cur][0];
#pragma unroll
        for (int kh = 0; kh < 2; kh++) {           // two k16 steps
            const int kk = kh * 8;
            uint32_t af[2][4];
#pragma unroll
            for (int mt = 0; mt < 2; mt++) {
                const int r = wm + mt * 16 + gid;
                af[mt][0] = as[r * HGSTR + kk + tig];
                af[mt][1] = as[(r + 8) * HGSTR + kk + tig];
                af[mt][2] = as[r * HGSTR + kk + tig + 4];
                af[mt][3] = as[(r + 8) * HGSTR + kk + tig + 4];
            }
#pragma unroll
            for (int nt = 0; nt < 8; nt++) {
                const int n = wn + nt * 8 + gid;
                const uint32_t b0 = bs[n * HGSTR + kk + tig];
                const uint32_t b1 = bs[n * HGSTR + kk + tig + 4];
#pragma unroll
                for (int mt = 0; mt < 2; mt++)
                    mma_f16(acc[mt][nt], af[mt][0], af[mt][1], af[mt][2], af[mt][3], b0, b1);
            }
        }
        __syncthreads();
    }

#pragma unroll
    for (int mt = 0; mt < 2; mt++) {
#pragma unroll
        for (int nt = 0; nt < 8; nt++) {
            const int r0 = rowBase + wm + mt * 16 + gid;
            const int c0 = colBase + wn + nt * 8 + 2 * tig;
            *(float2*)(C + (size_t)r0 * N + c0)       = make_float2(acc[mt][nt][0], acc[mt][nt][1]);
            *(float2*)(C + (size_t)(r0 + 8) * N + c0) = make_float2(acc[mt][nt][2], acc[mt][nt][3]);
        }
    }
}

// ---------------------------------------------------------------------------
// RMSNorm + RoPE + fold sqrt(1/128); fp32 [b,t,h,d] in -> fp16 [b,h,t,d] out.
// ---------------------------------------------------------------------------
__global__ __launch_bounds__(256) void normrope_h(const float* __restrict__ q,
                                                  const float* __restrict__ k,
                                                  __half* __restrict__ qh,
                                                  __half* __restrict__ kh) {
    int gwarp = (blockIdx.x * blockDim.x + threadIdx.x) >> 5;
    int lane  = threadIdx.x & 31;
    const int nrows = BT * Hh;
    const float* src = (gwarp < nrows) ? q : k;
    __half* dst = (gwarp < nrows) ? qh : kh;
    int row = (gwarp < nrows) ? gwarp : gwarp - nrows;
    int bt = row >> 3;
    int h  = row & 7;
    int t  = bt & (Tt - 1);
    int b  = bt >> 11;

    const float* p = src + (size_t)bt * HD + h * Dd;
    float e0 = p[lane], e1 = p[lane + 32];
    float o0 = p[lane + 64], o1 = p[lane + 96];

    float ss = e0 * e0 + e1 * e1 + o0 * o0 + o1 * o1;
#pragma unroll
    for (int off = 16; off; off >>= 1) ss += __shfl_xor_sync(0xffffffffu, ss, off);

    float scale = rsqrtf(ss * (1.0f / 128.0f) + 1e-6f) * 0.08838834764831845f;
    e0 *= scale; e1 *= scale; o0 *= scale; o1 *= scale;

    float f0 = powf(10000.0f, -((float)lane) * (1.0f / 64.0f));
    float f1 = powf(10000.0f, -((float)(lane + 32)) * (1.0f / 64.0f));
    float r0 = (float)t * f0, r1 = (float)t * f1;
    float s0, c0, s1, c1;
    sincosf(r0, &s0, &c0);
    sincosf(r1, &s1, &c1);

    __half* op = dst + (((size_t)(b * Hh + h)) * Tt + t) * Dd;
    op[lane]      = __float2half_rn(e0 * c0 - o0 * s0);
    op[lane + 32] = __float2half_rn(e1 * c1 - o1 * s1);
    op[lane + 64] = __float2half_rn(e0 * s0 + o0 * c0);
    op[lane + 96] = __float2half_rn(e1 * s1 + o1 * c1);
}

// ---------------------------------------------------------------------------
// V transpose + fp16: g_v [b,t,h,d] fp32 -> g_vt [b,h,d,t] fp16.
// ---------------------------------------------------------------------------
__global__ __launch_bounds__(256) void vtrans(const float* __restrict__ v,
                                              __half* __restrict__ vt) {
    __shared__ __half tile[32][33];
    const int tx = threadIdx.x, ty = threadIdx.y;
    const int t0 = blockIdx.x * 32;
    const int d0 = blockIdx.y * 32;
    const int bh = blockIdx.z;
    const int b = bh >> 3, h = bh & 7;

    const float* in = v + ((size_t)b * Tt) * HD + h * Dd;
#pragma unroll
    for (int i = 0; i < 4; i++) {
        int t = t0 + ty + i * 8;
        tile[ty + i * 8][tx] = __float2half_rn(in[(size_t)t * HD + d0 + tx]);
    }
    __syncthreads();

    __half* out = vt + ((size_t)bh * Dd) * Tt;
#pragma unroll
    for (int i = 0; i < 4; i++) {
        int d = d0 + ty + i * 8;
        out[(size_t)d * Tt + t0 + tx] = tile[tx][ty + i * 8];
    }
}

// ---------------------------------------------------------------------------
// FP16 flash attention (causal): BR=64 (4 warps), BC=64. (round-7 design)
// Epilogue now writes fp16 to g_oh [b,t,h,d].
// ---------------------------------------------------------------------------
#define BRt 64
#define BCt 64
#define HKSTR 68
#define HVSTR 36
#define HOFF_K0 0
#define HOFF_V0 (HOFF_K0 + 64*HKSTR)    // 4352
#define HOFF_K1 (HOFF_V0 + 128*HVSTR)   // 8960
#define HOFF_V1 (HOFF_K1 + 64*HKSTR)    // 13312
#define HSM_WORDS (HOFF_V1 + 128*HVSTR) // 17920 words = 71680 B

__global__ __launch_bounds__(128) void attn_h(const __half* __restrict__ qh,
                                              const __half* __restrict__ kh,
                                              const __half* __restrict__ vt,
                                              __half* __restrict__ oh) {
    extern __shared__ uint32_t smu[];

    const int tid  = threadIdx.x;
    const int lane = tid & 31;
    const int warp = tid >> 5;
    const int gid  = lane >> 2;
    const int tig  = lane & 3;
    const int qb = (gridDim.x - 1) - blockIdx.x;   // heavy blocks first
    const int h = blockIdx.y, b = blockIdx.z;
    const int t0 = qb * BRt;
    const int wrow = warp * 16;

    const size_t bhOff = (size_t)(b * Hh + h) * Tt * Dd;
    const __half* qbase = qh + bhOff + (size_t)t0 * Dd;
    const __half* kbase = kh + bhOff;
    const __half* vbase = vt + bhOff;              // [d][t]
    const uint32_t smemBase = (uint32_t)__cvta_generic_to_shared(smu);

    {
#pragma unroll
        for (int i = 0; i < 8; i++) {
            const int s = tid + i * 128;
            const int r = s >> 4, c = s & 15;
            cp16(smemBase + (HOFF_K0 + r * HKSTR + c * 4) * 4,
                 kbase + (size_t)r * Dd + c * 8);
        }
#pragma unroll
        for (int i = 0; i < 8; i++) {
            const int s = tid + i * 128;
            const int r = s >> 3, c = s & 7;
            cp16(smemBase + (HOFF_V0 + r * HVSTR + c * 4) * 4,
                 vbase + (size_t)r * Tt + c * 8);
        }
        CP_COMMIT();
    }
    {
#pragma unroll
        for (int i = 0; i < 8; i++) {
            const int s = tid + i * 128;
            const int r = s >> 4, c = s & 15;
            cp16(smemBase + (HOFF_K1 + r * HKSTR + c * 4) * 4,
                 qbase + (size_t)r * Dd + c * 8);
        }
        CP_COMMIT();
        CP_WAIT(0);
    }
    __syncthreads();

    uint32_t qf[8][4];
    {
        const uint32_t* Qs = smu + HOFF_K1;
#pragma unroll
        for (int ks = 0; ks < 8; ks++) {
            qf[ks][0] = Qs[(wrow + gid) * HKSTR + 8 * ks + tig];
            qf[ks][1] = Qs[(wrow + gid + 8) * HKSTR + 8 * ks + tig];
            qf[ks][2] = Qs[(wrow + gid) * HKSTR + 8 * ks + tig + 4];
            qf[ks][3] = Qs[(wrow + gid + 8) * HKSTR + 8 * ks + tig + 4];
        }
    }
    __syncthreads();

    float m0 = -1e30f, m1 = -1e30f, l0 = 0.f, l1 = 0.f;
    float oacc[16][4];
#pragma unroll
    for (int nt = 0; nt < 16; nt++)
#pragma unroll
        for (int i = 0; i < 4; i++) oacc[nt][i] = 0.f;

    for (int kb = 0; kb <= qb; kb++) {
        if (kb + 1 <= qb) {
            const int tk0 = (kb + 1) * BCt;
            const int offK = ((kb + 1) & 1) ? HOFF_K1 : HOFF_K0;
            const int offV = ((kb + 1) & 1) ? HOFF_V1 : HOFF_V0;
#pragma unroll
            for (int i = 0; i < 8; i++) {
                const int s = tid + i * 128;
                const int r = s >> 4, c = s & 15;
                cp16(smemBase + (offK + r * HKSTR + c * 4) * 4,
                     kbase + (size_t)(tk0 + r) * Dd + c * 8);
            }
#pragma unroll
            for (int i = 0; i < 8; i++) {
                const int s = tid + i * 128;
                const int r = s >> 3, c = s & 7;
                cp16(smemBase + (offV + r * HVSTR + c * 4) * 4,
                     vbase + (size_t)r * Tt + tk0 + c * 8);
            }
            CP_COMMIT();
            CP_WAIT(1);
        } else {
            CP_WAIT(0);
        }
        __syncthreads();

        const uint32_t* Ks = smu + ((kb & 1) ? HOFF_K1 : HOFF_K0);
        const uint32_t* Vs = smu + ((kb & 1) ? HOFF_V1 : HOFF_V0);
        const int tk0 = kb * BCt;

        float sacc[8][4];
#pragma unroll
        for (int nt = 0; nt < 8; nt++)
#pragma unroll
            for (int i = 0; i < 4; i++) sacc[nt][i] = 0.f;

#pragma unroll
        for (int ks = 0; ks < 8; ks++) {
#pragma unroll
            for (int nt = 0; nt < 8; nt++) {
                const uint32_t b0 = Ks[(nt * 8 + gid) * HKSTR + 8 * ks + tig];
                const uint32_t b1 = Ks[(nt * 8 + gid) * HKSTR + 8 * ks + tig + 4];
                mma_f16(sacc[nt], qf[ks][0], qf[ks][1], qf[ks][2], qf[ks][3], b0, b1);
            }
        }

        if (kb == qb) {
            const int rg0 = t0 + wrow + gid;
            const int rg1 = rg0 + 8;
#pragma unroll
            for (int nt = 0; nt < 8; nt++) {
                const int cg = tk0 + nt * 8 + 2 * tig;
                if (rg0 < cg)     sacc[nt][0] = -1e30f;
                if (rg0 < cg + 1) sacc[nt][1] = -1e30f;
                if (rg1 < cg)     sacc[nt][2] = -1e30f;
                if (rg1 < cg + 1) sacc[nt][3] = -1e30f;
            }
        }

        float rm0 = -1e30f, rm1 = -1e30f;
#pragma unroll
        for (int nt = 0; nt < 8; nt++) {
            rm0 = fmaxf(rm0, fmaxf(sacc[nt][0], sacc[nt][1]));
            rm1 = fmaxf(rm1, fmaxf(sacc[nt][2], sacc[nt][3]));
        }
        rm0 = fmaxf(rm0, __shfl_xor_sync(0xffffffffu, rm0, 1));
        rm0 = fmaxf(rm0, __shfl_xor_sync(0xffffffffu, rm0, 2));
        rm1 = fmaxf(rm1, __shfl_xor_sync(0xffffffffu, rm1, 1));
        rm1 = fmaxf(rm1, __shfl_xor_sync(0xffffffffu, rm1, 2));

        const float nm0 = fmaxf(m0, rm0);
        const float nm1 = fmaxf(m1, rm1);
        float sum0 = 0.f, sum1 = 0.f;
        uint32_t pe[8][2];
#pragma unroll
        for (int nt = 0; nt < 8; nt++) {
            float e00 = __expf(sacc[nt][0] - nm0);
            float e01 = __expf(sacc[nt][1] - nm0);
            float e10 = __expf(sacc[nt][2] - nm1);
            float e11 = __expf(sacc[nt][3] - nm1);
            sum0 += e00 + e01;
            sum1 += e10 + e11;
            pe[nt][0] = packh2(e00, e01);
            pe[nt][1] = packh2(e10, e11);
        }
        sum0 += __shfl_xor_sync(0xffffffffu, sum0, 1);
        sum0 += __shfl_xor_sync(0xffffffffu, sum0, 2);
        sum1 += __shfl_xor_sync(0xffffffffu, sum1, 1);
        sum1 += __shfl_xor_sync(0xffffffffu, sum1, 2);

        const float c0 = __expf(m0 - nm0);
        const float c1 = __expf(m1 - nm1);
        l0 = l0 * c0 + sum0; m0 = nm0;
        l1 = l1 * c1 + sum1; m1 = nm1;
#pragma unroll
        for (int nt = 0; nt < 16; nt++) {
            oacc[nt][0] *= c0; oacc[nt][1] *= c0;
            oacc[nt][2] *= c1; oacc[nt][3] *= c1;
        }

#pragma unroll
        for (int ks = 0; ks < 4; ks++) {
            const uint32_t a0 = pe[2 * ks][0];
            const uint32_t a1 = pe[2 * ks][1];
            const uint32_t a2 = pe[2 * ks + 1][0];
            const uint32_t a3 = pe[2 * ks + 1][1];
#pragma unroll
            for (int nt = 0; nt < 16; nt++) {
                const uint32_t b0 = Vs[(nt * 8 + gid) * HVSTR + 8 * ks + tig];
                const uint32_t b1 = Vs[(nt * 8 + gid) * HVSTR + 8 * ks + tig + 4];
                mma_f16(oacc[nt], a0, a1, a2, a3, b0, b1);
            }
        }
        __syncthreads();
    }

    // Epilogue: O / l -> fp16 g_oh [b,t,h,d]
    const float i0 = 1.0f / l0;
    const float i1 = 1.0f / l1;
    const int rg0 = t0 + wrow + gid;
    __half* ob0 = oh + ((size_t)(b * Tt + rg0) * Hh + h) * Dd;
    __half* ob1 = oh + ((size_t)(b * Tt + rg0 + 8) * Hh + h) * Dd;
#pragma unroll
    for (int nt = 0; nt < 16; nt++) {
        const int col = nt * 8 + 2 * tig;
        *(uint32_t*)(ob0 + col) = packh2(oacc[nt][0] * i0, oacc[nt][1] * i0);
        *(uint32_t*)(ob1 + col) = packh2(oacc[nt][2] * i1, oacc[nt][3] * i1);
    }
}

// ---------------------------------------------------------------------------
extern "C" void kernel_launch(void* const* d_in, const int* in_sizes, int n_in,
                              void* d_out, int out_size) {
    const float* x  = (const float*)d_in[0];
    const float* wq = (const float*)d_in[1];
    const float* wk = (const float*)d_in[2];
    const float* wv = (const float*)d_in[3];
    const float* wo = (const float*)d_in[4];
    float* out = (float*)d_out;

    float *qp, *kp, *vp;
    __half *xh, *wqt, *wkt, *wvt, *wot, *qhp, *khp, *vtp, *ohp;
    cudaGetSymbolAddress((void**)&qp, g_q);
    cudaGetSymbolAddress((void**)&kp, g_k);
    cudaGetSymbolAddress((void**)&vp, g_v);
    cudaGetSymbolAddress((void**)&xh, g_xh);
    cudaGetSymbolAddress((void**)&wqt, g_wqt);
    cudaGetSymbolAddress((void**)&wkt, g_wkt);
    cudaGetSymbolAddress((void**)&wvt, g_wvt);
    cudaGetSymbolAddress((void**)&wot, g_wot);
    cudaGetSymbolAddress((void**)&qhp, g_qh);
    cudaGetSymbolAddress((void**)&khp, g_kh);
    cudaGetSymbolAddress((void**)&vtp, g_vt);
    cudaGetSymbolAddress((void**)&ohp, g_oh);

    // Convert x to fp16; transpose+convert all four weights (one launch)
    f2h<<<(BT*Mm/4 + 255)/256, 256>>>(x, xh, BT*Mm/4);
    wtrans<<<dim3(32, 32, 4), dim3(32, 8)>>>(wq, wk, wv, wo, wqt, wkt, wvt, wot);

    // Fused QKV projections (fp16 MMA, fp32 out)
    dim3 gp(HD / 128, BT / 128, 3);
    gemm_h<<<gp, 256>>>(xh, wqt, wkt, wvt, qp, kp, vp, BT, HD, Mm);

    // RMSNorm + RoPE -> fp16 q,k in [b,h,t,d]
    int totalWarps = 2 * BT * Hh;
    normrope_h<<<totalWarps / 8, 256>>>(qp, kp, qhp, khp);

    // V -> fp16 transposed [b,h,d,t]
    dim3 gv(Tt / 32, Dd / 32, Bq * Hh);
    vtrans<<<gv, dim3(32, 8)>>>(vp, vtp);

    // FP16 flash attention -> fp16 O [b,t,h,d]
    size_t smem = (size_t)HSM_WORDS * 4;
    cudaFuncSetAttribute(attn_h, cudaFuncAttributeMaxDynamicSharedMemorySize, (int)smem);
    dim3 ga(Tt / BRt, Hh, Bq);
    attn_h<<<ga, 128, smem>>>(qhp, khp, vtp, ohp);

    // Output projection (fp16 MMA, fp32 out)
    dim3 go(Mm / 128, BT / 128, 1);
    gemm_h<<<go, 256>>>(ohp, wot, wot, wot, out, out, out, BT, Mm, HD);
}

// round 9
// speedup vs baseline: 11.3096x; 1.0940x over previous
#include <cuda_runtime.h>
#include <cuda_fp16.h>
#include <math.h>
#include <stdint.h>

// Problem dims (fixed)
#define Bq 2
#define Tt 2048
#define Mm 1024
#define Hh 8
#define Dd 128
#define BT (Bq*Tt)      // 4096
#define HD (Hh*Dd)      // 1024

// Scratch — no cudaMalloc allowed
__device__ __half g_xh[BT*Mm];         // fp16 x
__device__ __half g_wqt[Mm*HD];        // fp16 wq^T [N][K]
__device__ __half g_wkt[Mm*HD];
__device__ __half g_wvt[Mm*HD];
__device__ __half g_wot[HD*Mm];        // fp16 wo^T [N=Mm][K=HD]
__device__ __half g_qn[BT*HD];         // fp16 q proj [b,t,h,d]
__device__ __half g_kn[BT*HD];
__device__ __half g_vn[BT*HD];
__device__ __half g_qh[BT*HD];         // fp16 q (normed/roped) [b,h,t,d]
__device__ __half g_kh[BT*HD];         // fp16 k [b,h,t,d]
__device__ __half g_vt[BT*HD];         // fp16 v transposed [b,h,d,t]
__device__ __half g_oh[BT*HD];         // fp16 attention out [b,t,h,d]

__device__ __forceinline__ void mma_f16(float c[4], uint32_t a0, uint32_t a1,
                                        uint32_t a2, uint32_t a3,
                                        uint32_t b0, uint32_t b1) {
    asm volatile(
        "mma.sync.aligned.m16n8k16.row.col.f32.f16.f16.f32 "
        "{%0,%1,%2,%3}, {%4,%5,%6,%7}, {%8,%9}, {%0,%1,%2,%3};\n"
        : "+f"(c[0]), "+f"(c[1]), "+f"(c[2]), "+f"(c[3])
        : "r"(a0), "r"(a1), "r"(a2), "r"(a3), "r"(b0), "r"(b1));
}

__device__ __forceinline__ void ldsm4(uint32_t& r0, uint32_t& r1,
                                      uint32_t& r2, uint32_t& r3, uint32_t addr) {
    asm volatile("ldmatrix.sync.aligned.m8n8.x4.shared.b16 {%0,%1,%2,%3}, [%4];"
                 : "=r"(r0), "=r"(r1), "=r"(r2), "=r"(r3) : "r"(addr));
}

__device__ __forceinline__ uint32_t packh2(float lo, float hi) {
    __half2 h = __floats2half2_rn(lo, hi);
    return *(uint32_t*)&h;
}

__device__ __forceinline__ void cp16(uint32_t dst, const void* src) {
    asm volatile("cp.async.ca.shared.global [%0], [%1], 16;\n" :: "r"(dst), "l"(src));
}
#define CP_COMMIT() asm volatile("cp.async.commit_group;\n" ::: "memory")
#define CP_WAIT(n)  asm volatile("cp.async.wait_group %0;\n" :: "n"(n) : "memory")

// ---------------------------------------------------------------------------
__global__ __launch_bounds__(256) void f2h(const float* __restrict__ src,
                                           __half* __restrict__ dst, int n4) {
    int i = blockIdx.x * blockDim.x + threadIdx.x;
    if (i < n4) {
        float4 v = ((const float4*)src)[i];
        ((uint2*)dst)[i] = make_uint2(packh2(v.x, v.y), packh2(v.z, v.w));
    }
}

// ---------------------------------------------------------------------------
// Weight transpose + fp16: w [1024][1024] fp32 -> wt fp16 (w^T). z: which.
// ---------------------------------------------------------------------------
__global__ __launch_bounds__(256) void wtrans(const float* __restrict__ w0,
                                              const float* __restrict__ w1,
                                              const float* __restrict__ w2,
                                              const float* __restrict__ w3,
                                              __half* __restrict__ o0,
                                              __half* __restrict__ o1,
                                              __half* __restrict__ o2,
                                              __half* __restrict__ o3) {
    const float* w = (blockIdx.z == 0) ? w0 : (blockIdx.z == 1) ? w1
                     : (blockIdx.z == 2) ? w2 : w3;
    __half* o = (blockIdx.z == 0) ? o0 : (blockIdx.z == 1) ? o1
                : (blockIdx.z == 2) ? o2 : o3;
    __shared__ __half tile[32][33];
    const int tx = threadIdx.x, ty = threadIdx.y;
    const int k0 = blockIdx.x * 32, n0 = blockIdx.y * 32;
#pragma unroll
    for (int i = 0; i < 4; i++)
        tile[ty + i * 8][tx] = __float2half_rn(w[(size_t)(k0 + ty + i * 8) * 1024 + n0 + tx]);
    __syncthreads();
#pragma unroll
    for (int i = 0; i < 4; i++)
        o[(size_t)(n0 + ty + i * 8) * 1024 + k0 + tx] = tile[tx][ty + i * 8];
}

// ---------------------------------------------------------------------------
// FP16 GEMM (LDSM operands): C = A[M,K] * B^T[N,K].
// 128x128 CTA tile, BK=32, 256 threads (8 warps, 32x64 warp tiles).
// halfOut: write fp16 to Ch*, else fp32 to Cf*.
// ---------------------------------------------------------------------------
#define HGSTR 20

__global__ __launch_bounds__(256) void gemm_h(const __half* __restrict__ A,
                                              const __half* __restrict__ B0,
                                              const __half* __restrict__ B1,
                                              const __half* __restrict__ B2,
                                              float* __restrict__ Cf0,
                                              float* __restrict__ Cf1,
                                              float* __restrict__ Cf2,
                                              __half* __restrict__ Ch0,
                                              __half* __restrict__ Ch1,
                                              __half* __restrict__ Ch2,
                                              int M, int N, int K, int halfOut) {
    const __half* Bt = (blockIdx.z == 0) ? B0 : (blockIdx.z == 1) ? B1 : B2;
    float* Cf = (blockIdx.z == 0) ? Cf0 : (blockIdx.z == 1) ? Cf1 : Cf2;
    __half* Ch = (blockIdx.z == 0) ? Ch0 : (blockIdx.z == 1) ? Ch1 : Ch2;

    __shared__ uint32_t As[2][128 * HGSTR];
    __shared__ uint32_t Bs[2][128 * HGSTR];

    const int tid  = threadIdx.x;
    const int lane = tid & 31;
    const int warp = tid >> 5;
    const int gid  = lane >> 2;
    const int tig  = lane & 3;
    const int lm   = lane >> 3;     // ldmatrix matrix index
    const int lr   = lane & 7;      // ldmatrix row within matrix
    const int wm   = (warp >> 1) * 32;
    const int wn   = (warp & 1) * 64;
    const int rowBase = blockIdx.y * 128;
    const int colBase = blockIdx.x * 128;

    const __half* Ag = A + (size_t)rowBase * K;
    const __half* Bg = Bt + (size_t)colBase * K;
    const uint32_t sA = (uint32_t)__cvta_generic_to_shared(&As[0][0]);
    const uint32_t sB = (uint32_t)__cvta_generic_to_shared(&Bs[0][0]);

    float acc[2][8][4];
#pragma unroll
    for (int mt = 0; mt < 2; mt++)
#pragma unroll
        for (int nt = 0; nt < 8; nt++)
#pragma unroll
            for (int i = 0; i < 4; i++) acc[mt][nt][i] = 0.f;

    {
#pragma unroll
        for (int i = 0; i < 2; i++) {
            const int s = tid + i * 256;
            const int r = s >> 2, c = s & 3;
            cp16(sA + (r * HGSTR + c * 4) * 4, Ag + (size_t)r * K + c * 8);
            cp16(sB + (r * HGSTR + c * 4) * 4, Bg + (size_t)r * K + c * 8);
        }
        CP_COMMIT();
    }

    const int niter = K >> 5;
    for (int it = 0; it < niter; it++) {
        const int cur = it & 1;
        if (it + 1 < niter) {
            const int k0 = (it + 1) << 5;
            const int nxt = (it + 1) & 1;
#pragma unroll
            for (int i = 0; i < 2; i++) {
                const int s = tid + i * 256;
                const int r = s >> 2, c = s & 3;
                cp16(sA + (nxt * 128 * HGSTR + r * HGSTR + c * 4) * 4,
                     Ag + (size_t)r * K + k0 + c * 8);
                cp16(sB + (nxt * 128 * HGSTR + r * HGSTR + c * 4) * 4,
                     Bg + (size_t)r * K + k0 + c * 8);
            }
            CP_COMMIT();
            CP_WAIT(1);
        } else {
            CP_WAIT(0);
        }
        __syncthreads();

        const uint32_t sAc = sA + cur * 128 * HGSTR * 4;
        const uint32_t sBc = sB + cur * 128 * HGSTR * 4;
#pragma unroll
        for (int kh = 0; kh < 2; kh++) {
            const int kk = kh * 8;
            // A fragments: m0=rows0-7/k0, m1=rows8-15/k0, m2=rows0-7/k1, m3=rows8-15/k1
            uint32_t af[2][4];
#pragma unroll
            for (int mt = 0; mt < 2; mt++) {
                const int row = wm + mt * 16 + (lm & 1) * 8 + lr;
                const int word = kk + (lm >> 1) * 4;
                ldsm4(af[mt][0], af[mt][1], af[mt][2], af[mt][3],
                      sAc + (row * HGSTR + word) * 4);
            }
            // B fragments: pairs of nt; m0=nt/k0, m1=nt/k1, m2=nt+1/k0, m3=nt+1/k1
#pragma unroll
            for (int np = 0; np < 4; np++) {
                const int row = wn + (2 * np + (lm >> 1)) * 8 + lr;
                const int word = kk + (lm & 1) * 4;
                uint32_t b00, b01, b10, b11;
                ldsm4(b00, b01, b10, b11, sBc + (row * HGSTR + word) * 4);
#pragma unroll
                for (int mt = 0; mt < 2; mt++) {
                    mma_f16(acc[mt][2 * np],     af[mt][0], af[mt][1], af[mt][2], af[mt][3], b00, b01);
                    mma_f16(acc[mt][2 * np + 1], af[mt][0], af[mt][1], af[mt][2], af[mt][3], b10, b11);
                }
            }
        }
        __syncthreads();
    }

#pragma unroll
    for (int mt = 0; mt < 2; mt++) {
#pragma unroll
        for (int nt = 0; nt < 8; nt++) {
            const int r0 = rowBase + wm + mt * 16 + gid;
            const int c0 = colBase + wn + nt * 8 + 2 * tig;
            if (halfOut) {
                *(uint32_t*)(Ch + (size_t)r0 * N + c0)       = packh2(acc[mt][nt][0], acc[mt][nt][1]);
                *(uint32_t*)(Ch + (size_t)(r0 + 8) * N + c0) = packh2(acc[mt][nt][2], acc[mt][nt][3]);
            } else {
                *(float2*)(Cf + (size_t)r0 * N + c0)       = make_float2(acc[mt][nt][0], acc[mt][nt][1]);
                *(float2*)(Cf + (size_t)(r0 + 8) * N + c0) = make_float2(acc[mt][nt][2], acc[mt][nt][3]);
            }
        }
    }
}

// ---------------------------------------------------------------------------
// RMSNorm + RoPE + fold sqrt(1/128); fp16 [b,t,h,d] in -> fp16 [b,h,t,d] out.
// ---------------------------------------------------------------------------
__global__ __launch_bounds__(256) void normrope_h(const __half* __restrict__ q,
                                                  const __half* __restrict__ k,
                                                  __half* __restrict__ qh,
                                                  __half* __restrict__ kh) {
    int gwarp = (blockIdx.x * blockDim.x + threadIdx.x) >> 5;
    int lane  = threadIdx.x & 31;
    const int nrows = BT * Hh;
    const __half* src = (gwarp < nrows) ? q : k;
    __half* dst = (gwarp < nrows) ? qh : kh;
    int row = (gwarp < nrows) ? gwarp : gwarp - nrows;
    int bt = row >> 3;
    int h  = row & 7;
    int t  = bt & (Tt - 1);
    int b  = bt >> 11;

    const __half* p = src + (size_t)bt * HD + h * Dd;
    float e0 = __half2float(p[lane]),      e1 = __half2float(p[lane + 32]);
    float o0 = __half2float(p[lane + 64]), o1 = __half2float(p[lane + 96]);

    float ss = e0 * e0 + e1 * e1 + o0 * o0 + o1 * o1;
#pragma unroll
    for (int off = 16; off; off >>= 1) ss += __shfl_xor_sync(0xffffffffu, ss, off);

    float scale = rsqrtf(ss * (1.0f / 128.0f) + 1e-6f) * 0.08838834764831845f;
    e0 *= scale; e1 *= scale; o0 *= scale; o1 *= scale;

    float f0 = powf(10000.0f, -((float)lane) * (1.0f / 64.0f));
    float f1 = powf(10000.0f, -((float)(lane + 32)) * (1.0f / 64.0f));
    float r0 = (float)t * f0, r1 = (float)t * f1;
    float s0, c0, s1, c1;
    sincosf(r0, &s0, &c0);
    sincosf(r1, &s1, &c1);

    __half* op = dst + (((size_t)(b * Hh + h)) * Tt + t) * Dd;
    op[lane]      = __float2half_rn(e0 * c0 - o0 * s0);
    op[lane + 32] = __float2half_rn(e1 * c1 - o1 * s1);
    op[lane + 64] = __float2half_rn(e0 * s0 + o0 * c0);
    op[lane + 96] = __float2half_rn(e1 * s1 + o1 * c1);
}

// ---------------------------------------------------------------------------
// V transpose: g_vn [b,t,h,d] fp16 -> g_vt [b,h,d,t] fp16.
// ---------------------------------------------------------------------------
__global__ __launch_bounds__(256) void vtrans(const __half* __restrict__ v,
                                              __half* __restrict__ vt) {
    __shared__ __half tile[32][33];
    const int tx = threadIdx.x, ty = threadIdx.y;
    const int t0 = blockIdx.x * 32;
    const int d0 = blockIdx.y * 32;
    const int bh = blockIdx.z;
    const int b = bh >> 3, h = bh & 7;

    const __half* in = v + ((size_t)b * Tt) * HD + h * Dd;
#pragma unroll
    for (int i = 0; i < 4; i++) {
        int t = t0 + ty + i * 8;
        tile[ty + i * 8][tx] = in[(size_t)t * HD + d0 + tx];
    }
    __syncthreads();

    __half* out = vt + ((size_t)bh * Dd) * Tt;
#pragma unroll
    for (int i = 0; i < 4; i++) {
        int d = d0 + ty + i * 8;
        out[(size_t)d * Tt + t0 + tx] = tile[tx][ty + i * 8];
    }
}

// ---------------------------------------------------------------------------
// FP16 flash attention (causal), LDSM operands: BR=64 (4 warps), BC=64.
// ---------------------------------------------------------------------------
#define BRt 64
#define BCt 64
#define HKSTR 68
#define HVSTR 36
#define HOFF_K0 0
#define HOFF_V0 (HOFF_K0 + 64*HKSTR)    // 4352
#define HOFF_K1 (HOFF_V0 + 128*HVSTR)   // 8960
#define HOFF_V1 (HOFF_K1 + 64*HKSTR)    // 13312
#define HSM_WORDS (HOFF_V1 + 128*HVSTR) // 17920 words = 71680 B

__global__ __launch_bounds__(128) void attn_h(const __half* __restrict__ qh,
                                              const __half* __restrict__ kh,
                                              const __half* __restrict__ vt,
                                              __half* __restrict__ oh) {
    extern __shared__ uint32_t smu[];

    const int tid  = threadIdx.x;
    const int lane = tid & 31;
    const int warp = tid >> 5;
    const int gid  = lane >> 2;
    const int tig  = lane & 3;
    const int lm   = lane >> 3;
    const int lr   = lane & 7;
    const int qb = (gridDim.x - 1) - blockIdx.x;   // heavy blocks first
    const int h = blockIdx.y, b = blockIdx.z;
    const int t0 = qb * BRt;
    const int wrow = warp * 16;

    const size_t bhOff = (size_t)(b * Hh + h) * Tt * Dd;
    const __half* qbase = qh + bhOff + (size_t)t0 * Dd;
    const __half* kbase = kh + bhOff;
    const __half* vbase = vt + bhOff;              // [d][t]
    const uint32_t smemBase = (uint32_t)__cvta_generic_to_shared(smu);

    // LDSM per-thread address components (B-operand mapping):
    // m0=(ntpair row0,k0) m1=(row0,k1) m2=(row1,k0) m3=(row1,k1)
    const int bRowSel = lm >> 1;    // 0/1: which nt of the pair
    const int bKSel   = lm & 1;     // 0/1: which k-half

    {
#pragma unroll
        for (int i = 0; i < 8; i++) {
            const int s = tid + i * 128;
            const int r = s >> 4, c = s & 15;
            cp16(smemBase + (HOFF_K0 + r * HKSTR + c * 4) * 4,
                 kbase + (size_t)r * Dd + c * 8);
        }
#pragma unroll
        for (int i = 0; i < 8; i++) {
            const int s = tid + i * 128;
            const int r = s >> 3, c = s & 7;
            cp16(smemBase + (HOFF_V0 + r * HVSTR + c * 4) * 4,
                 vbase + (size_t)r * Tt + c * 8);
        }
        CP_COMMIT();
    }
    {
#pragma unroll
        for (int i = 0; i < 8; i++) {
            const int s = tid + i * 128;
            const int r = s >> 4, c = s & 15;
            cp16(smemBase + (HOFF_K1 + r * HKSTR + c * 4) * 4,
                 qbase + (size_t)r * Dd + c * 8);
        }
        CP_COMMIT();
        CP_WAIT(0);
    }
    __syncthreads();

    // Lift Q fragments via LDSM (A mapping: m0=r0/k0, m1=r8/k0, m2=r0/k1, m3=r8/k1)
    uint32_t qf[8][4];
    {
        const uint32_t qRow = wrow + (lm & 1) * 8 + lr;
        const uint32_t qWordSel = (lm >> 1) * 4;
#pragma unroll
        for (int ks = 0; ks < 8; ks++) {
            ldsm4(qf[ks][0], qf[ks][1], qf[ks][2], qf[ks][3],
                  smemBase + (HOFF_K1 + qRow * HKSTR + 8 * ks + qWordSel) * 4);
        }
    }
    __syncthreads();

    float m0 = -1e30f, m1 = -1e30f, l0 = 0.f, l1 = 0.f;
    float oacc[16][4];
#pragma unroll
    for (int nt = 0; nt < 16; nt++)
#pragma unroll
        for (int i = 0; i < 4; i++) oacc[nt][i] = 0.f;

    for (int kb = 0; kb <= qb; kb++) {
        if (kb + 1 <= qb) {
            const int tk0 = (kb + 1) * BCt;
            const int offK = ((kb + 1) & 1) ? HOFF_K1 : HOFF_K0;
            const int offV = ((kb + 1) & 1) ? HOFF_V1 : HOFF_V0;
#pragma unroll
            for (int i = 0; i < 8; i++) {
                const int s = tid + i * 128;
                const int r = s >> 4, c = s & 15;
                cp16(smemBase + (offK + r * HKSTR + c * 4) * 4,
                     kbase + (size_t)(tk0 + r) * Dd + c * 8);
            }
#pragma unroll
            for (int i = 0; i < 8; i++) {
                const int s = tid + i * 128;
                const int r = s >> 3, c = s & 7;
                cp16(smemBase + (offV + r * HVSTR + c * 4) * 4,
                     vbase + (size_t)r * Tt + tk0 + c * 8);
            }
            CP_COMMIT();
            CP_WAIT(1);
        } else {
            CP_WAIT(0);
        }
        __syncthreads();

        const uint32_t offK = (kb & 1) ? HOFF_K1 : HOFF_K0;
        const uint32_t offV = (kb & 1) ? HOFF_V1 : HOFF_V0;
        const int tk0 = kb * BCt;

        // S = Q K^T : warp tile 16x64; B frags via LDSM x4 (2 nt per load)
        float sacc[8][4];
#pragma unroll
        for (int nt = 0; nt < 8; nt++)
#pragma unroll
            for (int i = 0; i < 4; i++) sacc[nt][i] = 0.f;

        const uint32_t kAddr0 = smemBase + (offK + ((bRowSel * 8 + lr) * HKSTR) + bKSel * 4) * 4;
#pragma unroll
        for (int ks = 0; ks < 8; ks++) {
#pragma unroll
            for (int np = 0; np < 4; np++) {
                uint32_t b00, b01, b10, b11;
                ldsm4(b00, b01, b10, b11,
                      kAddr0 + ((2 * np) * 8 * HKSTR + 8 * ks) * 4);
                mma_f16(sacc[2 * np],     qf[ks][0], qf[ks][1], qf[ks][2], qf[ks][3], b00, b01);
                mma_f16(sacc[2 * np + 1], qf[ks][0], qf[ks][1], qf[ks][2], qf[ks][3], b10, b11);
            }
        }

        if (kb == qb) {
            const int rg0 = t0 + wrow + gid;
            const int rg1 = rg0 + 8;
#pragma unroll
            for (int nt = 0; nt < 8; nt++) {
                const int cg = tk0 + nt * 8 + 2 * tig;
                if (rg0 < cg)     sacc[nt][0] = -1e30f;
                if (rg0 < cg + 1) sacc[nt][1] = -1e30f;
                if (rg1 < cg)     sacc[nt][2] = -1e30f;
                if (rg1 < cg + 1) sacc[nt][3] = -1e30f;
            }
        }

        // Online softmax in registers
        float rm0 = -1e30f, rm1 = -1e30f;
#pragma unroll
        for (int nt = 0; nt < 8; nt++) {
            rm0 = fmaxf(rm0, fmaxf(sacc[nt][0], sacc[nt][1]));
            rm1 = fmaxf(rm1, fmaxf(sacc[nt][2], sacc[nt][3]));
        }
        rm0 = fmaxf(rm0, __shfl_xor_sync(0xffffffffu, rm0, 1));
        rm0 = fmaxf(rm0, __shfl_xor_sync(0xffffffffu, rm0, 2));
        rm1 = fmaxf(rm1, __shfl_xor_sync(0xffffffffu, rm1, 1));
        rm1 = fmaxf(rm1, __shfl_xor_sync(0xffffffffu, rm1, 2));

        const float nm0 = fmaxf(m0, rm0);
        const float nm1 = fmaxf(m1, rm1);
        float sum0 = 0.f, sum1 = 0.f;
        uint32_t pe[8][2];
#pragma unroll
        for (int nt = 0; nt < 8; nt++) {
            float e00 = __expf(sacc[nt][0] - nm0);
            float e01 = __expf(sacc[nt][1] - nm0);
            float e10 = __expf(sacc[nt][2] - nm1);
            float e11 = __expf(sacc[nt][3] - nm1);
            sum0 += e00 + e01;
            sum1 += e10 + e11;
            pe[nt][0] = packh2(e00, e01);
            pe[nt][1] = packh2(e10, e11);
        }
        sum0 += __shfl_xor_sync(0xffffffffu, sum0, 1);
        sum0 += __shfl_xor_sync(0xffffffffu, sum0, 2);
        sum1 += __shfl_xor_sync(0xffffffffu, sum1, 1);
        sum1 += __shfl_xor_sync(0xffffffffu, sum1, 2);

        const float c0 = __expf(m0 - nm0);
        const float c1 = __expf(m1 - nm1);
        l0 = l0 * c0 + sum0; m0 = nm0;
        l1 = l1 * c1 + sum1; m1 = nm1;
#pragma unroll
        for (int nt = 0; nt < 16; nt++) {
            oacc[nt][0] *= c0; oacc[nt][1] *= c0;
            oacc[nt][2] *= c1; oacc[nt][3] *= c1;
        }

        // O += P V : V B-frags via LDSM x4 (rows = d)
        const uint32_t vAddr0 = smemBase + (offV + ((bRowSel * 8 + lr) * HVSTR) + bKSel * 4) * 4;
#pragma unroll
        for (int ks = 0; ks < 4; ks++) {
            const uint32_t a0 = pe[2 * ks][0];
            const uint32_t a1 = pe[2 * ks][1];
            const uint32_t a2 = pe[2 * ks + 1][0];
            const uint32_t a3 = pe[2 * ks + 1][1];
#pragma unroll
            for (int np = 0; np < 8; np++) {
                uint32_t b00, b01, b10, b11;
                ldsm4(b00, b01, b10, b11,
                      vAddr0 + ((2 * np) * 8 * HVSTR + 8 * ks) * 4);
                mma_f16(oacc[2 * np],     a0, a1, a2, a3, b00, b01);
                mma_f16(oacc[2 * np + 1], a0, a1, a2, a3, b10, b11);
            }
        }
        __syncthreads();
    }

    // Epilogue: O / l -> fp16 g_oh [b,t,h,d]
    const float i0 = 1.0f / l0;
    const float i1 = 1.0f / l1;
    const int rg0 = t0 + wrow + gid;
    __half* ob0 = oh + ((size_t)(b * Tt + rg0) * Hh + h) * Dd;
    __half* ob1 = oh + ((size_t)(b * Tt + rg0 + 8) * Hh + h) * Dd;
#pragma unroll
    for (int nt = 0; nt < 16; nt++) {
        const int col = nt * 8 + 2 * tig;
        *(uint32_t*)(ob0 + col) = packh2(oacc[nt][0] * i0, oacc[nt][1] * i0);
        *(uint32_t*)(ob1 + col) = packh2(oacc[nt][2] * i1, oacc[nt][3] * i1);
    }
}

// ---------------------------------------------------------------------------
extern "C" void kernel_launch(void* const* d_in, const int* in_sizes, int n_in,
                              void* d_out, int out_size) {
    const float* x  = (const float*)d_in[0];
    const float* wq = (const float*)d_in[1];
    const float* wk = (const float*)d_in[2];
    const float* wv = (const float*)d_in[3];
    const float* wo = (const float*)d_in[4];
    float* out = (float*)d_out;

    __half *xh, *wqt, *wkt, *wvt, *wot, *qn, *kn, *vn, *qhp, *khp, *vtp, *ohp;
    cudaGetSymbolAddress((void**)&xh, g_xh);
    cudaGetSymbolAddress((void**)&wqt, g_wqt);
    cudaGetSymbolAddress((void**)&wkt, g_wkt);
    cudaGetSymbolAddress((void**)&wvt, g_wvt);
    cudaGetSymbolAddress((void**)&wot, g_wot);
    cudaGetSymbolAddress((void**)&qn, g_qn);
    cudaGetSymbolAddress((void**)&kn, g_kn);
    cudaGetSymbolAddress((void**)&vn, g_vn);
    cudaGetSymbolAddress((void**)&qhp, g_qh);
    cudaGetSymbolAddress((void**)&khp, g_kh);
    cudaGetSymbolAddress((void**)&vtp, g_vt);
    cudaGetSymbolAddress((void**)&ohp, g_oh);

    // Convert x; transpose+convert all four weights
    f2h<<<(BT*Mm/4 + 255)/256, 256>>>(x, xh, BT*Mm/4);
    wtrans<<<dim3(32, 32, 4), dim3(32, 8)>>>(wq, wk, wv, wo, wqt, wkt, wvt, wot);

    // Fused QKV projections -> fp16 [b,t,h,d]
    dim3 gp(HD / 128, BT / 128, 3);
    gemm_h<<<gp, 256>>>(xh, wqt, wkt, wvt,
                        nullptr, nullptr, nullptr, qn, kn, vn, BT, HD, Mm, 1);

    // RMSNorm + RoPE -> fp16 q,k in [b,h,t,d]
    int totalWarps = 2 * BT * Hh;
    normrope_h<<<totalWarps / 8, 256>>>(qn, kn, qhp, khp);

    // V -> fp16 transposed [b,h,d,t]
    dim3 gv(Tt / 32, Dd / 32, Bq * Hh);
    vtrans<<<gv, dim3(32, 8)>>>(vn, vtp);

    // FP16 flash attention -> fp16 O [b,t,h,d]
    size_t smem = (size_t)HSM_WORDS * 4;
    cudaFuncSetAttribute(attn_h, cudaFuncAttributeMaxDynamicSharedMemorySize, (int)smem);
    dim3 ga(Tt / BRt, Hh, Bq);
    attn_h<<<ga, 128, smem>>>(qhp, khp, vtp, ohp);

    // Output projection -> fp32 out
    dim3 go(Mm / 128, BT / 128, 1);
    gemm_h<<<go, 256>>>(ohp, wot, wot, wot,
                        out, out, out, nullptr, nullptr, nullptr, BT, Mm, HD, 0);
}

// round 10
// speedup vs baseline: 11.7394x; 1.0380x over previous
#include <cuda_runtime.h>
#include <cuda_fp16.h>
#include <math.h>
#include <stdint.h>

// Problem dims (fixed)
#define Bq 2
#define Tt 2048
#define Mm 1024
#define Hh 8
#define Dd 128
#define BT (Bq*Tt)      // 4096
#define HD (Hh*Dd)      // 1024

// Scratch — no cudaMalloc allowed
__device__ __half g_xh[BT*Mm];         // fp16 x
__device__ __half g_wqt[Mm*HD];        // fp16 wq^T [N][K]
__device__ __half g_wkt[Mm*HD];
__device__ __half g_wvt[Mm*HD];
__device__ __half g_wot[HD*Mm];        // fp16 wo^T [N=Mm][K=HD]
__device__ __half g_qn[BT*HD];         // fp16 q proj [b,t,h,d]
__device__ __half g_kn[BT*HD];
__device__ __half g_vn[BT*HD];
__device__ __half g_qh[BT*HD];         // fp16 q (normed/roped) [b,h,t,d]
__device__ __half g_kh[BT*HD];         // fp16 k [b,h,t,d]
__device__ __half g_vt[BT*HD];         // fp16 v transposed [b,h,d,t]
__device__ __half g_oh[BT*HD];         // fp16 attention out [b,t,h,d]

__device__ __forceinline__ void mma_f16(float c[4], uint32_t a0, uint32_t a1,
                                        uint32_t a2, uint32_t a3,
                                        uint32_t b0, uint32_t b1) {
    asm volatile(
        "mma.sync.aligned.m16n8k16.row.col.f32.f16.f16.f32 "
        "{%0,%1,%2,%3}, {%4,%5,%6,%7}, {%8,%9}, {%0,%1,%2,%3};\n"
        : "+f"(c[0]), "+f"(c[1]), "+f"(c[2]), "+f"(c[3])
        : "r"(a0), "r"(a1), "r"(a2), "r"(a3), "r"(b0), "r"(b1));
}

__device__ __forceinline__ void ldsm4(uint32_t& r0, uint32_t& r1,
                                      uint32_t& r2, uint32_t& r3, uint32_t addr) {
    asm volatile("ldmatrix.sync.aligned.m8n8.x4.shared.b16 {%0,%1,%2,%3}, [%4];"
                 : "=r"(r0), "=r"(r1), "=r"(r2), "=r"(r3) : "r"(addr));
}

__device__ __forceinline__ uint32_t packh2(float lo, float hi) {
    __half2 h = __floats2half2_rn(lo, hi);
    return *(uint32_t*)&h;
}

__device__ __forceinline__ void cp16(uint32_t dst, const void* src) {
    asm volatile("cp.async.ca.shared.global [%0], [%1], 16;\n" :: "r"(dst), "l"(src));
}
#define CP_COMMIT() asm volatile("cp.async.commit_group;\n" ::: "memory")
#define CP_WAIT(n)  asm volatile("cp.async.wait_group %0;\n" :: "n"(n) : "memory")

// ---------------------------------------------------------------------------
__global__ __launch_bounds__(256) void f2h(const float* __restrict__ src,
                                           __half* __restrict__ dst, int n4) {
    int i = blockIdx.x * blockDim.x + threadIdx.x;
    if (i < n4) {
        float4 v = ((const float4*)src)[i];
        ((uint2*)dst)[i] = make_uint2(packh2(v.x, v.y), packh2(v.z, v.w));
    }
}

// ---------------------------------------------------------------------------
// Weight transpose + fp16: w [1024][1024] fp32 -> wt fp16 (w^T). z: which.
// ---------------------------------------------------------------------------
__global__ __launch_bounds__(256) void wtrans(const float* __restrict__ w0,
                                              const float* __restrict__ w1,
                                              const float* __restrict__ w2,
                                              const float* __restrict__ w3,
                                              __half* __restrict__ o0,
                                              __half* __restrict__ o1,
                                              __half* __restrict__ o2,
                                              __half* __restrict__ o3) {
    const float* w = (blockIdx.z == 0) ? w0 : (blockIdx.z == 1) ? w1
                     : (blockIdx.z == 2) ? w2 : w3;
    __half* o = (blockIdx.z == 0) ? o0 : (blockIdx.z == 1) ? o1
                : (blockIdx.z == 2) ? o2 : o3;
    __shared__ __half tile[32][33];
    const int tx = threadIdx.x, ty = threadIdx.y;
    const int k0 = blockIdx.x * 32, n0 = blockIdx.y * 32;
#pragma unroll
    for (int i = 0; i < 4; i++)
        tile[ty + i * 8][tx] = __float2half_rn(w[(size_t)(k0 + ty + i * 8) * 1024 + n0 + tx]);
    __syncthreads();
#pragma unroll
    for (int i = 0; i < 4; i++)
        o[(size_t)(n0 + ty + i * 8) * 1024 + k0 + tx] = tile[tx][ty + i * 8];
}

// ---------------------------------------------------------------------------
// FP16 GEMM (LDSM operands): C = A[M,K] * B^T[N,K].
// 128x128 CTA tile, BK=32, 256 threads (8 warps, 32x64 warp tiles).
// ---------------------------------------------------------------------------
#define HGSTR 20

__global__ __launch_bounds__(256, 2) void gemm_h(const __half* __restrict__ A,
                                                 const __half* __restrict__ B0,
                                                 const __half* __restrict__ B1,
                                                 const __half* __restrict__ B2,
                                                 float* __restrict__ Cf0,
                                                 float* __restrict__ Cf1,
                                                 float* __restrict__ Cf2,
                                                 __half* __restrict__ Ch0,
                                                 __half* __restrict__ Ch1,
                                                 __half* __restrict__ Ch2,
                                                 int M, int N, int K, int halfOut) {
    const __half* Bt = (blockIdx.z == 0) ? B0 : (blockIdx.z == 1) ? B1 : B2;
    float* Cf = (blockIdx.z == 0) ? Cf0 : (blockIdx.z == 1) ? Cf1 : Cf2;
    __half* Ch = (blockIdx.z == 0) ? Ch0 : (blockIdx.z == 1) ? Ch1 : Ch2;

    __shared__ uint32_t As[2][128 * HGSTR];
    __shared__ uint32_t Bs[2][128 * HGSTR];

    const int tid  = threadIdx.x;
    const int lane = tid & 31;
    const int warp = tid >> 5;
    const int gid  = lane >> 2;
    const int tig  = lane & 3;
    const int lm   = lane >> 3;
    const int lr   = lane & 7;
    const int wm   = (warp >> 1) * 32;
    const int wn   = (warp & 1) * 64;
    const int rowBase = blockIdx.y * 128;
    const int colBase = blockIdx.x * 128;

    const __half* Ag = A + (size_t)rowBase * K;
    const __half* Bg = Bt + (size_t)colBase * K;
    const uint32_t sA = (uint32_t)__cvta_generic_to_shared(&As[0][0]);
    const uint32_t sB = (uint32_t)__cvta_generic_to_shared(&Bs[0][0]);

    float acc[2][8][4];
#pragma unroll
    for (int mt = 0; mt < 2; mt++)
#pragma unroll
        for (int nt = 0; nt < 8; nt++)
#pragma unroll
            for (int i = 0; i < 4; i++) acc[mt][nt][i] = 0.f;

    {
#pragma unroll
        for (int i = 0; i < 2; i++) {
            const int s = tid + i * 256;
            const int r = s >> 2, c = s & 3;
            cp16(sA + (r * HGSTR + c * 4) * 4, Ag + (size_t)r * K + c * 8);
            cp16(sB + (r * HGSTR + c * 4) * 4, Bg + (size_t)r * K + c * 8);
        }
        CP_COMMIT();
    }

    const int niter = K >> 5;
    for (int it = 0; it < niter; it++) {
        const int cur = it & 1;
        if (it + 1 < niter) {
            const int k0 = (it + 1) << 5;
            const int nxt = (it + 1) & 1;
#pragma unroll
            for (int i = 0; i < 2; i++) {
                const int s = tid + i * 256;
                const int r = s >> 2, c = s & 3;
                cp16(sA + (nxt * 128 * HGSTR + r * HGSTR + c * 4) * 4,
                     Ag + (size_t)r * K + k0 + c * 8);
                cp16(sB + (nxt * 128 * HGSTR + r * HGSTR + c * 4) * 4,
                     Bg + (size_t)r * K + k0 + c * 8);
            }
            CP_COMMIT();
            CP_WAIT(1);
        } else {
            CP_WAIT(0);
        }
        __syncthreads();

        const uint32_t sAc = sA + cur * 128 * HGSTR * 4;
        const uint32_t sBc = sB + cur * 128 * HGSTR * 4;
#pragma unroll
        for (int kh = 0; kh < 2; kh++) {
            const int kk = kh * 8;
            uint32_t af[2][4];
#pragma unroll
            for (int mt = 0; mt < 2; mt++) {
                const int row = wm + mt * 16 + (lm & 1) * 8 + lr;
                const int word = kk + (lm >> 1) * 4;
                ldsm4(af[mt][0], af[mt][1], af[mt][2], af[mt][3],
                      sAc + (row * HGSTR + word) * 4);
            }
#pragma unroll
            for (int np = 0; np < 4; np++) {
                const int row = wn + (2 * np + (lm >> 1)) * 8 + lr;
                const int word = kk + (lm & 1) * 4;
                uint32_t b00, b01, b10, b11;
                ldsm4(b00, b01, b10, b11, sBc + (row * HGSTR + word) * 4);
#pragma unroll
                for (int mt = 0; mt < 2; mt++) {
                    mma_f16(acc[mt][2 * np],     af[mt][0], af[mt][1], af[mt][2], af[mt][3], b00, b01);
                    mma_f16(acc[mt][2 * np + 1], af[mt][0], af[mt][1], af[mt][2], af[mt][3], b10, b11);
                }
            }
        }
        __syncthreads();
    }

#pragma unroll
    for (int mt = 0; mt < 2; mt++) {
#pragma unroll
        for (int nt = 0; nt < 8; nt++) {
            const int r0 = rowBase + wm + mt * 16 + gid;
            const int c0 = colBase + wn + nt * 8 + 2 * tig;
            if (halfOut) {
                *(uint32_t*)(Ch + (size_t)r0 * N + c0)       = packh2(acc[mt][nt][0], acc[mt][nt][1]);
                *(uint32_t*)(Ch + (size_t)(r0 + 8) * N + c0) = packh2(acc[mt][nt][2], acc[mt][nt][3]);
            } else {
                *(float2*)(Cf + (size_t)r0 * N + c0)       = make_float2(acc[mt][nt][0], acc[mt][nt][1]);
                *(float2*)(Cf + (size_t)(r0 + 8) * N + c0) = make_float2(acc[mt][nt][2], acc[mt][nt][3]);
            }
        }
    }
}

// ---------------------------------------------------------------------------
// RMSNorm + RoPE + fold sqrt(1/128); fp16 [b,t,h,d] in -> fp16 [b,h,t,d] out.
// Fast-math: exp2f for the rotary frequency, __sincosf (HW RRO reduction).
// ---------------------------------------------------------------------------
__global__ __launch_bounds__(256) void normrope_h(const __half* __restrict__ q,
                                                  const __half* __restrict__ k,
                                                  __half* __restrict__ qh,
                                                  __half* __restrict__ kh) {
    int gwarp = (blockIdx.x * blockDim.x + threadIdx.x) >> 5;
    int lane  = threadIdx.x & 31;
    const int nrows = BT * Hh;
    const __half* src = (gwarp < nrows) ? q : k;
    __half* dst = (gwarp < nrows) ? qh : kh;
    int row = (gwarp < nrows) ? gwarp : gwarp - nrows;
    int bt = row >> 3;
    int h  = row & 7;
    int t  = bt & (Tt - 1);
    int b  = bt >> 11;

    const __half* p = src + (size_t)bt * HD + h * Dd;
    float e0 = __half2float(p[lane]),      e1 = __half2float(p[lane + 32]);
    float o0 = __half2float(p[lane + 64]), o1 = __half2float(p[lane + 96]);

    float ss = e0 * e0 + e1 * e1 + o0 * o0 + o1 * o1;
#pragma unroll
    for (int off = 16; off; off >>= 1) ss += __shfl_xor_sync(0xffffffffu, ss, off);

    float scale = rsqrtf(ss * (1.0f / 128.0f) + 1e-6f) * 0.08838834764831845f;
    e0 *= scale; e1 *= scale; o0 *= scale; o1 *= scale;

    // freq = 10000^(-i/64) = 2^(-i * log2(10000)/64)
    const float c64 = -0.20762050593017578f;   // -log2(10000)/64
    float f0 = exp2f((float)lane * c64);
    float f1 = exp2f((float)(lane + 32) * c64);
    float r0 = (float)t * f0, r1 = (float)t * f1;
    float s0, c0, s1, c1;
    __sincosf(r0, &s0, &c0);
    __sincosf(r1, &s1, &c1);

    __half* op = dst + (((size_t)(b * Hh + h)) * Tt + t) * Dd;
    op[lane]      = __float2half_rn(e0 * c0 - o0 * s0);
    op[lane + 32] = __float2half_rn(e1 * c1 - o1 * s1);
    op[lane + 64] = __float2half_rn(e0 * s0 + o0 * c0);
    op[lane + 96] = __float2half_rn(e1 * s1 + o1 * c1);
}

// ---------------------------------------------------------------------------
// V transpose: g_vn [b,t,h,d] fp16 -> g_vt [b,h,d,t] fp16.
// ---------------------------------------------------------------------------
__global__ __launch_bounds__(256) void vtrans(const __half* __restrict__ v,
                                              __half* __restrict__ vt) {
    __shared__ __half tile[32][33];
    const int tx = threadIdx.x, ty = threadIdx.y;
    const int t0 = blockIdx.x * 32;
    const int d0 = blockIdx.y * 32;
    const int bh = blockIdx.z;
    const int b = bh >> 3, h = bh & 7;

    const __half* in = v + ((size_t)b * Tt) * HD + h * Dd;
#pragma unroll
    for (int i = 0; i < 4; i++) {
        int t = t0 + ty + i * 8;
        tile[ty + i * 8][tx] = in[(size_t)t * HD + d0 + tx];
    }
    __syncthreads();

    __half* out = vt + ((size_t)bh * Dd) * Tt;
#pragma unroll
    for (int i = 0; i < 4; i++) {
        int d = d0 + ty + i * 8;
        out[(size_t)d * Tt + t0 + tx] = tile[tx][ty + i * 8];
    }
}

// ---------------------------------------------------------------------------
// FP16 flash attention (causal), LDSM operands: BR=64 (4 warps), BC=64.
// __launch_bounds__(128, 3): cap regs at 170 -> 3 CTAs/SM (215 KB smem of 228).
// ---------------------------------------------------------------------------
#define BRt 64
#define BCt 64
#define HKSTR 68
#define HVSTR 36
#define HOFF_K0 0
#define HOFF_V0 (HOFF_K0 + 64*HKSTR)    // 4352
#define HOFF_K1 (HOFF_V0 + 128*HVSTR)   // 8960
#define HOFF_V1 (HOFF_K1 + 64*HKSTR)    // 13312
#define HSM_WORDS (HOFF_V1 + 128*HVSTR) // 17920 words = 71680 B

__global__ __launch_bounds__(128, 3) void attn_h(const __half* __restrict__ qh,
                                                 const __half* __restrict__ kh,
                                                 const __half* __restrict__ vt,
                                                 __half* __restrict__ oh) {
    extern __shared__ uint32_t smu[];

    const int tid  = threadIdx.x;
    const int lane = tid & 31;
    const int warp = tid >> 5;
    const int gid  = lane >> 2;
    const int tig  = lane & 3;
    const int lm   = lane >> 3;
    const int lr   = lane & 7;
    const int qb = (gridDim.x - 1) - blockIdx.x;   // heavy blocks first
    const int h = blockIdx.y, b = blockIdx.z;
    const int t0 = qb * BRt;
    const int wrow = warp * 16;

    const size_t bhOff = (size_t)(b * Hh + h) * Tt * Dd;
    const __half* qbase = qh + bhOff + (size_t)t0 * Dd;
    const __half* kbase = kh + bhOff;
    const __half* vbase = vt + bhOff;              // [d][t]
    const uint32_t smemBase = (uint32_t)__cvta_generic_to_shared(smu);

    const int bRowSel = lm >> 1;
    const int bKSel   = lm & 1;

    {
#pragma unroll
        for (int i = 0; i < 8; i++) {
            const int s = tid + i * 128;
            const int r = s >> 4, c = s & 15;
            cp16(smemBase + (HOFF_K0 + r * HKSTR + c * 4) * 4,
                 kbase + (size_t)r * Dd + c * 8);
        }
#pragma unroll
        for (int i = 0; i < 8; i++) {
            const int s = tid + i * 128;
            const int r = s >> 3, c = s & 7;
            cp16(smemBase + (HOFF_V0 + r * HVSTR + c * 4) * 4,
                 vbase + (size_t)r * Tt + c * 8);
        }
        CP_COMMIT();
    }
    {
#pragma unroll
        for (int i = 0; i < 8; i++) {
            const int s = tid + i * 128;
            const int r = s >> 4, c = s & 15;
            cp16(smemBase + (HOFF_K1 + r * HKSTR + c * 4) * 4,
                 qbase + (size_t)r * Dd + c * 8);
        }
        CP_COMMIT();
        CP_WAIT(0);
    }
    __syncthreads();

    uint32_t qf[8][4];
    {
        const uint32_t qRow = wrow + (lm & 1) * 8 + lr;
        const uint32_t qWordSel = (lm >> 1) * 4;
#pragma unroll
        for (int ks = 0; ks < 8; ks++) {
            ldsm4(qf[ks][0], qf[ks][1], qf[ks][2], qf[ks][3],
                  smemBase + (HOFF_K1 + qRow * HKSTR + 8 * ks + qWordSel) * 4);
        }
    }
    __syncthreads();

    float m0 = -1e30f, m1 = -1e30f, l0 = 0.f, l1 = 0.f;
    float oacc[16][4];
#pragma unroll
    for (int nt = 0; nt < 16; nt++)
#pragma unroll
        for (int i = 0; i < 4; i++) oacc[nt][i] = 0.f;

    for (int kb = 0; kb <= qb; kb++) {
        if (kb + 1 <= qb) {
            const int tk0 = (kb + 1) * BCt;
            const int offK = ((kb + 1) & 1) ? HOFF_K1 : HOFF_K0;
            const int offV = ((kb + 1) & 1) ? HOFF_V1 : HOFF_V0;
#pragma unroll
            for (int i = 0; i < 8; i++) {
                const int s = tid + i * 128;
                const int r = s >> 4, c = s & 15;
                cp16(smemBase + (offK + r * HKSTR + c * 4) * 4,
                     kbase + (size_t)(tk0 + r) * Dd + c * 8);
            }
#pragma unroll
            for (int i = 0; i < 8; i++) {
                const int s = tid + i * 128;
                const int r = s >> 3, c = s & 7;
                cp16(smemBase + (offV + r * HVSTR + c * 4) * 4,
                     vbase + (size_t)r * Tt + tk0 + c * 8);
            }
            CP_COMMIT();
            CP_WAIT(1);
        } else {
            CP_WAIT(0);
        }
        __syncthreads();

        const uint32_t offK = (kb & 1) ? HOFF_K1 : HOFF_K0;
        const uint32_t offV = (kb & 1) ? HOFF_V1 : HOFF_V0;
        const int tk0 = kb * BCt;

        float sacc[8][4];
#pragma unroll
        for (int nt = 0; nt < 8; nt++)
#pragma unroll
            for (int i = 0; i < 4; i++) sacc[nt][i] = 0.f;

        const uint32_t kAddr0 = smemBase + (offK + ((bRowSel * 8 + lr) * HKSTR) + bKSel * 4) * 4;
#pragma unroll
        for (int ks = 0; ks < 8; ks++) {
#pragma unroll
            for (int np = 0; np < 4; np++) {
                uint32_t b00, b01, b10, b11;
                ldsm4(b00, b01, b10, b11,
                      kAddr0 + ((2 * np) * 8 * HKSTR + 8 * ks) * 4);
                mma_f16(sacc[2 * np],     qf[ks][0], qf[ks][1], qf[ks][2], qf[ks][3], b00, b01);
                mma_f16(sacc[2 * np + 1], qf[ks][0], qf[ks][1], qf[ks][2], qf[ks][3], b10, b11);
            }
        }

        if (kb == qb) {
            const int rg0 = t0 + wrow + gid;
            const int rg1 = rg0 + 8;
#pragma unroll
            for (int nt = 0; nt < 8; nt++) {
                const int cg = tk0 + nt * 8 + 2 * tig;
                if (rg0 < cg)     sacc[nt][0] = -1e30f;
                if (rg0 < cg + 1) sacc[nt][1] = -1e30f;
                if (rg1 < cg)     sacc[nt][2] = -1e30f;
                if (rg1 < cg + 1) sacc[nt][3] = -1e30f;
            }
        }

        float rm0 = -1e30f, rm1 = -1e30f;
#pragma unroll
        for (int nt = 0; nt < 8; nt++) {
            rm0 = fmaxf(rm0, fmaxf(sacc[nt][0], sacc[nt][1]));
            rm1 = fmaxf(rm1, fmaxf(sacc[nt][2], sacc[nt][3]));
        }
        rm0 = fmaxf(rm0, __shfl_xor_sync(0xffffffffu, rm0, 1));
        rm0 = fmaxf(rm0, __shfl_xor_sync(0xffffffffu, rm0, 2));
        rm1 = fmaxf(rm1, __shfl_xor_sync(0xffffffffu, rm1, 1));
        rm1 = fmaxf(rm1, __shfl_xor_sync(0xffffffffu, rm1, 2));

        const float nm0 = fmaxf(m0, rm0);
        const float nm1 = fmaxf(m1, rm1);
        float sum0 = 0.f, sum1 = 0.f;
        uint32_t pe[8][2];
#pragma unroll
        for (int nt = 0; nt < 8; nt++) {
            float e00 = __expf(sacc[nt][0] - nm0);
            float e01 = __expf(sacc[nt][1] - nm0);
            float e10 = __expf(sacc[nt][2] - nm1);
            float e11 = __expf(sacc[nt][3] - nm1);
            sum0 += e00 + e01;
            sum1 += e10 + e11;
            pe[nt][0] = packh2(e00, e01);
            pe[nt][1] = packh2(e10, e11);
        }
        sum0 += __shfl_xor_sync(0xffffffffu, sum0, 1);
        sum0 += __shfl_xor_sync(0xffffffffu, sum0, 2);
        sum1 += __shfl_xor_sync(0xffffffffu, sum1, 1);
        sum1 += __shfl_xor_sync(0xffffffffu, sum1, 2);

        const float c0 = __expf(m0 - nm0);
        const float c1 = __expf(m1 - nm1);
        l0 = l0 * c0 + sum0; m0 = nm0;
        l1 = l1 * c1 + sum1; m1 = nm1;
#pragma unroll
        for (int nt = 0; nt < 16; nt++) {
            oacc[nt][0] *= c0; oacc[nt][1] *= c0;
            oacc[nt][2] *= c1; oacc[nt][3] *= c1;
        }

        const uint32_t vAddr0 = smemBase + (offV + ((bRowSel * 8 + lr) * HVSTR) + bKSel * 4) * 4;
#pragma unroll
        for (int ks = 0; ks < 4; ks++) {
            const uint32_t a0 = pe[2 * ks][0];
            const uint32_t a1 = pe[2 * ks][1];
            const uint32_t a2 = pe[2 * ks + 1][0];
            const uint32_t a3 = pe[2 * ks + 1][1];
#pragma unroll
            for (int np = 0; np < 8; np++) {
                uint32_t b00, b01, b10, b11;
                ldsm4(b00, b01, b10, b11,
                      vAddr0 + ((2 * np) * 8 * HVSTR + 8 * ks) * 4);
                mma_f16(oacc[2 * np],     a0, a1, a2, a3, b00, b01);
                mma_f16(oacc[2 * np + 1], a0, a1, a2, a3, b10, b11);
            }
        }
        __syncthreads();
    }

    const float i0 = 1.0f / l0;
    const float i1 = 1.0f / l1;
    const int rg0 = t0 + wrow + gid;
    __half* ob0 = oh + ((size_t)(b * Tt + rg0) * Hh + h) * Dd;
    __half* ob1 = oh + ((size_t)(b * Tt + rg0 + 8) * Hh + h) * Dd;
#pragma unroll
    for (int nt = 0; nt < 16; nt++) {
        const int col = nt * 8 + 2 * tig;
        *(uint32_t*)(ob0 + col) = packh2(oacc[nt][0] * i0, oacc[nt][1] * i0);
        *(uint32_t*)(ob1 + col) = packh2(oacc[nt][2] * i1, oacc[nt][3] * i1);
    }
}

// ---------------------------------------------------------------------------
extern "C" void kernel_launch(void* const* d_in, const int* in_sizes, int n_in,
                              void* d_out, int out_size) {
    const float* x  = (const float*)d_in[0];
    const float* wq = (const float*)d_in[1];
    const float* wk = (const float*)d_in[2];
    const float* wv = (const float*)d_in[3];
    const float* wo = (const float*)d_in[4];
    float* out = (float*)d_out;

    __half *xh, *wqt, *wkt, *wvt, *wot, *qn, *kn, *vn, *qhp, *khp, *vtp, *ohp;
    cudaGetSymbolAddress((void**)&xh, g_xh);
    cudaGetSymbolAddress((void**)&wqt, g_wqt);
    cudaGetSymbolAddress((void**)&wkt, g_wkt);
    cudaGetSymbolAddress((void**)&wvt, g_wvt);
    cudaGetSymbolAddress((void**)&wot, g_wot);
    cudaGetSymbolAddress((void**)&qn, g_qn);
    cudaGetSymbolAddress((void**)&kn, g_kn);
    cudaGetSymbolAddress((void**)&vn, g_vn);
    cudaGetSymbolAddress((void**)&qhp, g_qh);
    cudaGetSymbolAddress((void**)&khp, g_kh);
    cudaGetSymbolAddress((void**)&vtp, g_vt);
    cudaGetSymbolAddress((void**)&ohp, g_oh);

    // Convert x; transpose+convert all four weights
    f2h<<<(BT*Mm/4 + 255)/256, 256>>>(x, xh, BT*Mm/4);
    wtrans<<<dim3(32, 32, 4), dim3(32, 8)>>>(wq, wk, wv, wo, wqt, wkt, wvt, wot);

    // Fused QKV projections -> fp16 [b,t,h,d]
    dim3 gp(HD / 128, BT / 128, 3);
    gemm_h<<<gp, 256>>>(xh, wqt, wkt, wvt,
                        nullptr, nullptr, nullptr, qn, kn, vn, BT, HD, Mm, 1);

    // RMSNorm + RoPE -> fp16 q,k in [b,h,t,d]
    int totalWarps = 2 * BT * Hh;
    normrope_h<<<totalWarps / 8, 256>>>(qn, kn, qhp, khp);

    // V -> fp16 transposed [b,h,d,t]
    dim3 gv(Tt / 32, Dd / 32, Bq * Hh);
    vtrans<<<gv, dim3(32, 8)>>>(vn, vtp);

    // FP16 flash attention -> fp16 O [b,t,h,d]
    size_t smem = (size_t)HSM_WORDS * 4;
    cudaFuncSetAttribute(attn_h, cudaFuncAttributeMaxDynamicSharedMemorySize, (int)smem);
    dim3 ga(Tt / BRt, Hh, Bq);
    attn_h<<<ga, 128, smem>>>(qhp, khp, vtp, ohp);

    // Output projection -> fp32 out
    dim3 go(Mm / 128, BT / 128, 1);
    gemm_h<<<go, 256>>>(ohp, wot, wot, wot,
                        out, out, out, nullptr, nullptr, nullptr, BT, Mm, HD, 0);
}

// round 11
// speedup vs baseline: 12.1468x; 1.0347x over previous
#include <cuda_runtime.h>
#include <cuda_fp16.h>
#include <math.h>
#include <stdint.h>

// Problem dims (fixed)
#define Bq 2
#define Tt 2048
#define Mm 1024
#define Hh 8
#define Dd 128
#define BT (Bq*Tt)      // 4096
#define HD (Hh*Dd)      // 1024

// Scratch — no cudaMalloc allowed
__device__ __half g_xh[BT*Mm];         // fp16 x
__device__ __half g_wqt[Mm*HD];        // fp16 wq^T [N][K]
__device__ __half g_wkt[Mm*HD];
__device__ __half g_wvt[Mm*HD];
__device__ __half g_wot[HD*Mm];        // fp16 wo^T [N=Mm][K=HD]
__device__ __half g_qh[BT*HD];         // fp16 q (normed/roped) [b,h,t,d]
__device__ __half g_kh[BT*HD];         // fp16 k [b,h,t,d]
__device__ __half g_vt[BT*HD];         // fp16 v transposed [b,h,d,t]
__device__ __half g_oh[BT*HD];         // fp16 attention out [b,t,h,d]

__device__ __forceinline__ void mma_f16(float c[4], uint32_t a0, uint32_t a1,
                                        uint32_t a2, uint32_t a3,
                                        uint32_t b0, uint32_t b1) {
    asm volatile(
        "mma.sync.aligned.m16n8k16.row.col.f32.f16.f16.f32 "
        "{%0,%1,%2,%3}, {%4,%5,%6,%7}, {%8,%9}, {%0,%1,%2,%3};\n"
        : "+f"(c[0]), "+f"(c[1]), "+f"(c[2]), "+f"(c[3])
        : "r"(a0), "r"(a1), "r"(a2), "r"(a3), "r"(b0), "r"(b1));
}

__device__ __forceinline__ void ldsm4(uint32_t& r0, uint32_t& r1,
                                      uint32_t& r2, uint32_t& r3, uint32_t addr) {
    asm volatile("ldmatrix.sync.aligned.m8n8.x4.shared.b16 {%0,%1,%2,%3}, [%4];"
                 : "=r"(r0), "=r"(r1), "=r"(r2), "=r"(r3) : "r"(addr));
}

__device__ __forceinline__ uint32_t packh2(float lo, float hi) {
    __half2 h = __floats2half2_rn(lo, hi);
    return *(uint32_t*)&h;
}

__device__ __forceinline__ void cp16(uint32_t dst, const void* src) {
    asm volatile("cp.async.ca.shared.global [%0], [%1], 16;\n" :: "r"(dst), "l"(src));
}
#define CP_COMMIT() asm volatile("cp.async.commit_group;\n" ::: "memory")
#define CP_WAIT(n)  asm volatile("cp.async.wait_group %0;\n" :: "n"(n) : "memory")

// ---------------------------------------------------------------------------
__global__ __launch_bounds__(256) void f2h(const float* __restrict__ src,
                                           __half* __restrict__ dst, int n4) {
    int i = blockIdx.x * blockDim.x + threadIdx.x;
    if (i < n4) {
        float4 v = ((const float4*)src)[i];
        ((uint2*)dst)[i] = make_uint2(packh2(v.x, v.y), packh2(v.z, v.w));
    }
}

// ---------------------------------------------------------------------------
// Weight transpose + fp16: w [1024][1024] fp32 -> wt fp16 (w^T). z: which.
// ---------------------------------------------------------------------------
__global__ __launch_bounds__(256) void wtrans(const float* __restrict__ w0,
                                              const float* __restrict__ w1,
                                              const float* __restrict__ w2,
                                              const float* __restrict__ w3,
                                              __half* __restrict__ o0,
                                              __half* __restrict__ o1,
                                              __half* __restrict__ o2,
                                              __half* __restrict__ o3) {
    const float* w = (blockIdx.z == 0) ? w0 : (blockIdx.z == 1) ? w1
                     : (blockIdx.z == 2) ? w2 : w3;
    __half* o = (blockIdx.z == 0) ? o0 : (blockIdx.z == 1) ? o1
                : (blockIdx.z == 2) ? o2 : o3;
    __shared__ __half tile[32][33];
    const int tx = threadIdx.x, ty = threadIdx.y;
    const int k0 = blockIdx.x * 32, n0 = blockIdx.y * 32;
#pragma unroll
    for (int i = 0; i < 4; i++)
        tile[ty + i * 8][tx] = __float2half_rn(w[(size_t)(k0 + ty + i * 8) * 1024 + n0 + tx]);
    __syncthreads();
#pragma unroll
    for (int i = 0; i < 4; i++)
        o[(size_t)(n0 + ty + i * 8) * 1024 + k0 + tx] = tile[tx][ty + i * 8];
}

// ---------------------------------------------------------------------------
// Fused QKV GEMM: [BT,1024]x[1024,1024(head-major)] with per-head epilogue.
// z=0: q -> RMSNorm+RoPE -> g_qh [b,h,t,d]
// z=1: k -> RMSNorm+RoPE -> g_kh [b,h,t,d]
// z=2: v -> transposed scatter -> g_vt [b,h,d,t]
// Each CTA tile = [128 t-rows] x [one head's full 128 d] (colBase = h*128).
// ---------------------------------------------------------------------------
#define HGSTR 20
#define GW (128*HGSTR)   // 2560 words per buffer

__global__ __launch_bounds__(256, 2) void gemm_qkv(const __half* __restrict__ A,
                                                   const __half* __restrict__ B0,
                                                   const __half* __restrict__ B1,
                                                   const __half* __restrict__ B2,
                                                   __half* __restrict__ qh,
                                                   __half* __restrict__ kh,
                                                   __half* __restrict__ vt) {
    const int z = blockIdx.z;
    const __half* Bt = (z == 0) ? B0 : (z == 1) ? B1 : B2;

    __shared__ uint32_t smx[4 * GW];            // As[2] | Bs[2]; aliased by tile
    uint32_t* sAb = smx;                        // As base
    uint32_t* sBb = smx + 2 * GW;               // Bs base
    __half*   tile = (__half*)smx;              // epilogue: [128][136] halfs (8704 words)

    const int tid  = threadIdx.x;
    const int lane = tid & 31;
    const int warp = tid >> 5;
    const int gid  = lane >> 2;
    const int tig  = lane & 3;
    const int lm   = lane >> 3;
    const int lr   = lane & 7;
    const int wm   = (warp >> 1) * 32;
    const int wn   = (warp & 1) * 64;
    const int rowBase = blockIdx.y * 128;
    const int colBase = blockIdx.x * 128;
    const int K = Mm, N = HD;

    const __half* Ag = A + (size_t)rowBase * K;
    const __half* Bg = Bt + (size_t)colBase * K;
    const uint32_t sA = (uint32_t)__cvta_generic_to_shared(sAb);
    const uint32_t sB = (uint32_t)__cvta_generic_to_shared(sBb);

    float acc[2][8][4];
#pragma unroll
    for (int mt = 0; mt < 2; mt++)
#pragma unroll
        for (int nt = 0; nt < 8; nt++)
#pragma unroll
            for (int i = 0; i < 4; i++) acc[mt][nt][i] = 0.f;

    {
#pragma unroll
        for (int i = 0; i < 2; i++) {
            const int s = tid + i * 256;
            const int r = s >> 2, c = s & 3;
            cp16(sA + (r * HGSTR + c * 4) * 4, Ag + (size_t)r * K + c * 8);
            cp16(sB + (r * HGSTR + c * 4) * 4, Bg + (size_t)r * K + c * 8);
        }
        CP_COMMIT();
    }

    const int niter = K >> 5;
    for (int it = 0; it < niter; it++) {
        const int cur = it & 1;
        if (it + 1 < niter) {
            const int k0 = (it + 1) << 5;
            const int nxt = (it + 1) & 1;
#pragma unroll
            for (int i = 0; i < 2; i++) {
                const int s = tid + i * 256;
                const int r = s >> 2, c = s & 3;
                cp16(sA + (nxt * GW + r * HGSTR + c * 4) * 4,
                     Ag + (size_t)r * K + k0 + c * 8);
                cp16(sB + (nxt * GW + r * HGSTR + c * 4) * 4,
                     Bg + (size_t)r * K + k0 + c * 8);
            }
            CP_COMMIT();
            CP_WAIT(1);
        } else {
            CP_WAIT(0);
        }
        __syncthreads();

        const uint32_t sAc = sA + cur * GW * 4;
        const uint32_t sBc = sB + cur * GW * 4;
#pragma unroll
        for (int kh2 = 0; kh2 < 2; kh2++) {
            const int kk = kh2 * 8;
            uint32_t af[2][4];
#pragma unroll
            for (int mt = 0; mt < 2; mt++) {
                const int row = wm + mt * 16 + (lm & 1) * 8 + lr;
                const int word = kk + (lm >> 1) * 4;
                ldsm4(af[mt][0], af[mt][1], af[mt][2], af[mt][3],
                      sAc + (row * HGSTR + word) * 4);
            }
#pragma unroll
            for (int np = 0; np < 4; np++) {
                const int row = wn + (2 * np + (lm >> 1)) * 8 + lr;
                const int word = kk + (lm & 1) * 4;
                uint32_t b00, b01, b10, b11;
                ldsm4(b00, b01, b10, b11, sBc + (row * HGSTR + word) * 4);
#pragma unroll
                for (int mt = 0; mt < 2; mt++) {
                    mma_f16(acc[mt][2 * np],     af[mt][0], af[mt][1], af[mt][2], af[mt][3], b00, b01);
                    mma_f16(acc[mt][2 * np + 1], af[mt][0], af[mt][1], af[mt][2], af[mt][3], b10, b11);
                }
            }
        }
        __syncthreads();
    }

    // ---- epilogue ----
    const int bIdx  = rowBase >> 11;          // rowBase / T
    const int tbase = rowBase & (Tt - 1);
    const int hIdx  = colBase >> 7;           // head

    if (z == 2) {
        // V: direct transposed scatter to [b,h,d,t]
        __half* dst = vt + ((size_t)(bIdx * Hh + hIdx) * Dd) * Tt;
#pragma unroll
        for (int mt = 0; mt < 2; mt++) {
#pragma unroll
            for (int nt = 0; nt < 8; nt++) {
                const int r0 = wm + mt * 16 + gid;
                const int c0 = wn + nt * 8 + 2 * tig;
                const int tg = tbase + r0;
                dst[(size_t)c0 * Tt + tg]           = __float2half_rn(acc[mt][nt][0]);
                dst[(size_t)(c0 + 1) * Tt + tg]     = __float2half_rn(acc[mt][nt][1]);
                dst[(size_t)c0 * Tt + tg + 8]       = __float2half_rn(acc[mt][nt][2]);
                dst[(size_t)(c0 + 1) * Tt + tg + 8] = __float2half_rn(acc[mt][nt][3]);
            }
        }
        return;
    }

    // Q/K: stage fp16 tile in smem (stride 136 halfs = 68 words), then norm+rope
#pragma unroll
    for (int mt = 0; mt < 2; mt++) {
#pragma unroll
        for (int nt = 0; nt < 8; nt++) {
            const int r0 = wm + mt * 16 + gid;
            const int cw = ((wn + nt * 8) >> 1) + tig;   // word within row
            ((uint32_t*)tile)[r0 * 68 + cw]       = packh2(acc[mt][nt][0], acc[mt][nt][1]);
            ((uint32_t*)tile)[(r0 + 8) * 68 + cw] = packh2(acc[mt][nt][2], acc[mt][nt][3]);
        }
    }
    __syncthreads();

    // 2 lanes per row: row = 16*warp + (lane>>1); halfSel selects d-subset
    const int row = warp * 16 + (lane >> 1);
    const int halfSel = lane & 1;
    const int d0 = halfSel * 32;               // pairs (d0+j, d0+j+64), j 0..31
    const __half* trow = tile + row * 136;

    // pass 1: sum of squares over this lane's 64 values
    float ssq = 0.f;
#pragma unroll
    for (int j = 0; j < 32; j += 8) {
        uint4 eu = *(const uint4*)(trow + d0 + j);
        uint4 ou = *(const uint4*)(trow + d0 + 64 + j);
        const uint32_t* ew = (const uint32_t*)&eu;
        const uint32_t* ow = (const uint32_t*)&ou;
#pragma unroll
        for (int w2 = 0; w2 < 4; w2++) {
            float2 e2 = __half22float2(*(const __half2*)&ew[w2]);
            float2 o2 = __half22float2(*(const __half2*)&ow[w2]);
            ssq += e2.x * e2.x + e2.y * e2.y + o2.x * o2.x + o2.y * o2.y;
        }
    }
    ssq += __shfl_xor_sync(0xffffffffu, ssq, 1);

    const float scale = rsqrtf(ssq * (1.0f / 128.0f) + 1e-6f) * 0.08838834764831845f;
    const int tg = tbase + row;
    const float c64 = -0.20762050593017578f;   // -log2(10000)/64
    __half* dst = ((z == 0) ? qh : kh) + ((size_t)(bIdx * Hh + hIdx) * Tt + tg) * Dd;

    // pass 2: rope + store
#pragma unroll
    for (int j = 0; j < 32; j += 8) {
        uint4 eu = *(const uint4*)(trow + d0 + j);
        uint4 ou = *(const uint4*)(trow + d0 + 64 + j);
        const uint32_t* ew = (const uint32_t*)&eu;
        const uint32_t* ow = (const uint32_t*)&ou;
        uint32_t outE[4], outO[4];
#pragma unroll
        for (int w2 = 0; w2 < 4; w2++) {
            float2 e2 = __half22float2(*(const __half2*)&ew[w2]);
            float2 o2 = __half22float2(*(const __half2*)&ow[w2]);
            float re[2], ro[2];
#pragma unroll
            for (int u = 0; u < 2; u++) {
                const int i = d0 + j + w2 * 2 + u;
                float f = exp2f((float)i * c64);
                float sn, cs;
                __sincosf((float)tg * f, &sn, &cs);
                float ev = (u ? e2.y : e2.x) * scale;
                float ov = (u ? o2.y : o2.x) * scale;
                re[u] = ev * cs - ov * sn;
                ro[u] = ev * sn + ov * cs;
            }
            outE[w2] = packh2(re[0], re[1]);
            outO[w2] = packh2(ro[0], ro[1]);
        }
        *(uint4*)(dst + d0 + j)      = *(uint4*)outE;
        *(uint4*)(dst + d0 + 64 + j) = *(uint4*)outO;
    }
}

// ---------------------------------------------------------------------------
// FP16 GEMM for out-projection: C(fp32)[M,N] = A[M,K] * B^T[N,K].
// ---------------------------------------------------------------------------
__global__ __launch_bounds__(256, 2) void gemm_h(const __half* __restrict__ A,
                                                 const __half* __restrict__ Bt,
                                                 float* __restrict__ C,
                                                 int M, int N, int K) {
    __shared__ uint32_t As[2][GW];
    __shared__ uint32_t Bs[2][GW];

    const int tid  = threadIdx.x;
    const int lane = tid & 31;
    const int warp = tid >> 5;
    const int gid  = lane >> 2;
    const int tig  = lane & 3;
    const int lm   = lane >> 3;
    const int lr   = lane & 7;
    const int wm   = (warp >> 1) * 32;
    const int wn   = (warp & 1) * 64;
    const int rowBase = blockIdx.y * 128;
    const int colBase = blockIdx.x * 128;

    const __half* Ag = A + (size_t)rowBase * K;
    const __half* Bg = Bt + (size_t)colBase * K;
    const uint32_t sA = (uint32_t)__cvta_generic_to_shared(&As[0][0]);
    const uint32_t sB = (uint32_t)__cvta_generic_to_shared(&Bs[0][0]);

    float acc[2][8][4];
#pragma unroll
    for (int mt = 0; mt < 2; mt++)
#pragma unroll
        for (int nt = 0; nt < 8; nt++)
#pragma unroll
            for (int i = 0; i < 4; i++) acc[mt][nt][i] = 0.f;

    {
#pragma unroll
        for (int i = 0; i < 2; i++) {
            const int s = tid + i * 256;
            const int r = s >> 2, c = s & 3;
            cp16(sA + (r * HGSTR + c * 4) * 4, Ag + (size_t)r * K + c * 8);
            cp16(sB + (r * HGSTR + c * 4) * 4, Bg + (size_t)r * K + c * 8);
        }
        CP_COMMIT();
    }

    const int niter = K >> 5;
    for (int it = 0; it < niter; it++) {
        const int cur = it & 1;
        if (it + 1 < niter) {
            const int k0 = (it + 1) << 5;
            const int nxt = (it + 1) & 1;
#pragma unroll
            for (int i = 0; i < 2; i++) {
                const int s = tid + i * 256;
                const int r = s >> 2, c = s & 3;
                cp16(sA + (nxt * GW + r * HGSTR + c * 4) * 4,
                     Ag + (size_t)r * K + k0 + c * 8);
                cp16(sB + (nxt * GW + r * HGSTR + c * 4) * 4,
                     Bg + (size_t)r * K + k0 + c * 8);
            }
            CP_COMMIT();
            CP_WAIT(1);
        } else {
            CP_WAIT(0);
        }
        __syncthreads();

        const uint32_t sAc = sA + cur * GW * 4;
        const uint32_t sBc = sB + cur * GW * 4;
#pragma unroll
        for (int kh2 = 0; kh2 < 2; kh2++) {
            const int kk = kh2 * 8;
            uint32_t af[2][4];
#pragma unroll
            for (int mt = 0; mt < 2; mt++) {
                const int row = wm + mt * 16 + (lm & 1) * 8 + lr;
                const int word = kk + (lm >> 1) * 4;
                ldsm4(af[mt][0], af[mt][1], af[mt][2], af[mt][3],
                      sAc + (row * HGSTR + word) * 4);
            }
#pragma unroll
            for (int np = 0; np < 4; np++) {
                const int row = wn + (2 * np + (lm >> 1)) * 8 + lr;
                const int word = kk + (lm & 1) * 4;
                uint32_t b00, b01, b10, b11;
                ldsm4(b00, b01, b10, b11, sBc + (row * HGSTR + word) * 4);
#pragma unroll
                for (int mt = 0; mt < 2; mt++) {
                    mma_f16(acc[mt][2 * np],     af[mt][0], af[mt][1], af[mt][2], af[mt][3], b00, b01);
                    mma_f16(acc[mt][2 * np + 1], af[mt][0], af[mt][1], af[mt][2], af[mt][3], b10, b11);
                }
            }
        }
        __syncthreads();
    }

#pragma unroll
    for (int mt = 0; mt < 2; mt++) {
#pragma unroll
        for (int nt = 0; nt < 8; nt++) {
            const int r0 = rowBase + wm + mt * 16 + gid;
            const int c0 = colBase + wn + nt * 8 + 2 * tig;
            *(float2*)(C + (size_t)r0 * N + c0)       = make_float2(acc[mt][nt][0], acc[mt][nt][1]);
            *(float2*)(C + (size_t)(r0 + 8) * N + c0) = make_float2(acc[mt][nt][2], acc[mt][nt][3]);
        }
    }
}

// ---------------------------------------------------------------------------
// FP16 flash attention (causal), LDSM operands: BR=64 (4 warps), BC=64.
// ---------------------------------------------------------------------------
#define BRt 64
#define BCt 64
#define HKSTR 68
#define HVSTR 36
#define HOFF_K0 0
#define HOFF_V0 (HOFF_K0 + 64*HKSTR)    // 4352
#define HOFF_K1 (HOFF_V0 + 128*HVSTR)   // 8960
#define HOFF_V1 (HOFF_K1 + 64*HKSTR)    // 13312
#define HSM_WORDS (HOFF_V1 + 128*HVSTR) // 17920 words = 71680 B

__global__ __launch_bounds__(128, 3) void attn_h(const __half* __restrict__ qh,
                                                 const __half* __restrict__ kh,
                                                 const __half* __restrict__ vt,
                                                 __half* __restrict__ oh) {
    extern __shared__ uint32_t smu[];

    const int tid  = threadIdx.x;
    const int lane = tid & 31;
    const int warp = tid >> 5;
    const int gid  = lane >> 2;
    const int tig  = lane & 3;
    const int lm   = lane >> 3;
    const int lr   = lane & 7;
    const int qb = (gridDim.x - 1) - blockIdx.x;   // heavy blocks first
    const int h = blockIdx.y, b = blockIdx.z;
    const int t0 = qb * BRt;
    const int wrow = warp * 16;

    const size_t bhOff = (size_t)(b * Hh + h) * Tt * Dd;
    const __half* qbase = qh + bhOff + (size_t)t0 * Dd;
    const __half* kbase = kh + bhOff;
    const __half* vbase = vt + bhOff;              // [d][t]
    const uint32_t smemBase = (uint32_t)__cvta_generic_to_shared(smu);

    const int bRowSel = lm >> 1;
    const int bKSel   = lm & 1;

    {
#pragma unroll
        for (int i = 0; i < 8; i++) {
            const int s = tid + i * 128;
            const int r = s >> 4, c = s & 15;
            cp16(smemBase + (HOFF_K0 + r * HKSTR + c * 4) * 4,
                 kbase + (size_t)r * Dd + c * 8);
        }
#pragma unroll
        for (int i = 0; i < 8; i++) {
            const int s = tid + i * 128;
            const int r = s >> 3, c = s & 7;
            cp16(smemBase + (HOFF_V0 + r * HVSTR + c * 4) * 4,
                 vbase + (size_t)r * Tt + c * 8);
        }
        CP_COMMIT();
    }
    {
#pragma unroll
        for (int i = 0; i < 8; i++) {
            const int s = tid + i * 128;
            const int r = s >> 4, c = s & 15;
            cp16(smemBase + (HOFF_K1 + r * HKSTR + c * 4) * 4,
                 qbase + (size_t)r * Dd + c * 8);
        }
        CP_COMMIT();
        CP_WAIT(0);
    }
    __syncthreads();

    uint32_t qf[8][4];
    {
        const uint32_t qRow = wrow + (lm & 1) * 8 + lr;
        const uint32_t qWordSel = (lm >> 1) * 4;
#pragma unroll
        for (int ks = 0; ks < 8; ks++) {
            ldsm4(qf[ks][0], qf[ks][1], qf[ks][2], qf[ks][3],
                  smemBase + (HOFF_K1 + qRow * HKSTR + 8 * ks + qWordSel) * 4);
        }
    }
    __syncthreads();

    float m0 = -1e30f, m1 = -1e30f, l0 = 0.f, l1 = 0.f;
    float oacc[16][4];
#pragma unroll
    for (int nt = 0; nt < 16; nt++)
#pragma unroll
        for (int i = 0; i < 4; i++) oacc[nt][i] = 0.f;

    for (int kb = 0; kb <= qb; kb++) {
        if (kb + 1 <= qb) {
            const int tk0 = (kb + 1) * BCt;
            const int offK = ((kb + 1) & 1) ? HOFF_K1 : HOFF_K0;
            const int offV = ((kb + 1) & 1) ? HOFF_V1 : HOFF_V0;
#pragma unroll
            for (int i = 0; i < 8; i++) {
                const int s = tid + i * 128;
                const int r = s >> 4, c = s & 15;
                cp16(smemBase + (offK + r * HKSTR + c * 4) * 4,
                     kbase + (size_t)(tk0 + r) * Dd + c * 8);
            }
#pragma unroll
            for (int i = 0; i < 8; i++) {
                const int s = tid + i * 128;
                const int r = s >> 3, c = s & 7;
                cp16(smemBase + (offV + r * HVSTR + c * 4) * 4,
                     vbase + (size_t)r * Tt + tk0 + c * 8);
            }
            CP_COMMIT();
            CP_WAIT(1);
        } else {
            CP_WAIT(0);
        }
        __syncthreads();

        const uint32_t offK = (kb & 1) ? HOFF_K1 : HOFF_K0;
        const uint32_t offV = (kb & 1) ? HOFF_V1 : HOFF_V0;
        const int tk0 = kb * BCt;

        float sacc[8][4];
#pragma unroll
        for (int nt = 0; nt < 8; nt++)
#pragma unroll
            for (int i = 0; i < 4; i++) sacc[nt][i] = 0.f;

        const uint32_t kAddr0 = smemBase + (offK + ((bRowSel * 8 + lr) * HKSTR) + bKSel * 4) * 4;
#pragma unroll
        for (int ks = 0; ks < 8; ks++) {
#pragma unroll
            for (int np = 0; np < 4; np++) {
                uint32_t b00, b01, b10, b11;
                ldsm4(b00, b01, b10, b11,
                      kAddr0 + ((2 * np) * 8 * HKSTR + 8 * ks) * 4);
                mma_f16(sacc[2 * np],     qf[ks][0], qf[ks][1], qf[ks][2], qf[ks][3], b00, b01);
                mma_f16(sacc[2 * np + 1], qf[ks][0], qf[ks][1], qf[ks][2], qf[ks][3], b10, b11);
            }
        }

        if (kb == qb) {
            const int rg0 = t0 + wrow + gid;
            const int rg1 = rg0 + 8;
#pragma unroll
            for (int nt = 0; nt < 8; nt++) {
                const int cg = tk0 + nt * 8 + 2 * tig;
                if (rg0 < cg)     sacc[nt][0] = -1e30f;
                if (rg0 < cg + 1) sacc[nt][1] = -1e30f;
                if (rg1 < cg)     sacc[nt][2] = -1e30f;
                if (rg1 < cg + 1) sacc[nt][3] = -1e30f;
            }
        }

        float rm0 = -1e30f, rm1 = -1e30f;
#pragma unroll
        for (int nt = 0; nt < 8; nt++) {
            rm0 = fmaxf(rm0, fmaxf(sacc[nt][0], sacc[nt][1]));
            rm1 = fmaxf(rm1, fmaxf(sacc[nt][2], sacc[nt][3]));
        }
        rm0 = fmaxf(rm0, __shfl_xor_sync(0xffffffffu, rm0, 1));
        rm0 = fmaxf(rm0, __shfl_xor_sync(0xffffffffu, rm0, 2));
        rm1 = fmaxf(rm1, __shfl_xor_sync(0xffffffffu, rm1, 1));
        rm1 = fmaxf(rm1, __shfl_xor_sync(0xffffffffu, rm1, 2));

        const float nm0 = fmaxf(m0, rm0);
        const float nm1 = fmaxf(m1, rm1);
        float sum0 = 0.f, sum1 = 0.f;
        uint32_t pe[8][2];
#pragma unroll
        for (int nt = 0; nt < 8; nt++) {
            float e00 = __expf(sacc[nt][0] - nm0);
            float e01 = __expf(sacc[nt][1] - nm0);
            float e10 = __expf(sacc[nt][2] - nm1);
            float e11 = __expf(sacc[nt][3] - nm1);
            sum0 += e00 + e01;
            sum1 += e10 + e11;
            pe[nt][0] = packh2(e00, e01);
            pe[nt][1] = packh2(e10, e11);
        }
        sum0 += __shfl_xor_sync(0xffffffffu, sum0, 1);
        sum0 += __shfl_xor_sync(0xffffffffu, sum0, 2);
        sum1 += __shfl_xor_sync(0xffffffffu, sum1, 1);
        sum1 += __shfl_xor_sync(0xffffffffu, sum1, 2);

        const float c0 = __expf(m0 - nm0);
        const float c1 = __expf(m1 - nm1);
        l0 = l0 * c0 + sum0; m0 = nm0;
        l1 = l1 * c1 + sum1; m1 = nm1;
#pragma unroll
        for (int nt = 0; nt < 16; nt++) {
            oacc[nt][0] *= c0; oacc[nt][1] *= c0;
            oacc[nt][2] *= c1; oacc[nt][3] *= c1;
        }

        const uint32_t vAddr0 = smemBase + (offV + ((bRowSel * 8 + lr) * HVSTR) + bKSel * 4) * 4;
#pragma unroll
        for (int ks = 0; ks < 4; ks++) {
            const uint32_t a0 = pe[2 * ks][0];
            const uint32_t a1 = pe[2 * ks][1];
            const uint32_t a2 = pe[2 * ks + 1][0];
            const uint32_t a3 = pe[2 * ks + 1][1];
#pragma unroll
            for (int np = 0; np < 8; np++) {
                uint32_t b00, b01, b10, b11;
                ldsm4(b00, b01, b10, b11,
                      vAddr0 + ((2 * np) * 8 * HVSTR + 8 * ks) * 4);
                mma_f16(oacc[2 * np],     a0, a1, a2, a3, b00, b01);
                mma_f16(oacc[2 * np + 1], a0, a1, a2, a3, b10, b11);
            }
        }
        __syncthreads();
    }

    const float i0 = 1.0f / l0;
    const float i1 = 1.0f / l1;
    const int rg0 = t0 + wrow + gid;
    __half* ob0 = oh + ((size_t)(b * Tt + rg0) * Hh + h) * Dd;
    __half* ob1 = oh + ((size_t)(b * Tt + rg0 + 8) * Hh + h) * Dd;
#pragma unroll
    for (int nt = 0; nt < 16; nt++) {
        const int col = nt * 8 + 2 * tig;
        *(uint32_t*)(ob0 + col) = packh2(oacc[nt][0] * i0, oacc[nt][1] * i0);
        *(uint32_t*)(ob1 + col) = packh2(oacc[nt][2] * i1, oacc[nt][3] * i1);
    }
}

// ---------------------------------------------------------------------------
extern "C" void kernel_launch(void* const* d_in, const int* in_sizes, int n_in,
                              void* d_out, int out_size) {
    const float* x  = (const float*)d_in[0];
    const float* wq = (const float*)d_in[1];
    const float* wk = (const float*)d_in[2];
    const float* wv = (const float*)d_in[3];
    const float* wo = (const float*)d_in[4];
    float* out = (float*)d_out;

    __half *xh, *wqt, *wkt, *wvt, *wot, *qhp, *khp, *vtp, *ohp;
    cudaGetSymbolAddress((void**)&xh, g_xh);
    cudaGetSymbolAddress((void**)&wqt, g_wqt);
    cudaGetSymbolAddress((void**)&wkt, g_wkt);
    cudaGetSymbolAddress((void**)&wvt, g_wvt);
    cudaGetSymbolAddress((void**)&wot, g_wot);
    cudaGetSymbolAddress((void**)&qhp, g_qh);
    cudaGetSymbolAddress((void**)&khp, g_kh);
    cudaGetSymbolAddress((void**)&vtp, g_vt);
    cudaGetSymbolAddress((void**)&ohp, g_oh);

    // Convert x; transpose+convert all four weights
    f2h<<<(BT*Mm/4 + 255)/256, 256>>>(x, xh, BT*Mm/4);
    wtrans<<<dim3(32, 32, 4), dim3(32, 8)>>>(wq, wk, wv, wo, wqt, wkt, wvt, wot);

    // Fused QKV projections + RMSNorm/RoPE (q,k) + transpose (v)
    dim3 gp(HD / 128, BT / 128, 3);
    gemm_qkv<<<gp, 256>>>(xh, wqt, wkt, wvt, qhp, khp, vtp);

    // FP16 flash attention -> fp16 O [b,t,h,d]
    size_t smem = (size_t)HSM_WORDS * 4;
    cudaFuncSetAttribute(attn_h, cudaFuncAttributeMaxDynamicSharedMemorySize, (int)smem);
    dim3 ga(Tt / BRt, Hh, Bq);
    attn_h<<<ga, 128, smem>>>(qhp, khp, vtp, ohp);

    // Output projection -> fp32 out
    dim3 go(Mm / 128, BT / 128);
    gemm_h<<<go, 256>>>(ohp, wot, out, BT, Mm, HD);
}